// round 2
// baseline (speedup 1.0000x reference)
#include <cuda_runtime.h>
#include <math.h>
#include <float.h>

#define Nn 50000
#define Ee 800000
#define INF 128
#define HIDf 96
#define Hh 8
#define Dd 12
#define Gg 64
#define OUTf 10
#define NB_SCAN ((Nn + 511) / 512)   // 98
#define GAT_CAP 64

// ---------------- scratch (device globals; no allocation allowed) ------------
__device__ __align__(16) float g_tmp[Nn * HIDf];
__device__ __align__(16) float g_h0[Nn * HIDf];
__device__ __align__(16) float g_h1[Nn * HIDf];
__device__ __align__(16) float g_fs[Nn * HIDf];
__device__ __align__(16) float g_fd[Nn * HIDf];
__device__ int   g_degout[Nn];
__device__ int   g_degin[Nn];
__device__ int   g_fill[Nn];
__device__ int   g_rowptr[Nn + 1];
__device__ int   g_esrc[Ee];
__device__ int   g_part[128];
__device__ int   g_hg[Gg * HIDf];
__device__ float g_dinvout[Nn];
__device__ float g_dinvin[Nn];

// ---------------- init ----------------
__global__ void k_init() {
    int i = blockIdx.x * blockDim.x + threadIdx.x;
    if (i < Nn) { g_degout[i] = 0; g_degin[i] = 0; g_fill[i] = 0; }
    if (i < Gg * HIDf) g_hg[i] = 0;   // bits of +0.0f; readout inputs are >= 0
}

// ---------------- degrees / histogram ----------------
__global__ void k_degree(const int* __restrict__ src, const int* __restrict__ dst) {
    int e = blockIdx.x * blockDim.x + threadIdx.x;
    if (e < Ee) {
        atomicAdd(&g_degout[src[e]], 1);
        atomicAdd(&g_degin[dst[e]], 1);
    }
}

// ---------------- exclusive scan of g_degin -> g_rowptr ----------------
__global__ void k_scan1() {
    __shared__ int s[512];
    int t = threadIdx.x;
    int idx = blockIdx.x * 512 + t;
    int v = (idx < Nn) ? g_degin[idx] : 0;
    s[t] = v;
    __syncthreads();
    for (int off = 1; off < 512; off <<= 1) {
        int x = (t >= off) ? s[t - off] : 0;
        __syncthreads();
        s[t] += x;
        __syncthreads();
    }
    if (idx < Nn) g_rowptr[idx] = s[t] - v;
    if (t == 511) g_part[blockIdx.x] = s[511];
}

__global__ void k_scan2() {
    __shared__ int s[128];
    int t = threadIdx.x;
    int v = (t < NB_SCAN) ? g_part[t] : 0;
    s[t] = v;
    __syncthreads();
    for (int off = 1; off < 128; off <<= 1) {
        int x = (t >= off) ? s[t - off] : 0;
        __syncthreads();
        s[t] += x;
        __syncthreads();
    }
    if (t < NB_SCAN) g_part[t] = s[t] - v;
}

// scan finalize + deg^-0.5 fused
__global__ void k_scan3() {
    int idx = blockIdx.x * blockDim.x + threadIdx.x;
    if (idx < Nn) {
        g_rowptr[idx] += g_part[idx >> 9];
        g_dinvout[idx] = rsqrtf((float)max(g_degout[idx], 1));
        g_dinvin[idx]  = rsqrtf((float)max(g_degin[idx], 1));
    }
    if (idx == 0) g_rowptr[Nn] = Ee;
}

// ---------------- CSR fill (edges grouped by dst) ----------------
__global__ void k_fill(const int* __restrict__ src, const int* __restrict__ dst) {
    int e = blockIdx.x * blockDim.x + threadIdx.x;
    if (e < Ee) {
        int d = dst[e];
        int pos = g_rowptr[d] + atomicAdd(&g_fill[d], 1);
        g_esrc[pos] = src[e];
    }
}

// ---------------- GEMM: out[N,96] = (in [* dinvout]) @ W [+ bias] ----------------
// 128-row x 96-col block tile, threads (12,32), 4x8 micro-tile
__global__ void k_gemm(const float* __restrict__ in, const float* __restrict__ W,
                       const float* __restrict__ bias, int use_rowscale,
                       float* __restrict__ out, int kin) {
    __shared__ float sW[32][HIDf];
    __shared__ float sIn[128][33];
    int tx = threadIdx.x;            // 0..11 -> cols 8*tx..8*tx+7
    int ty = threadIdx.y;            // 0..31 -> rows 4*ty..4*ty+3
    int tid = ty * 12 + tx;          // 0..383
    int rowBase = blockIdx.x * 128;
    float acc[4][8] = {};

    for (int kc = 0; kc < kin; kc += 32) {
        for (int i = tid; i < 32 * HIDf; i += 384) {
            int kk = i / HIDf, cc = i % HIDf;
            sW[kk][cc] = W[(kc + kk) * HIDf + cc];
        }
        for (int i = tid; i < 128 * 32; i += 384) {
            int r = i >> 5, k = i & 31;
            int row = rowBase + r;
            float v = 0.f;
            if (row < Nn) {
                v = in[row * kin + kc + k];
                if (use_rowscale) v *= g_dinvout[row];
            }
            sIn[r][k] = v;
        }
        __syncthreads();
#pragma unroll
        for (int k = 0; k < 32; k++) {
            float4 b0 = *(const float4*)&sW[k][tx * 8];
            float4 b1 = *(const float4*)&sW[k][tx * 8 + 4];
#pragma unroll
            for (int i = 0; i < 4; i++) {
                float a = sIn[ty * 4 + i][k];
                acc[i][0] += a * b0.x; acc[i][1] += a * b0.y;
                acc[i][2] += a * b0.z; acc[i][3] += a * b0.w;
                acc[i][4] += a * b1.x; acc[i][5] += a * b1.y;
                acc[i][6] += a * b1.z; acc[i][7] += a * b1.w;
            }
        }
        __syncthreads();
    }
    float bb[8];
#pragma unroll
    for (int j = 0; j < 8; j++) bb[j] = bias ? bias[tx * 8 + j] : 0.f;
#pragma unroll
    for (int i = 0; i < 4; i++) {
        int row = rowBase + ty * 4 + i;
        if (row < Nn) {
            float4 o0, o1;
            o0.x = acc[i][0] + bb[0]; o0.y = acc[i][1] + bb[1];
            o0.z = acc[i][2] + bb[2]; o0.w = acc[i][3] + bb[3];
            o1.x = acc[i][4] + bb[4]; o1.y = acc[i][5] + bb[5];
            o1.z = acc[i][6] + bb[6]; o1.w = acc[i][7] + bb[7];
            *(float4*)(out + row * HIDf + tx * 8)     = o0;
            *(float4*)(out + row * HIDf + tx * 8 + 4) = o1;
        }
    }
}

// ---------------- GraphConv aggregation: out = relu(sum_in(pre[src]) * dinvin + b)
__global__ void k_agg(const float* __restrict__ pre, const float* __restrict__ bias,
                      float* __restrict__ out) {
    int warp = (blockIdx.x * blockDim.x + threadIdx.x) >> 5;
    int lane = threadIdx.x & 31;
    if (warp >= Nn) return;
    int beg = g_rowptr[warp], end = g_rowptr[warp + 1];
    float a0 = 0.f, a1 = 0.f, a2 = 0.f;
    for (int p = beg; p < end; p++) {
        const float* r = pre + g_esrc[p] * HIDf;
        a0 += r[lane];
        a1 += r[lane + 32];
        a2 += r[lane + 64];
    }
    float sc = g_dinvin[warp];
    out[warp * HIDf + lane]      = fmaxf(a0 * sc + bias[lane], 0.f);
    out[warp * HIDf + lane + 32] = fmaxf(a1 * sc + bias[lane + 32], 0.f);
    out[warp * HIDf + lane + 64] = fmaxf(a2 * sc + bias[lane + 64], 0.f);
}

// ---------------- fused GATv2: logits + online edge-softmax + weighted sum + relu
// one warp per dst node; logits cached in smem per 64-edge chunk.
__global__ void k_gat(const float* __restrict__ fs, const float* __restrict__ fd,
                      const float* __restrict__ attn, float* __restrict__ out) {
    __shared__ float slog[8][GAT_CAP * Hh];   // 8 warps * 64 edges * 8 heads = 16KB
    int wl = threadIdx.x >> 5;
    int node = (blockIdx.x * blockDim.x + threadIdx.x) >> 5;
    int lane = threadIdx.x & 31;
    if (node >= Nn) return;
    float* lg = slog[wl];
    int beg = g_rowptr[node], end = g_rowptr[node + 1];

    int h = lane & 7, sub = lane >> 3;
    float fdv[Dd], av[Dd];
    const float* fdp = fd + node * HIDf + h * Dd;
    const float* ap  = attn + h * Dd;
#pragma unroll
    for (int j = 0; j < Dd; j++) { fdv[j] = fdp[j]; av[j] = ap[j]; }

    int f0 = lane, f1 = lane + 32, f2 = lane + 64;
    int h0 = f0 / Dd, h1 = f1 / Dd, h2 = f2 / Dd;

    float m_run = -FLT_MAX, den = 0.f;
    float acc0 = 0.f, acc1 = 0.f, acc2 = 0.f;

    for (int p0 = beg; p0 < end; p0 += GAT_CAP) {
        int cnt = min(end - p0, GAT_CAP);
        // phase 1: logits for this lane's (sub, head) edges
        float mc = -FLT_MAX;
        for (int q = sub; q < cnt; q += 4) {
            const float* fsp = fs + g_esrc[p0 + q] * HIDf + h * Dd;
            float l = 0.f;
#pragma unroll
            for (int j = 0; j < Dd; j++) {
                float v = fsp[j] + fdv[j];
                v = (v > 0.f) ? v : 0.2f * v;
                l += v * av[j];
            }
            lg[q * 8 + h] = l;
            mc = fmaxf(mc, l);
        }
        mc = fmaxf(mc, __shfl_xor_sync(0xffffffffu, mc, 8));
        mc = fmaxf(mc, __shfl_xor_sync(0xffffffffu, mc, 16));
        float m_new = fmaxf(m_run, mc);
        float scale = (m_run == -FLT_MAX) ? 0.f : __expf(m_run - m_new);
        __syncwarp();
        // phase 2: exp + chunk denominator; overwrite logits with weights
        float dc = 0.f;
        for (int q = sub; q < cnt; q += 4) {
            float w = __expf(lg[q * 8 + h] - m_new);
            lg[q * 8 + h] = w;
            dc += w;
        }
        dc += __shfl_xor_sync(0xffffffffu, dc, 8);
        dc += __shfl_xor_sync(0xffffffffu, dc, 16);
        den = den * scale + dc;
        // rescale accumulators for this lane's heads
        float s0 = __shfl_sync(0xffffffffu, scale, h0);
        float s1 = __shfl_sync(0xffffffffu, scale, h1);
        float s2 = __shfl_sync(0xffffffffu, scale, h2);
        acc0 *= s0; acc1 *= s1; acc2 *= s2;
        __syncwarp();
        // phase 3: weighted accumulate (all lanes sweep all chunk edges)
        for (int q = 0; q < cnt; q++) {
            const float* fr = fs + g_esrc[p0 + q] * HIDf;
            float w0 = lg[q * 8 + h0];
            float w1 = lg[q * 8 + h1];
            float w2 = lg[q * 8 + h2];
            acc0 += w0 * fr[f0];
            acc1 += w1 * fr[f1];
            acc2 += w2 * fr[f2];
        }
        m_run = m_new;
        __syncwarp();
    }
    float d0 = __shfl_sync(0xffffffffu, den, h0);
    float d1 = __shfl_sync(0xffffffffu, den, h1);
    float d2 = __shfl_sync(0xffffffffu, den, h2);
    float r0 = (d0 > 0.f) ? 1.f / d0 : 0.f;
    float r1 = (d1 > 0.f) ? 1.f / d1 : 0.f;
    float r2 = (d2 > 0.f) ? 1.f / d2 : 0.f;
    out[node * HIDf + f0] = fmaxf(acc0 * r0, 0.f);
    out[node * HIDf + f1] = fmaxf(acc1 * r1, 0.f);
    out[node * HIDf + f2] = fmaxf(acc2 * r2, 0.f);
}

// ---------------- per-graph max readout (values >= 0 after relu) ----------------
__global__ void k_readout(const float* __restrict__ hfin, const int* __restrict__ gid) {
    __shared__ int s[Gg * HIDf];
    int tid = threadIdx.x;  // 384
    for (int i = tid; i < Gg * HIDf; i += 384) s[i] = 0;
    __syncthreads();
    int f = tid % 96, rr = tid / 96;
    for (int node = blockIdx.x * 4 + rr; node < Nn; node += 64 * 4) {
        int g = gid[node];
        float v = hfin[node * HIDf + f];
        atomicMax(&s[g * HIDf + f], __float_as_int(v));
    }
    __syncthreads();
    for (int i = tid; i < Gg * HIDf; i += 384) atomicMax(&g_hg[i], s[i]);
}

// ---------------- classifier MLP on [64,96] ----------------
__global__ void k_mlp(const float* __restrict__ Wc1, const float* __restrict__ bc1,
                      const float* __restrict__ Wc2, const float* __restrict__ bc2,
                      const float* __restrict__ Wc3, const float* __restrict__ bc3,
                      float* __restrict__ out) {
    __shared__ float A[Gg * HIDf];
    __shared__ float B[Gg * HIDf];
    int tid = threadIdx.x;  // 512
    for (int i = tid; i < Gg * HIDf; i += 512) A[i] = __int_as_float(g_hg[i]);
    __syncthreads();
    for (int i = tid; i < Gg * HIDf; i += 512) {
        int r = i / 96, c = i % 96;
        float acc = bc1[c];
        for (int k = 0; k < 96; k++) acc += A[r * 96 + k] * Wc1[k * 96 + c];
        B[i] = fmaxf(acc, 0.f);
    }
    __syncthreads();
    for (int i = tid; i < Gg * 48; i += 512) {
        int r = i / 48, c = i % 48;
        float acc = bc2[c];
        for (int k = 0; k < 96; k++) acc += B[r * 96 + k] * Wc2[k * 48 + c];
        A[i] = fmaxf(acc, 0.f);
    }
    __syncthreads();
    for (int i = tid; i < Gg * OUTf; i += 512) {
        int r = i / 10, c = i % 10;
        float acc = bc3[c];
        for (int k = 0; k < 48; k++) acc += A[r * 48 + k] * Wc3[k * 10 + c];
        out[i] = acc;
    }
}

// ---------------- host launcher ----------------
extern "C" void kernel_launch(void* const* d_in, const int* in_sizes, int n_in,
                              void* d_out, int out_size) {
    (void)in_sizes; (void)n_in; (void)out_size;
    const float* x    = (const float*)d_in[0];
    const int*   src  = (const int*)d_in[1];
    const int*   dst  = (const int*)d_in[2];
    const int*   gid  = (const int*)d_in[3];
    const float* W1   = (const float*)d_in[4];
    const float* b1   = (const float*)d_in[5];
    const float* W2   = (const float*)d_in[6];
    const float* b2   = (const float*)d_in[7];
    const float* Ws   = (const float*)d_in[8];
    const float* bs   = (const float*)d_in[9];
    const float* Wd   = (const float*)d_in[10];
    const float* bd   = (const float*)d_in[11];
    const float* attn = (const float*)d_in[12];
    const float* Wc1  = (const float*)d_in[13];
    const float* bc1  = (const float*)d_in[14];
    const float* Wc2  = (const float*)d_in[15];
    const float* bc2  = (const float*)d_in[16];
    const float* Wc3  = (const float*)d_in[17];
    const float* bc3  = (const float*)d_in[18];
    float* out = (float*)d_out;

    float *p_tmp, *p_h0, *p_h1, *p_fs, *p_fd;
    cudaGetSymbolAddress((void**)&p_tmp, g_tmp);
    cudaGetSymbolAddress((void**)&p_h0, g_h0);
    cudaGetSymbolAddress((void**)&p_h1, g_h1);
    cudaGetSymbolAddress((void**)&p_fs, g_fs);
    cudaGetSymbolAddress((void**)&p_fd, g_fd);

    const int TPB = 256;
    dim3 gb(12, 32);
    int gemm_blocks = (Nn + 127) / 128;           // 391
    int warp_blocks = (Nn * 32 + TPB - 1) / TPB;  // 6250
    int edge_blocks = (Ee + TPB - 1) / TPB;       // 3125

    // launch order chosen so ncu (-s 5 -c 1) profiles the first GEMM
    k_init<<<(Nn + TPB - 1) / TPB, TPB>>>();                         // 0
    k_degree<<<edge_blocks, TPB>>>(src, dst);                        // 1
    k_scan1<<<NB_SCAN, 512>>>();                                     // 2
    k_scan2<<<1, 128>>>();                                           // 3
    k_scan3<<<NB_SCAN, 512>>>();                                     // 4
    k_gemm<<<gemm_blocks, gb>>>(x, W1, nullptr, 1, p_tmp, INF);      // 5  <- profiled
    k_fill<<<edge_blocks, TPB>>>(src, dst);                          // 6
    k_agg<<<warp_blocks, TPB>>>(p_tmp, b1, p_h0);                    // 7

    k_gemm<<<gemm_blocks, gb>>>(p_h0, W2, nullptr, 1, p_tmp, HIDf);
    k_agg<<<warp_blocks, TPB>>>(p_tmp, b2, p_h1);

    float* hin = p_h1;
    float* hout = p_h0;
    for (int i = 0; i < 3; i++) {
        k_gemm<<<gemm_blocks, gb>>>(hin, Ws + i * HIDf * HIDf, bs + i * HIDf, 0, p_fs, HIDf);
        k_gemm<<<gemm_blocks, gb>>>(hin, Wd + i * HIDf * HIDf, bd + i * HIDf, 0, p_fd, HIDf);
        k_gat<<<warp_blocks, TPB>>>(p_fs, p_fd, attn + i * Hh * Dd, hout);
        float* t = hin; hin = hout; hout = t;
    }

    k_readout<<<64, 384>>>(hin, gid);
    k_mlp<<<1, 512>>>(Wc1, bc1, Wc2, bc2, Wc3, bc3, out);
}

// round 3
// speedup vs baseline: 1.0529x; 1.0529x over previous
#include <cuda_runtime.h>
#include <math.h>

#define Nn 50000
#define Ee 800000
#define INF 128
#define HIDf 96
#define Hh 8
#define Dd 12
#define Gg 64
#define OUTf 10
#define NB_SCAN ((Nn + 511) / 512)   // 98

// ---------------- scratch (device globals; no allocation allowed) ------------
__device__ __align__(16) float g_tmp[Nn * HIDf];
__device__ __align__(16) float g_h0[Nn * HIDf];
__device__ __align__(16) float g_h1[Nn * HIDf];
__device__ __align__(16) float g_fs[Nn * HIDf];
__device__ __align__(16) float g_fd[Nn * HIDf];
__device__ __align__(16) float g_logits[Ee * Hh];
__device__ int   g_degout[Nn];
__device__ int   g_degin[Nn];
__device__ int   g_fill[Nn];
__device__ int   g_rowptr[Nn + 1];
__device__ int   g_esrc[Ee];
__device__ int   g_edst[Ee];
__device__ int   g_part[128];
__device__ int   g_hg[Gg * HIDf];
__device__ float g_dinvout[Nn];
__device__ float g_dinvin[Nn];

// ---------------- init ----------------
__global__ void k_init() {
    int i = blockIdx.x * blockDim.x + threadIdx.x;
    if (i < Nn) { g_degout[i] = 0; g_degin[i] = 0; g_fill[i] = 0; }
    if (i < Gg * HIDf) g_hg[i] = 0;   // bits of +0.0f; readout inputs are >= 0
}

// ---------------- degrees / histogram ----------------
__global__ void k_degree(const int* __restrict__ src, const int* __restrict__ dst) {
    int e = blockIdx.x * blockDim.x + threadIdx.x;
    if (e < Ee) {
        atomicAdd(&g_degout[src[e]], 1);
        atomicAdd(&g_degin[dst[e]], 1);
    }
}

// ---------------- deg^-0.5 (clamped >= 1) ----------------
__global__ void k_dinv() {
    int i = blockIdx.x * blockDim.x + threadIdx.x;
    if (i < Nn) {
        g_dinvout[i] = rsqrtf((float)max(g_degout[i], 1));
        g_dinvin[i]  = rsqrtf((float)max(g_degin[i], 1));
    }
}

// ---------------- exclusive scan of g_degin -> g_rowptr ----------------
__global__ void k_scan1() {
    __shared__ int s[512];
    int t = threadIdx.x;
    int idx = blockIdx.x * 512 + t;
    int v = (idx < Nn) ? g_degin[idx] : 0;
    s[t] = v;
    __syncthreads();
    for (int off = 1; off < 512; off <<= 1) {
        int x = (t >= off) ? s[t - off] : 0;
        __syncthreads();
        s[t] += x;
        __syncthreads();
    }
    if (idx < Nn) g_rowptr[idx] = s[t] - v;
    if (t == 511) g_part[blockIdx.x] = s[511];
}

__global__ void k_scan2() {
    __shared__ int s[128];
    int t = threadIdx.x;
    int v = (t < NB_SCAN) ? g_part[t] : 0;
    s[t] = v;
    __syncthreads();
    for (int off = 1; off < 128; off <<= 1) {
        int x = (t >= off) ? s[t - off] : 0;
        __syncthreads();
        s[t] += x;
        __syncthreads();
    }
    if (t < NB_SCAN) g_part[t] = s[t] - v;
}

__global__ void k_scan3() {
    int idx = blockIdx.x * blockDim.x + threadIdx.x;
    if (idx < Nn) g_rowptr[idx] += g_part[idx >> 9];
    if (idx == 0) g_rowptr[Nn] = Ee;
}

// ---------------- CSR fill (edges grouped by dst) ----------------
__global__ void k_fill(const int* __restrict__ src, const int* __restrict__ dst) {
    int e = blockIdx.x * blockDim.x + threadIdx.x;
    if (e < Ee) {
        int d = dst[e];
        int pos = g_rowptr[d] + atomicAdd(&g_fill[d], 1);
        g_esrc[pos] = src[e];
        g_edst[pos] = d;
    }
}

// ---------------- GEMM: out[N,96] = (in [* dinvout]) @ W [+ bias] ----------------
// block tile 128 rows x 96 cols, threads (12,16)=192, 8x8 micro-tile.
// Per k-step per thread: 8 scalar A-LDS + 2 LDS128 B for 64 FMA -> FMA-bound.
__global__ void __launch_bounds__(192, 2)
k_gemm(const float* __restrict__ in, const float* __restrict__ W,
       const float* __restrict__ bias, int use_rowscale,
       float* __restrict__ out, int kin) {
    __shared__ float sW[32][HIDf];     // 12 KB
    __shared__ float sIn[128][33];     // 16.9 KB
    int tx = threadIdx.x;              // 0..11 -> cols 8*tx..8*tx+7
    int ty = threadIdx.y;              // 0..15 -> rows 8*ty..8*ty+7
    int tid = ty * 12 + tx;            // 0..191
    int rowBase = blockIdx.x * 128;
    float acc[8][8] = {};

    for (int kc = 0; kc < kin; kc += 32) {
        for (int i = tid; i < 32 * HIDf; i += 192) {
            int kk = i / HIDf, cc = i % HIDf;
            sW[kk][cc] = W[(kc + kk) * HIDf + cc];
        }
        for (int i = tid; i < 128 * 32; i += 192) {
            int r = i >> 5, k = i & 31;
            int row = rowBase + r;
            float v = 0.f;
            if (row < Nn) {
                v = in[row * kin + kc + k];
                if (use_rowscale) v *= g_dinvout[row];
            }
            sIn[r][k] = v;
        }
        __syncthreads();
#pragma unroll
        for (int k = 0; k < 32; k++) {
            float4 b0 = *(const float4*)&sW[k][tx * 8];
            float4 b1 = *(const float4*)&sW[k][tx * 8 + 4];
            float a[8];
#pragma unroll
            for (int i = 0; i < 8; i++) a[i] = sIn[ty * 8 + i][k];
#pragma unroll
            for (int i = 0; i < 8; i++) {
                acc[i][0] += a[i] * b0.x; acc[i][1] += a[i] * b0.y;
                acc[i][2] += a[i] * b0.z; acc[i][3] += a[i] * b0.w;
                acc[i][4] += a[i] * b1.x; acc[i][5] += a[i] * b1.y;
                acc[i][6] += a[i] * b1.z; acc[i][7] += a[i] * b1.w;
            }
        }
        __syncthreads();
    }
    float bb[8];
#pragma unroll
    for (int j = 0; j < 8; j++) bb[j] = bias ? bias[tx * 8 + j] : 0.f;
#pragma unroll
    for (int i = 0; i < 8; i++) {
        int row = rowBase + ty * 8 + i;
        if (row < Nn) {
            float4 o0, o1;
            o0.x = acc[i][0] + bb[0]; o0.y = acc[i][1] + bb[1];
            o0.z = acc[i][2] + bb[2]; o0.w = acc[i][3] + bb[3];
            o1.x = acc[i][4] + bb[4]; o1.y = acc[i][5] + bb[5];
            o1.z = acc[i][6] + bb[6]; o1.w = acc[i][7] + bb[7];
            *(float4*)(out + row * HIDf + tx * 8)     = o0;
            *(float4*)(out + row * HIDf + tx * 8 + 4) = o1;
        }
    }
}

// ---------------- GraphConv aggregation: out = relu(sum_in(pre[src]) * dinvin + b)
__global__ void k_agg(const float* __restrict__ pre, const float* __restrict__ bias,
                      float* __restrict__ out) {
    int warp = (blockIdx.x * blockDim.x + threadIdx.x) >> 5;
    int lane = threadIdx.x & 31;
    if (warp >= Nn) return;
    int beg = g_rowptr[warp], end = g_rowptr[warp + 1];
    float a0 = 0.f, a1 = 0.f, a2 = 0.f;
    for (int p = beg; p < end; p++) {
        const float* r = pre + g_esrc[p] * HIDf;
        a0 += r[lane];
        a1 += r[lane + 32];
        a2 += r[lane + 64];
    }
    float sc = g_dinvin[warp];
    out[warp * HIDf + lane]      = fmaxf(a0 * sc + bias[lane], 0.f);
    out[warp * HIDf + lane + 32] = fmaxf(a1 * sc + bias[lane + 32], 0.f);
    out[warp * HIDf + lane + 64] = fmaxf(a2 * sc + bias[lane + 64], 0.f);
}

// ---------------- GATv2 edge logits (dst-sorted order) ----------------
__global__ void k_logits(const float* __restrict__ attn) {
    int idx = blockIdx.x * blockDim.x + threadIdx.x;
    if (idx >= Ee * Hh) return;
    int p = idx >> 3, h = idx & 7;
    int s = g_esrc[p], d = g_edst[p];
    const float4* fsp = (const float4*)(g_fs + s * HIDf + h * Dd);
    const float4* fdp = (const float4*)(g_fd + d * HIDf + h * Dd);
    float lg = 0.f;
#pragma unroll
    for (int j = 0; j < 3; j++) {
        float4 a = fsp[j];
        float4 b = fdp[j];
        float v;
        v = a.x + b.x; v = (v > 0.f) ? v : 0.2f * v; lg += v * __ldg(attn + h * Dd + j * 4 + 0);
        v = a.y + b.y; v = (v > 0.f) ? v : 0.2f * v; lg += v * __ldg(attn + h * Dd + j * 4 + 1);
        v = a.z + b.z; v = (v > 0.f) ? v : 0.2f * v; lg += v * __ldg(attn + h * Dd + j * 4 + 2);
        v = a.w + b.w; v = (v > 0.f) ? v : 0.2f * v; lg += v * __ldg(attn + h * Dd + j * 4 + 3);
    }
    g_logits[idx] = lg;   // idx == p*8 + h
}

// ---------------- GATv2 per-node softmax + weighted sum + relu ----------------
__global__ void k_gatnode(float* __restrict__ out) {
    int warp = (blockIdx.x * blockDim.x + threadIdx.x) >> 5;
    int lane = threadIdx.x & 31;
    if (warp >= Nn) return;
    int beg = g_rowptr[warp], end = g_rowptr[warp + 1];
    int h = lane & 7, sub = lane >> 3;

    float mh = -3.402823466e38f;
    for (int p = beg + sub; p < end; p += 4) mh = fmaxf(mh, g_logits[p * 8 + h]);
    mh = fmaxf(mh, __shfl_xor_sync(0xffffffffu, mh, 8));
    mh = fmaxf(mh, __shfl_xor_sync(0xffffffffu, mh, 16));

    float den = 0.f;
    for (int p = beg + sub; p < end; p += 4) den += __expf(g_logits[p * 8 + h] - mh);
    den += __shfl_xor_sync(0xffffffffu, den, 8);
    den += __shfl_xor_sync(0xffffffffu, den, 16);

    int f0 = lane, f1 = lane + 32, f2 = lane + 64;
    int h0 = f0 / Dd, h1 = f1 / Dd, h2 = f2 / Dd;
    float m0 = __shfl_sync(0xffffffffu, mh, h0);
    float m1 = __shfl_sync(0xffffffffu, mh, h1);
    float m2 = __shfl_sync(0xffffffffu, mh, h2);
    float d0 = __shfl_sync(0xffffffffu, den, h0);
    float d1 = __shfl_sync(0xffffffffu, den, h1);
    float d2 = __shfl_sync(0xffffffffu, den, h2);
    float r0 = (d0 > 0.f) ? 1.f / d0 : 0.f;
    float r1 = (d1 > 0.f) ? 1.f / d1 : 0.f;
    float r2 = (d2 > 0.f) ? 1.f / d2 : 0.f;

    float acc0 = 0.f, acc1 = 0.f, acc2 = 0.f;
    for (int p = beg; p < end; p++) {
        const float* lg = g_logits + p * 8;
        float a0 = __expf(lg[h0] - m0) * r0;
        float a1 = __expf(lg[h1] - m1) * r1;
        float a2 = __expf(lg[h2] - m2) * r2;
        const float* fr = g_fs + g_esrc[p] * HIDf;
        acc0 += a0 * fr[f0];
        acc1 += a1 * fr[f1];
        acc2 += a2 * fr[f2];
    }
    out[warp * HIDf + f0] = fmaxf(acc0, 0.f);
    out[warp * HIDf + f1] = fmaxf(acc1, 0.f);
    out[warp * HIDf + f2] = fmaxf(acc2, 0.f);
}

// ---------------- per-graph max readout (values >= 0 after relu) ----------------
__global__ void k_readout(const float* __restrict__ hfin, const int* __restrict__ gid) {
    __shared__ int s[Gg * HIDf];
    int tid = threadIdx.x;  // 384
    for (int i = tid; i < Gg * HIDf; i += 384) s[i] = 0;
    __syncthreads();
    int f = tid % 96, rr = tid / 96;
    for (int node = blockIdx.x * 4 + rr; node < Nn; node += 64 * 4) {
        int g = gid[node];
        float v = hfin[node * HIDf + f];
        atomicMax(&s[g * HIDf + f], __float_as_int(v));
    }
    __syncthreads();
    for (int i = tid; i < Gg * HIDf; i += 384) atomicMax(&g_hg[i], s[i]);
}

// ---------------- classifier MLP on [64,96] ----------------
__global__ void k_mlp(const float* __restrict__ Wc1, const float* __restrict__ bc1,
                      const float* __restrict__ Wc2, const float* __restrict__ bc2,
                      const float* __restrict__ Wc3, const float* __restrict__ bc3,
                      float* __restrict__ out) {
    __shared__ float A[Gg * HIDf];
    __shared__ float B[Gg * HIDf];
    int tid = threadIdx.x;  // 512
    for (int i = tid; i < Gg * HIDf; i += 512) A[i] = __int_as_float(g_hg[i]);
    __syncthreads();
    for (int i = tid; i < Gg * HIDf; i += 512) {
        int r = i / 96, c = i % 96;
        float acc = bc1[c];
        for (int k = 0; k < 96; k++) acc += A[r * 96 + k] * Wc1[k * 96 + c];
        B[i] = fmaxf(acc, 0.f);
    }
    __syncthreads();
    for (int i = tid; i < Gg * 48; i += 512) {
        int r = i / 48, c = i % 48;
        float acc = bc2[c];
        for (int k = 0; k < 96; k++) acc += B[r * 96 + k] * Wc2[k * 48 + c];
        A[i] = fmaxf(acc, 0.f);
    }
    __syncthreads();
    for (int i = tid; i < Gg * OUTf; i += 512) {
        int r = i / 10, c = i % 10;
        float acc = bc3[c];
        for (int k = 0; k < 48; k++) acc += A[r * 48 + k] * Wc3[k * 10 + c];
        out[i] = acc;
    }
}

// ---------------- host launcher ----------------
extern "C" void kernel_launch(void* const* d_in, const int* in_sizes, int n_in,
                              void* d_out, int out_size) {
    (void)in_sizes; (void)n_in; (void)out_size;
    const float* x    = (const float*)d_in[0];
    const int*   src  = (const int*)d_in[1];
    const int*   dst  = (const int*)d_in[2];
    const int*   gid  = (const int*)d_in[3];
    const float* W1   = (const float*)d_in[4];
    const float* b1   = (const float*)d_in[5];
    const float* W2   = (const float*)d_in[6];
    const float* b2   = (const float*)d_in[7];
    const float* Ws   = (const float*)d_in[8];
    const float* bs   = (const float*)d_in[9];
    const float* Wd   = (const float*)d_in[10];
    const float* bd   = (const float*)d_in[11];
    const float* attn = (const float*)d_in[12];
    const float* Wc1  = (const float*)d_in[13];
    const float* bc1  = (const float*)d_in[14];
    const float* Wc2  = (const float*)d_in[15];
    const float* bc2  = (const float*)d_in[16];
    const float* Wc3  = (const float*)d_in[17];
    const float* bc3  = (const float*)d_in[18];
    float* out = (float*)d_out;

    float *p_tmp, *p_h0, *p_h1, *p_fs, *p_fd;
    cudaGetSymbolAddress((void**)&p_tmp, g_tmp);
    cudaGetSymbolAddress((void**)&p_h0, g_h0);
    cudaGetSymbolAddress((void**)&p_h1, g_h1);
    cudaGetSymbolAddress((void**)&p_fs, g_fs);
    cudaGetSymbolAddress((void**)&p_fd, g_fd);

    const int TPB = 256;
    dim3 gb(12, 16);
    int gemm_blocks = (Nn + 127) / 128;           // 391
    int warp_blocks = (Nn * 32 + TPB - 1) / TPB;  // 6250
    int edge_blocks = (Ee + TPB - 1) / TPB;       // 3125
    int logit_blocks = (Ee * Hh + TPB - 1) / TPB; // 25000

    // ncu captures launch index 3 -> make it the first GEMM
    k_init<<<(Nn + TPB - 1) / TPB, TPB>>>();                         // 0
    k_degree<<<edge_blocks, TPB>>>(src, dst);                        // 1
    k_dinv<<<(Nn + TPB - 1) / TPB, TPB>>>();                         // 2
    k_gemm<<<gemm_blocks, gb>>>(x, W1, nullptr, 1, p_tmp, INF);      // 3  <- profiled
    k_scan1<<<NB_SCAN, 512>>>();                                     // 4
    k_scan2<<<1, 128>>>();                                           // 5
    k_scan3<<<NB_SCAN, 512>>>();                                     // 6
    k_fill<<<edge_blocks, TPB>>>(src, dst);                          // 7
    k_agg<<<warp_blocks, TPB>>>(p_tmp, b1, p_h0);                    // 8

    k_gemm<<<gemm_blocks, gb>>>(p_h0, W2, nullptr, 1, p_tmp, HIDf);
    k_agg<<<warp_blocks, TPB>>>(p_tmp, b2, p_h1);

    float* hin = p_h1;
    float* hout = p_h0;
    for (int i = 0; i < 3; i++) {
        k_gemm<<<gemm_blocks, gb>>>(hin, Ws + i * HIDf * HIDf, bs + i * HIDf, 0, p_fs, HIDf);
        k_gemm<<<gemm_blocks, gb>>>(hin, Wd + i * HIDf * HIDf, bd + i * HIDf, 0, p_fd, HIDf);
        k_logits<<<logit_blocks, TPB>>>(attn + i * Hh * Dd);
        k_gatnode<<<warp_blocks, TPB>>>(hout);
        float* t = hin; hin = hout; hout = t;
    }

    k_readout<<<64, 384>>>(hin, gid);
    k_mlp<<<1, 512>>>(Wc1, bc1, Wc2, bc2, Wc3, bc3, out);
}

// round 4
// speedup vs baseline: 1.0877x; 1.0330x over previous
#include <cuda_runtime.h>
#include <math.h>

#define Nn 50000
#define Ee 800000
#define INF 128
#define HIDf 96
#define Hh 8
#define Dd 12
#define Gg 64
#define OUTf 10
#define NB_SCAN ((Nn + 511) / 512)   // 98

// ---------------- scratch (device globals; no allocation allowed) ------------
__device__ __align__(16) float g_tmp[Nn * HIDf];
__device__ __align__(16) float g_h0[Nn * HIDf];
__device__ __align__(16) float g_h1[Nn * HIDf];
__device__ __align__(16) float g_fs[Nn * HIDf];
__device__ __align__(16) float g_fd[Nn * HIDf];
__device__ __align__(16) float g_logits[Ee * Hh];
__device__ int   g_degout[Nn];
__device__ int   g_degin[Nn];
__device__ int   g_fill[Nn];
__device__ int   g_rowptr[Nn + 1];
__device__ int   g_esrc[Ee];
__device__ int   g_edst[Ee];
__device__ int   g_part[128];
__device__ int   g_hg[Gg * HIDf];
__device__ float g_dinvout[Nn];
__device__ float g_dinvin[Nn];

// ---------------- init ----------------
__global__ void k_init() {
    int i = blockIdx.x * blockDim.x + threadIdx.x;
    if (i < Nn) { g_degout[i] = 0; g_degin[i] = 0; g_fill[i] = 0; }
    if (i < Gg * HIDf) g_hg[i] = 0;   // bits of +0.0f; readout inputs are >= 0
}

// ---------------- degrees / histogram ----------------
__global__ void k_degree(const int* __restrict__ src, const int* __restrict__ dst) {
    int e = blockIdx.x * blockDim.x + threadIdx.x;
    if (e < Ee) {
        atomicAdd(&g_degout[src[e]], 1);
        atomicAdd(&g_degin[dst[e]], 1);
    }
}

// ---------------- deg^-0.5 (clamped >= 1) ----------------
__global__ void k_dinv() {
    int i = blockIdx.x * blockDim.x + threadIdx.x;
    if (i < Nn) {
        g_dinvout[i] = rsqrtf((float)max(g_degout[i], 1));
        g_dinvin[i]  = rsqrtf((float)max(g_degin[i], 1));
    }
}

// ---------------- exclusive scan of g_degin -> g_rowptr ----------------
__global__ void k_scan1() {
    __shared__ int s[512];
    int t = threadIdx.x;
    int idx = blockIdx.x * 512 + t;
    int v = (idx < Nn) ? g_degin[idx] : 0;
    s[t] = v;
    __syncthreads();
    for (int off = 1; off < 512; off <<= 1) {
        int x = (t >= off) ? s[t - off] : 0;
        __syncthreads();
        s[t] += x;
        __syncthreads();
    }
    if (idx < Nn) g_rowptr[idx] = s[t] - v;
    if (t == 511) g_part[blockIdx.x] = s[511];
}

__global__ void k_scan2() {
    __shared__ int s[128];
    int t = threadIdx.x;
    int v = (t < NB_SCAN) ? g_part[t] : 0;
    s[t] = v;
    __syncthreads();
    for (int off = 1; off < 128; off <<= 1) {
        int x = (t >= off) ? s[t - off] : 0;
        __syncthreads();
        s[t] += x;
        __syncthreads();
    }
    if (t < NB_SCAN) g_part[t] = s[t] - v;
}

__global__ void k_scan3() {
    int idx = blockIdx.x * blockDim.x + threadIdx.x;
    if (idx < Nn) g_rowptr[idx] += g_part[idx >> 9];
    if (idx == 0) g_rowptr[Nn] = Ee;
}

// ---------------- CSR fill (edges grouped by dst) ----------------
__global__ void k_fill(const int* __restrict__ src, const int* __restrict__ dst) {
    int e = blockIdx.x * blockDim.x + threadIdx.x;
    if (e < Ee) {
        int d = dst[e];
        int pos = g_rowptr[d] + atomicAdd(&g_fill[d], 1);
        g_esrc[pos] = src[e];
        g_edst[pos] = d;
    }
}

// ---------------- GEMM: out[N,96] = (in [* dinvout]) @ W [+ bias] ----------------
// block tile 64 rows x 96 cols, threads (12,16)=192, 4x8 micro-tile.
// ~60 regs -> ~5 blocks/SM (30 warps, ~47% occ). float4 global loads.
__global__ void __launch_bounds__(192)
k_gemm(const float* __restrict__ in, const float* __restrict__ W,
       const float* __restrict__ bias, int use_rowscale,
       float* __restrict__ out, int kin) {
    __shared__ float sW[32][HIDf];     // 12 KB
    __shared__ float sIn[64][33];      // 8.4 KB
    int tx = threadIdx.x;              // 0..11 -> cols 8*tx..8*tx+7
    int ty = threadIdx.y;              // 0..15 -> rows 4*ty..4*ty+3
    int tid = ty * 12 + tx;            // 0..191
    int rowBase = blockIdx.x * 64;
    float acc[4][8] = {};

    for (int kc = 0; kc < kin; kc += 32) {
        // stage W chunk: 32x96 = 768 float4
#pragma unroll
        for (int i = tid; i < 768; i += 192) {
            int kk = i / 24, c4 = (i % 24) * 4;
            float4 w = *(const float4*)&W[(kc + kk) * HIDf + c4];
            *(float4*)&sW[kk][c4] = w;
        }
        // stage input chunk: 64 rows x 8 float4
#pragma unroll
        for (int i = tid; i < 512; i += 192) {
            int r = i >> 3, k4 = (i & 7) * 4;
            int row = rowBase + r;
            float4 v = make_float4(0.f, 0.f, 0.f, 0.f);
            if (row < Nn) {
                v = *(const float4*)&in[row * kin + kc + k4];
                if (use_rowscale) {
                    float sc = g_dinvout[row];
                    v.x *= sc; v.y *= sc; v.z *= sc; v.w *= sc;
                }
            }
            sIn[r][k4]     = v.x;
            sIn[r][k4 + 1] = v.y;
            sIn[r][k4 + 2] = v.z;
            sIn[r][k4 + 3] = v.w;
        }
        __syncthreads();
#pragma unroll
        for (int k = 0; k < 32; k++) {
            float4 b0 = *(const float4*)&sW[k][tx * 8];
            float4 b1 = *(const float4*)&sW[k][tx * 8 + 4];
            float a[4];
#pragma unroll
            for (int i = 0; i < 4; i++) a[i] = sIn[ty * 4 + i][k];
#pragma unroll
            for (int i = 0; i < 4; i++) {
                acc[i][0] += a[i] * b0.x; acc[i][1] += a[i] * b0.y;
                acc[i][2] += a[i] * b0.z; acc[i][3] += a[i] * b0.w;
                acc[i][4] += a[i] * b1.x; acc[i][5] += a[i] * b1.y;
                acc[i][6] += a[i] * b1.z; acc[i][7] += a[i] * b1.w;
            }
        }
        __syncthreads();
    }
    float bb[8];
#pragma unroll
    for (int j = 0; j < 8; j++) bb[j] = bias ? bias[tx * 8 + j] : 0.f;
#pragma unroll
    for (int i = 0; i < 4; i++) {
        int row = rowBase + ty * 4 + i;
        if (row < Nn) {
            float4 o0, o1;
            o0.x = acc[i][0] + bb[0]; o0.y = acc[i][1] + bb[1];
            o0.z = acc[i][2] + bb[2]; o0.w = acc[i][3] + bb[3];
            o1.x = acc[i][4] + bb[4]; o1.y = acc[i][5] + bb[5];
            o1.z = acc[i][6] + bb[6]; o1.w = acc[i][7] + bb[7];
            *(float4*)(out + row * HIDf + tx * 8)     = o0;
            *(float4*)(out + row * HIDf + tx * 8 + 4) = o1;
        }
    }
}

// ---------------- GraphConv aggregation: out = relu(sum_in(pre[src]) * dinvin + b)
__global__ void k_agg(const float* __restrict__ pre, const float* __restrict__ bias,
                      float* __restrict__ out) {
    int warp = (blockIdx.x * blockDim.x + threadIdx.x) >> 5;
    int lane = threadIdx.x & 31;
    if (warp >= Nn) return;
    int beg = g_rowptr[warp], end = g_rowptr[warp + 1];
    float a0 = 0.f, a1 = 0.f, a2 = 0.f;
    for (int p = beg; p < end; p++) {
        const float* r = pre + g_esrc[p] * HIDf;
        a0 += r[lane];
        a1 += r[lane + 32];
        a2 += r[lane + 64];
    }
    float sc = g_dinvin[warp];
    out[warp * HIDf + lane]      = fmaxf(a0 * sc + bias[lane], 0.f);
    out[warp * HIDf + lane + 32] = fmaxf(a1 * sc + bias[lane + 32], 0.f);
    out[warp * HIDf + lane + 64] = fmaxf(a2 * sc + bias[lane + 64], 0.f);
}

// ---------------- GATv2 edge logits (dst-sorted order) ----------------
__global__ void k_logits(const float* __restrict__ attn) {
    int idx = blockIdx.x * blockDim.x + threadIdx.x;
    if (idx >= Ee * Hh) return;
    int p = idx >> 3, h = idx & 7;
    int s = g_esrc[p], d = g_edst[p];
    const float4* fsp = (const float4*)(g_fs + s * HIDf + h * Dd);
    const float4* fdp = (const float4*)(g_fd + d * HIDf + h * Dd);
    float lg = 0.f;
#pragma unroll
    for (int j = 0; j < 3; j++) {
        float4 a = fsp[j];
        float4 b = fdp[j];
        float v;
        v = a.x + b.x; v = (v > 0.f) ? v : 0.2f * v; lg += v * __ldg(attn + h * Dd + j * 4 + 0);
        v = a.y + b.y; v = (v > 0.f) ? v : 0.2f * v; lg += v * __ldg(attn + h * Dd + j * 4 + 1);
        v = a.z + b.z; v = (v > 0.f) ? v : 0.2f * v; lg += v * __ldg(attn + h * Dd + j * 4 + 2);
        v = a.w + b.w; v = (v > 0.f) ? v : 0.2f * v; lg += v * __ldg(attn + h * Dd + j * 4 + 3);
    }
    g_logits[idx] = lg;   // idx == p*8 + h
}

// ---------------- GATv2 per-node softmax + weighted sum + relu ----------------
__global__ void k_gatnode(float* __restrict__ out) {
    int warp = (blockIdx.x * blockDim.x + threadIdx.x) >> 5;
    int lane = threadIdx.x & 31;
    if (warp >= Nn) return;
    int beg = g_rowptr[warp], end = g_rowptr[warp + 1];
    int h = lane & 7, sub = lane >> 3;

    float mh = -3.402823466e38f;
    for (int p = beg + sub; p < end; p += 4) mh = fmaxf(mh, g_logits[p * 8 + h]);
    mh = fmaxf(mh, __shfl_xor_sync(0xffffffffu, mh, 8));
    mh = fmaxf(mh, __shfl_xor_sync(0xffffffffu, mh, 16));

    float den = 0.f;
    for (int p = beg + sub; p < end; p += 4) den += __expf(g_logits[p * 8 + h] - mh);
    den += __shfl_xor_sync(0xffffffffu, den, 8);
    den += __shfl_xor_sync(0xffffffffu, den, 16);

    int f0 = lane, f1 = lane + 32, f2 = lane + 64;
    int h0 = f0 / Dd, h1 = f1 / Dd, h2 = f2 / Dd;
    float m0 = __shfl_sync(0xffffffffu, mh, h0);
    float m1 = __shfl_sync(0xffffffffu, mh, h1);
    float m2 = __shfl_sync(0xffffffffu, mh, h2);
    float d0 = __shfl_sync(0xffffffffu, den, h0);
    float d1 = __shfl_sync(0xffffffffu, den, h1);
    float d2 = __shfl_sync(0xffffffffu, den, h2);
    float r0 = (d0 > 0.f) ? 1.f / d0 : 0.f;
    float r1 = (d1 > 0.f) ? 1.f / d1 : 0.f;
    float r2 = (d2 > 0.f) ? 1.f / d2 : 0.f;

    float acc0 = 0.f, acc1 = 0.f, acc2 = 0.f;
    for (int p = beg; p < end; p++) {
        const float* lg = g_logits + p * 8;
        float a0 = __expf(lg[h0] - m0) * r0;
        float a1 = __expf(lg[h1] - m1) * r1;
        float a2 = __expf(lg[h2] - m2) * r2;
        const float* fr = g_fs + g_esrc[p] * HIDf;
        acc0 += a0 * fr[f0];
        acc1 += a1 * fr[f1];
        acc2 += a2 * fr[f2];
    }
    out[warp * HIDf + f0] = fmaxf(acc0, 0.f);
    out[warp * HIDf + f1] = fmaxf(acc1, 0.f);
    out[warp * HIDf + f2] = fmaxf(acc2, 0.f);
}

// ---------------- per-graph max readout (values >= 0 after relu) ----------------
__global__ void k_readout(const float* __restrict__ hfin, const int* __restrict__ gid) {
    __shared__ int s[Gg * HIDf];
    int tid = threadIdx.x;  // 384
    for (int i = tid; i < Gg * HIDf; i += 384) s[i] = 0;
    __syncthreads();
    int f = tid % 96, rr = tid / 96;
    for (int node = blockIdx.x * 4 + rr; node < Nn; node += 64 * 4) {
        int g = gid[node];
        float v = hfin[node * HIDf + f];
        atomicMax(&s[g * HIDf + f], __float_as_int(v));
    }
    __syncthreads();
    for (int i = tid; i < Gg * HIDf; i += 384) atomicMax(&g_hg[i], s[i]);
}

// ---------------- classifier MLP on [64,96] ----------------
__global__ void k_mlp(const float* __restrict__ Wc1, const float* __restrict__ bc1,
                      const float* __restrict__ Wc2, const float* __restrict__ bc2,
                      const float* __restrict__ Wc3, const float* __restrict__ bc3,
                      float* __restrict__ out) {
    __shared__ float A[Gg * HIDf];
    __shared__ float B[Gg * HIDf];
    int tid = threadIdx.x;  // 512
    for (int i = tid; i < Gg * HIDf; i += 512) A[i] = __int_as_float(g_hg[i]);
    __syncthreads();
    for (int i = tid; i < Gg * HIDf; i += 512) {
        int r = i / 96, c = i % 96;
        float acc = bc1[c];
        for (int k = 0; k < 96; k++) acc += A[r * 96 + k] * Wc1[k * 96 + c];
        B[i] = fmaxf(acc, 0.f);
    }
    __syncthreads();
    for (int i = tid; i < Gg * 48; i += 512) {
        int r = i / 48, c = i % 48;
        float acc = bc2[c];
        for (int k = 0; k < 96; k++) acc += B[r * 96 + k] * Wc2[k * 48 + c];
        A[i] = fmaxf(acc, 0.f);
    }
    __syncthreads();
    for (int i = tid; i < Gg * OUTf; i += 512) {
        int r = i / 10, c = i % 10;
        float acc = bc3[c];
        for (int k = 0; k < 48; k++) acc += A[r * 48 + k] * Wc3[k * 10 + c];
        out[i] = acc;
    }
}

// ---------------- host launcher ----------------
extern "C" void kernel_launch(void* const* d_in, const int* in_sizes, int n_in,
                              void* d_out, int out_size) {
    (void)in_sizes; (void)n_in; (void)out_size;
    const float* x    = (const float*)d_in[0];
    const int*   src  = (const int*)d_in[1];
    const int*   dst  = (const int*)d_in[2];
    const int*   gid  = (const int*)d_in[3];
    const float* W1   = (const float*)d_in[4];
    const float* b1   = (const float*)d_in[5];
    const float* W2   = (const float*)d_in[6];
    const float* b2   = (const float*)d_in[7];
    const float* Ws   = (const float*)d_in[8];
    const float* bs   = (const float*)d_in[9];
    const float* Wd   = (const float*)d_in[10];
    const float* bd   = (const float*)d_in[11];
    const float* attn = (const float*)d_in[12];
    const float* Wc1  = (const float*)d_in[13];
    const float* bc1  = (const float*)d_in[14];
    const float* Wc2  = (const float*)d_in[15];
    const float* bc2  = (const float*)d_in[16];
    const float* Wc3  = (const float*)d_in[17];
    const float* bc3  = (const float*)d_in[18];
    float* out = (float*)d_out;

    float *p_tmp, *p_h0, *p_h1, *p_fs, *p_fd;
    cudaGetSymbolAddress((void**)&p_tmp, g_tmp);
    cudaGetSymbolAddress((void**)&p_h0, g_h0);
    cudaGetSymbolAddress((void**)&p_h1, g_h1);
    cudaGetSymbolAddress((void**)&p_fs, g_fs);
    cudaGetSymbolAddress((void**)&p_fd, g_fd);

    const int TPB = 256;
    dim3 gb(12, 16);
    int gemm_blocks = (Nn + 63) / 64;             // 782
    int warp_blocks = (Nn * 32 + TPB - 1) / TPB;  // 6250
    int edge_blocks = (Ee + TPB - 1) / TPB;       // 3125
    int logit_blocks = (Ee * Hh + TPB - 1) / TPB; // 25000

    // ncu captures launch index 3 -> keep first GEMM there
    k_init<<<(Nn + TPB - 1) / TPB, TPB>>>();                         // 0
    k_degree<<<edge_blocks, TPB>>>(src, dst);                        // 1
    k_dinv<<<(Nn + TPB - 1) / TPB, TPB>>>();                         // 2
    k_gemm<<<gemm_blocks, gb>>>(x, W1, nullptr, 1, p_tmp, INF);      // 3  <- profiled
    k_scan1<<<NB_SCAN, 512>>>();                                     // 4
    k_scan2<<<1, 128>>>();                                           // 5
    k_scan3<<<NB_SCAN, 512>>>();                                     // 6
    k_fill<<<edge_blocks, TPB>>>(src, dst);                          // 7
    k_agg<<<warp_blocks, TPB>>>(p_tmp, b1, p_h0);                    // 8

    k_gemm<<<gemm_blocks, gb>>>(p_h0, W2, nullptr, 1, p_tmp, HIDf);
    k_agg<<<warp_blocks, TPB>>>(p_tmp, b2, p_h1);

    float* hin = p_h1;
    float* hout = p_h0;
    for (int i = 0; i < 3; i++) {
        k_gemm<<<gemm_blocks, gb>>>(hin, Ws + i * HIDf * HIDf, bs + i * HIDf, 0, p_fs, HIDf);
        k_gemm<<<gemm_blocks, gb>>>(hin, Wd + i * HIDf * HIDf, bd + i * HIDf, 0, p_fd, HIDf);
        k_logits<<<logit_blocks, TPB>>>(attn + i * Hh * Dd);
        k_gatnode<<<warp_blocks, TPB>>>(hout);
        float* t = hin; hin = hout; hout = t;
    }

    k_readout<<<64, 384>>>(hin, gid);
    k_mlp<<<1, 512>>>(Wc1, bc1, Wc2, bc2, Wc3, bc3, out);
}

// round 5
// speedup vs baseline: 1.1156x; 1.0257x over previous
#include <cuda_runtime.h>
#include <math.h>

#define Nn 50000
#define Ee 800000
#define INF 128
#define HIDf 96
#define Hh 8
#define Dd 12
#define Gg 64
#define OUTf 10
#define NB_SCAN ((Nn + 511) / 512)   // 98

// ---------------- scratch (device globals; no allocation allowed) ------------
__device__ __align__(16) float g_tmp[Nn * HIDf];
__device__ __align__(16) float g_h0[Nn * HIDf];
__device__ __align__(16) float g_h1[Nn * HIDf];
__device__ __align__(16) float g_fs[Nn * HIDf];
__device__ __align__(16) float g_fd[Nn * HIDf];
__device__ __align__(16) float g_logits[Ee * Hh];
__device__ int   g_degout[Nn];
__device__ int   g_degin[Nn];
__device__ int   g_fill[Nn];
__device__ int   g_rowptr[Nn + 1];
__device__ int   g_esrc[Ee];
__device__ int   g_edst[Ee];
__device__ int   g_part[128];
__device__ int   g_hg[Gg * HIDf];
__device__ float g_dinvout[Nn];
__device__ float g_dinvin[Nn];

// ---------------- packed f32x2 helpers (sm_103a FFMA2 path) ----------------
__device__ __forceinline__ unsigned long long pack2(float x) {
    unsigned long long r;
    asm("mov.b64 %0, {%1, %1};" : "=l"(r) : "f"(x));
    return r;
}
__device__ __forceinline__ unsigned long long fma2(unsigned long long a,
                                                   unsigned long long b,
                                                   unsigned long long c) {
    unsigned long long d;
    asm("fma.rn.f32x2 %0, %1, %2, %3;" : "=l"(d) : "l"(a), "l"(b), "l"(c));
    return d;
}
__device__ __forceinline__ unsigned long long add2(unsigned long long a,
                                                   unsigned long long b) {
    unsigned long long d;
    asm("add.rn.f32x2 %0, %1, %2;" : "=l"(d) : "l"(a), "l"(b));
    return d;
}

// ---------------- init ----------------
__global__ void k_init() {
    int i = blockIdx.x * blockDim.x + threadIdx.x;
    if (i < Nn) { g_degout[i] = 0; g_degin[i] = 0; g_fill[i] = 0; }
    if (i < Gg * HIDf) g_hg[i] = 0;   // bits of +0.0f; readout inputs are >= 0
}

// ---------------- degrees / histogram ----------------
__global__ void k_degree(const int* __restrict__ src, const int* __restrict__ dst) {
    int e = blockIdx.x * blockDim.x + threadIdx.x;
    if (e < Ee) {
        atomicAdd(&g_degout[src[e]], 1);
        atomicAdd(&g_degin[dst[e]], 1);
    }
}

// ---------------- deg^-0.5 (clamped >= 1) ----------------
__global__ void k_dinv() {
    int i = blockIdx.x * blockDim.x + threadIdx.x;
    if (i < Nn) {
        g_dinvout[i] = rsqrtf((float)max(g_degout[i], 1));
        g_dinvin[i]  = rsqrtf((float)max(g_degin[i], 1));
    }
}

// ---------------- exclusive scan of g_degin -> g_rowptr ----------------
__global__ void k_scan1() {
    __shared__ int s[512];
    int t = threadIdx.x;
    int idx = blockIdx.x * 512 + t;
    int v = (idx < Nn) ? g_degin[idx] : 0;
    s[t] = v;
    __syncthreads();
    for (int off = 1; off < 512; off <<= 1) {
        int x = (t >= off) ? s[t - off] : 0;
        __syncthreads();
        s[t] += x;
        __syncthreads();
    }
    if (idx < Nn) g_rowptr[idx] = s[t] - v;
    if (t == 511) g_part[blockIdx.x] = s[511];
}

__global__ void k_scan2() {
    __shared__ int s[128];
    int t = threadIdx.x;
    int v = (t < NB_SCAN) ? g_part[t] : 0;
    s[t] = v;
    __syncthreads();
    for (int off = 1; off < 128; off <<= 1) {
        int x = (t >= off) ? s[t - off] : 0;
        __syncthreads();
        s[t] += x;
        __syncthreads();
    }
    if (t < NB_SCAN) g_part[t] = s[t] - v;
}

__global__ void k_scan3() {
    int idx = blockIdx.x * blockDim.x + threadIdx.x;
    if (idx < Nn) g_rowptr[idx] += g_part[idx >> 9];
    if (idx == 0) g_rowptr[Nn] = Ee;
}

// ---------------- CSR fill (edges grouped by dst) ----------------
__global__ void k_fill(const int* __restrict__ src, const int* __restrict__ dst) {
    int e = blockIdx.x * blockDim.x + threadIdx.x;
    if (e < Ee) {
        int d = dst[e];
        int pos = g_rowptr[d] + atomicAdd(&g_fill[d], 1);
        g_esrc[pos] = src[e];
        g_edst[pos] = d;
    }
}

// ---------------- GEMM: out[N,96] = (in [* dinvout]) @ W [+ bias] ----------------
// 64x96 tile, (12,16)=192 threads, 4x8 micro-tile with packed fma.rn.f32x2:
// 16 FFMA2 + 4 packs per k-step instead of 32 FFMA -> half the issue pressure.
__global__ void __launch_bounds__(192, 4)
k_gemm(const float* __restrict__ in, const float* __restrict__ W,
       const float* __restrict__ bias, int use_rowscale,
       float* __restrict__ out, int kin) {
    __shared__ float sW[32][HIDf];     // 12 KB
    __shared__ float sIn[64][33];      // 8.4 KB
    int tx = threadIdx.x;              // 0..11 -> cols 8*tx..8*tx+7
    int ty = threadIdx.y;              // 0..15 -> rows 4*ty..4*ty+3
    int tid = ty * 12 + tx;            // 0..191
    int rowBase = blockIdx.x * 64;
    unsigned long long acc[4][4] = {};   // 4 rows x 4 col-pairs (f32x2)

    for (int kc = 0; kc < kin; kc += 32) {
        for (int i = tid; i < 768; i += 192) {          // W chunk: 32x96 = 768 float4
            int kk = i / 24, c4 = (i % 24) * 4;
            *(float4*)&sW[kk][c4] = *(const float4*)&W[(kc + kk) * HIDf + c4];
        }
        for (int i = tid; i < 512; i += 192) {          // In chunk: 64 rows x 8 float4
            int r = i >> 3, k4 = (i & 7) * 4;
            int row = rowBase + r;
            float4 v = make_float4(0.f, 0.f, 0.f, 0.f);
            if (row < Nn) {
                v = *(const float4*)&in[row * kin + kc + k4];
                if (use_rowscale) {
                    float sc = g_dinvout[row];
                    v.x *= sc; v.y *= sc; v.z *= sc; v.w *= sc;
                }
            }
            sIn[r][k4]     = v.x;
            sIn[r][k4 + 1] = v.y;
            sIn[r][k4 + 2] = v.z;
            sIn[r][k4 + 3] = v.w;
        }
        __syncthreads();
#pragma unroll
        for (int k = 0; k < 32; k++) {
            ulonglong2 b01 = *(const ulonglong2*)&sW[k][tx * 8];       // cols 8tx..8tx+3
            ulonglong2 b23 = *(const ulonglong2*)&sW[k][tx * 8 + 4];   // cols 8tx+4..8tx+7
#pragma unroll
            for (int i = 0; i < 4; i++) {
                unsigned long long aa = pack2(sIn[ty * 4 + i][k]);
                acc[i][0] = fma2(aa, b01.x, acc[i][0]);
                acc[i][1] = fma2(aa, b01.y, acc[i][1]);
                acc[i][2] = fma2(aa, b23.x, acc[i][2]);
                acc[i][3] = fma2(aa, b23.y, acc[i][3]);
            }
        }
        __syncthreads();
    }
    unsigned long long bv[4] = {0ull, 0ull, 0ull, 0ull};
    if (bias) {
        const unsigned long long* bq = (const unsigned long long*)(bias + tx * 8);
        bv[0] = bq[0]; bv[1] = bq[1]; bv[2] = bq[2]; bv[3] = bq[3];
    }
#pragma unroll
    for (int i = 0; i < 4; i++) {
        int row = rowBase + ty * 4 + i;
        if (row < Nn) {
            float* o = out + row * HIDf + tx * 8;
#pragma unroll
            for (int j = 0; j < 4; j++) {
                unsigned long long r = add2(acc[i][j], bv[j]);
                *(unsigned long long*)(o + j * 2) = r;   // two adjacent cols
            }
        }
    }
}

// ---------------- GraphConv aggregation: out = relu(sum_in(pre[src]) * dinvin + b)
__global__ void k_agg(const float* __restrict__ pre, const float* __restrict__ bias,
                      float* __restrict__ out) {
    int warp = (blockIdx.x * blockDim.x + threadIdx.x) >> 5;
    int lane = threadIdx.x & 31;
    if (warp >= Nn) return;
    int beg = g_rowptr[warp], end = g_rowptr[warp + 1];
    float a0 = 0.f, a1 = 0.f, a2 = 0.f;
    for (int p = beg; p < end; p++) {
        const float* r = pre + g_esrc[p] * HIDf;
        a0 += r[lane];
        a1 += r[lane + 32];
        a2 += r[lane + 64];
    }
    float sc = g_dinvin[warp];
    out[warp * HIDf + lane]      = fmaxf(a0 * sc + bias[lane], 0.f);
    out[warp * HIDf + lane + 32] = fmaxf(a1 * sc + bias[lane + 32], 0.f);
    out[warp * HIDf + lane + 64] = fmaxf(a2 * sc + bias[lane + 64], 0.f);
}

// ---------------- GATv2 edge logits (dst-sorted order) ----------------
__global__ void k_logits(const float* __restrict__ attn) {
    int idx = blockIdx.x * blockDim.x + threadIdx.x;
    if (idx >= Ee * Hh) return;
    int p = idx >> 3, h = idx & 7;
    int s = g_esrc[p], d = g_edst[p];
    const float4* fsp = (const float4*)(g_fs + s * HIDf + h * Dd);
    const float4* fdp = (const float4*)(g_fd + d * HIDf + h * Dd);
    float lg = 0.f;
#pragma unroll
    for (int j = 0; j < 3; j++) {
        float4 a = fsp[j];
        float4 b = fdp[j];
        float v;
        v = a.x + b.x; v = (v > 0.f) ? v : 0.2f * v; lg += v * __ldg(attn + h * Dd + j * 4 + 0);
        v = a.y + b.y; v = (v > 0.f) ? v : 0.2f * v; lg += v * __ldg(attn + h * Dd + j * 4 + 1);
        v = a.z + b.z; v = (v > 0.f) ? v : 0.2f * v; lg += v * __ldg(attn + h * Dd + j * 4 + 2);
        v = a.w + b.w; v = (v > 0.f) ? v : 0.2f * v; lg += v * __ldg(attn + h * Dd + j * 4 + 3);
    }
    g_logits[idx] = lg;   // idx == p*8 + h
}

// ---------------- GATv2 per-node softmax + weighted sum + relu ----------------
__global__ void k_gatnode(float* __restrict__ out) {
    int warp = (blockIdx.x * blockDim.x + threadIdx.x) >> 5;
    int lane = threadIdx.x & 31;
    if (warp >= Nn) return;
    int beg = g_rowptr[warp], end = g_rowptr[warp + 1];
    int h = lane & 7, sub = lane >> 3;

    float mh = -3.402823466e38f;
    for (int p = beg + sub; p < end; p += 4) mh = fmaxf(mh, g_logits[p * 8 + h]);
    mh = fmaxf(mh, __shfl_xor_sync(0xffffffffu, mh, 8));
    mh = fmaxf(mh, __shfl_xor_sync(0xffffffffu, mh, 16));

    float den = 0.f;
    for (int p = beg + sub; p < end; p += 4) den += __expf(g_logits[p * 8 + h] - mh);
    den += __shfl_xor_sync(0xffffffffu, den, 8);
    den += __shfl_xor_sync(0xffffffffu, den, 16);

    int f0 = lane, f1 = lane + 32, f2 = lane + 64;
    int h0 = f0 / Dd, h1 = f1 / Dd, h2 = f2 / Dd;
    float m0 = __shfl_sync(0xffffffffu, mh, h0);
    float m1 = __shfl_sync(0xffffffffu, mh, h1);
    float m2 = __shfl_sync(0xffffffffu, mh, h2);
    float d0 = __shfl_sync(0xffffffffu, den, h0);
    float d1 = __shfl_sync(0xffffffffu, den, h1);
    float d2 = __shfl_sync(0xffffffffu, den, h2);
    float r0 = (d0 > 0.f) ? 1.f / d0 : 0.f;
    float r1 = (d1 > 0.f) ? 1.f / d1 : 0.f;
    float r2 = (d2 > 0.f) ? 1.f / d2 : 0.f;

    float acc0 = 0.f, acc1 = 0.f, acc2 = 0.f;
    for (int p = beg; p < end; p++) {
        const float* lg = g_logits + p * 8;
        float a0 = __expf(lg[h0] - m0) * r0;
        float a1 = __expf(lg[h1] - m1) * r1;
        float a2 = __expf(lg[h2] - m2) * r2;
        const float* fr = g_fs + g_esrc[p] * HIDf;
        acc0 += a0 * fr[f0];
        acc1 += a1 * fr[f1];
        acc2 += a2 * fr[f2];
    }
    out[warp * HIDf + f0] = fmaxf(acc0, 0.f);
    out[warp * HIDf + f1] = fmaxf(acc1, 0.f);
    out[warp * HIDf + f2] = fmaxf(acc2, 0.f);
}

// ---------------- per-graph max readout (values >= 0 after relu) ----------------
__global__ void k_readout(const float* __restrict__ hfin, const int* __restrict__ gid) {
    __shared__ int s[Gg * HIDf];
    int tid = threadIdx.x;  // 384
    for (int i = tid; i < Gg * HIDf; i += 384) s[i] = 0;
    __syncthreads();
    int f = tid % 96, rr = tid / 96;
    for (int node = blockIdx.x * 4 + rr; node < Nn; node += 64 * 4) {
        int g = gid[node];
        float v = hfin[node * HIDf + f];
        atomicMax(&s[g * HIDf + f], __float_as_int(v));
    }
    __syncthreads();
    for (int i = tid; i < Gg * HIDf; i += 384) atomicMax(&g_hg[i], s[i]);
}

// ---------------- classifier MLP on [64,96] ----------------
__global__ void k_mlp(const float* __restrict__ Wc1, const float* __restrict__ bc1,
                      const float* __restrict__ Wc2, const float* __restrict__ bc2,
                      const float* __restrict__ Wc3, const float* __restrict__ bc3,
                      float* __restrict__ out) {
    __shared__ float A[Gg * HIDf];
    __shared__ float B[Gg * HIDf];
    int tid = threadIdx.x;  // 512
    for (int i = tid; i < Gg * HIDf; i += 512) A[i] = __int_as_float(g_hg[i]);
    __syncthreads();
    for (int i = tid; i < Gg * HIDf; i += 512) {
        int r = i / 96, c = i % 96;
        float acc = bc1[c];
        for (int k = 0; k < 96; k++) acc += A[r * 96 + k] * Wc1[k * 96 + c];
        B[i] = fmaxf(acc, 0.f);
    }
    __syncthreads();
    for (int i = tid; i < Gg * 48; i += 512) {
        int r = i / 48, c = i % 48;
        float acc = bc2[c];
        for (int k = 0; k < 96; k++) acc += B[r * 96 + k] * Wc2[k * 48 + c];
        A[i] = fmaxf(acc, 0.f);
    }
    __syncthreads();
    for (int i = tid; i < Gg * OUTf; i += 512) {
        int r = i / 10, c = i % 10;
        float acc = bc3[c];
        for (int k = 0; k < 48; k++) acc += A[r * 48 + k] * Wc3[k * 10 + c];
        out[i] = acc;
    }
}

// ---------------- host launcher ----------------
extern "C" void kernel_launch(void* const* d_in, const int* in_sizes, int n_in,
                              void* d_out, int out_size) {
    (void)in_sizes; (void)n_in; (void)out_size;
    const float* x    = (const float*)d_in[0];
    const int*   src  = (const int*)d_in[1];
    const int*   dst  = (const int*)d_in[2];
    const int*   gid  = (const int*)d_in[3];
    const float* W1   = (const float*)d_in[4];
    const float* b1   = (const float*)d_in[5];
    const float* W2   = (const float*)d_in[6];
    const float* b2   = (const float*)d_in[7];
    const float* Ws   = (const float*)d_in[8];
    const float* bs   = (const float*)d_in[9];
    const float* Wd   = (const float*)d_in[10];
    const float* bd   = (const float*)d_in[11];
    const float* attn = (const float*)d_in[12];
    const float* Wc1  = (const float*)d_in[13];
    const float* bc1  = (const float*)d_in[14];
    const float* Wc2  = (const float*)d_in[15];
    const float* bc2  = (const float*)d_in[16];
    const float* Wc3  = (const float*)d_in[17];
    const float* bc3  = (const float*)d_in[18];
    float* out = (float*)d_out;

    float *p_tmp, *p_h0, *p_h1, *p_fs, *p_fd;
    cudaGetSymbolAddress((void**)&p_tmp, g_tmp);
    cudaGetSymbolAddress((void**)&p_h0, g_h0);
    cudaGetSymbolAddress((void**)&p_h1, g_h1);
    cudaGetSymbolAddress((void**)&p_fs, g_fs);
    cudaGetSymbolAddress((void**)&p_fd, g_fd);

    const int TPB = 256;
    dim3 gb(12, 16);
    int gemm_blocks = (Nn + 63) / 64;             // 782
    int warp_blocks = (Nn * 32 + TPB - 1) / TPB;  // 6250
    int edge_blocks = (Ee + TPB - 1) / TPB;       // 3125
    int logit_blocks = (Ee * Hh + TPB - 1) / TPB; // 25000

    // ncu captures launch index 3 -> keep first GEMM there
    k_init<<<(Nn + TPB - 1) / TPB, TPB>>>();                         // 0
    k_degree<<<edge_blocks, TPB>>>(src, dst);                        // 1
    k_dinv<<<(Nn + TPB - 1) / TPB, TPB>>>();                         // 2
    k_gemm<<<gemm_blocks, gb>>>(x, W1, nullptr, 1, p_tmp, INF);      // 3  <- profiled
    k_scan1<<<NB_SCAN, 512>>>();                                     // 4
    k_scan2<<<1, 128>>>();                                           // 5
    k_scan3<<<NB_SCAN, 512>>>();                                     // 6
    k_fill<<<edge_blocks, TPB>>>(src, dst);                          // 7
    k_agg<<<warp_blocks, TPB>>>(p_tmp, b1, p_h0);                    // 8

    k_gemm<<<gemm_blocks, gb>>>(p_h0, W2, nullptr, 1, p_tmp, HIDf);
    k_agg<<<warp_blocks, TPB>>>(p_tmp, b2, p_h1);

    float* hin = p_h1;
    float* hout = p_h0;
    for (int i = 0; i < 3; i++) {
        k_gemm<<<gemm_blocks, gb>>>(hin, Ws + i * HIDf * HIDf, bs + i * HIDf, 0, p_fs, HIDf);
        k_gemm<<<gemm_blocks, gb>>>(hin, Wd + i * HIDf * HIDf, bd + i * HIDf, 0, p_fd, HIDf);
        k_logits<<<logit_blocks, TPB>>>(attn + i * Hh * Dd);
        k_gatnode<<<warp_blocks, TPB>>>(hout);
        float* t = hin; hin = hout; hout = t;
    }

    k_readout<<<64, 384>>>(hin, gid);
    k_mlp<<<1, 512>>>(Wc1, bc1, Wc2, bc2, Wc3, bc3, out);
}

// round 6
// speedup vs baseline: 1.1611x; 1.0408x over previous
#include <cuda_runtime.h>
#include <math.h>

#define Nn 50000
#define Ee 800000
#define INF 128
#define HIDf 96
#define Hh 8
#define Dd 12
#define Gg 64
#define OUTf 10
#define NB_SCAN ((Nn + 511) / 512)   // 98

// ---------------- scratch (device globals; no allocation allowed) ------------
__device__ __align__(16) float g_tmp[Nn * HIDf];
__device__ __align__(16) float g_h0[Nn * HIDf];
__device__ __align__(16) float g_h1[Nn * HIDf];
__device__ __align__(16) float g_fs[Nn * HIDf];
__device__ __align__(16) float g_fd[Nn * HIDf];
__device__ __align__(16) float g_logits[Ee * Hh];
__device__ int   g_degout[Nn];
__device__ int   g_degin[Nn];
__device__ int   g_fill[Nn];
__device__ int   g_rowptr[Nn + 1];
__device__ int   g_esrc[Ee];
__device__ int   g_edst[Ee];
__device__ int   g_part[128];
__device__ int   g_hg[Gg * HIDf];
__device__ float g_dinvout[Nn];
__device__ float g_dinvin[Nn];

// ---------------- init ----------------
__global__ void k_init() {
    int i = blockIdx.x * blockDim.x + threadIdx.x;
    if (i < Nn) { g_degout[i] = 0; g_degin[i] = 0; g_fill[i] = 0; }
    if (i < Gg * HIDf) g_hg[i] = 0;   // bits of +0.0f; readout inputs are >= 0
}

// ---------------- degrees / histogram ----------------
__global__ void k_degree(const int* __restrict__ src, const int* __restrict__ dst) {
    int e = blockIdx.x * blockDim.x + threadIdx.x;
    if (e < Ee) {
        atomicAdd(&g_degout[src[e]], 1);
        atomicAdd(&g_degin[dst[e]], 1);
    }
}

// ---------------- deg^-0.5 (clamped >= 1) ----------------
__global__ void k_dinv() {
    int i = blockIdx.x * blockDim.x + threadIdx.x;
    if (i < Nn) {
        g_dinvout[i] = rsqrtf((float)max(g_degout[i], 1));
        g_dinvin[i]  = rsqrtf((float)max(g_degin[i], 1));
    }
}

// ---------------- exclusive scan of g_degin -> g_rowptr ----------------
__global__ void k_scan1() {
    __shared__ int s[512];
    int t = threadIdx.x;
    int idx = blockIdx.x * 512 + t;
    int v = (idx < Nn) ? g_degin[idx] : 0;
    s[t] = v;
    __syncthreads();
    for (int off = 1; off < 512; off <<= 1) {
        int x = (t >= off) ? s[t - off] : 0;
        __syncthreads();
        s[t] += x;
        __syncthreads();
    }
    if (idx < Nn) g_rowptr[idx] = s[t] - v;
    if (t == 511) g_part[blockIdx.x] = s[511];
}

__global__ void k_scan2() {
    __shared__ int s[128];
    int t = threadIdx.x;
    int v = (t < NB_SCAN) ? g_part[t] : 0;
    s[t] = v;
    __syncthreads();
    for (int off = 1; off < 128; off <<= 1) {
        int x = (t >= off) ? s[t - off] : 0;
        __syncthreads();
        s[t] += x;
        __syncthreads();
    }
    if (t < NB_SCAN) g_part[t] = s[t] - v;
}

__global__ void k_scan3() {
    int idx = blockIdx.x * blockDim.x + threadIdx.x;
    if (idx < Nn) g_rowptr[idx] += g_part[idx >> 9];
    if (idx == 0) g_rowptr[Nn] = Ee;
}

// ---------------- CSR fill (edges grouped by dst) ----------------
__global__ void k_fill(const int* __restrict__ src, const int* __restrict__ dst) {
    int e = blockIdx.x * blockDim.x + threadIdx.x;
    if (e < Ee) {
        int d = dst[e];
        int pos = g_rowptr[d] + atomicAdd(&g_fill[d], 1);
        g_esrc[pos] = src[e];
        g_edst[pos] = d;
    }
}

// ---------------- GEMM (R1-proven): out[N,96] = (in [* dinvout]) @ W [+ bias]
// block tile 64 rows x 96 cols, threads (24,16)=384, 4x4 micro-tile
__global__ void __launch_bounds__(384)
k_gemm(const float* __restrict__ in, const float* __restrict__ W,
       const float* __restrict__ bias, int use_rowscale,
       float* __restrict__ out, int kin) {
    __shared__ float sW[32][HIDf];
    __shared__ float sIn[64][33];
    int tx = threadIdx.x;            // 0..23 -> cols 4*tx..4*tx+3
    int ty = threadIdx.y;            // 0..15 -> rows 4*ty..4*ty+3
    int tid = ty * 24 + tx;          // 0..383
    int rowBase = blockIdx.x * 64;
    float acc[4][4] = {};

    for (int kc = 0; kc < kin; kc += 32) {
        for (int i = tid; i < 32 * HIDf; i += 384) {
            int kk = i / HIDf, cc = i % HIDf;
            sW[kk][cc] = W[(kc + kk) * HIDf + cc];
        }
        for (int i = tid; i < 64 * 32; i += 384) {
            int r = i >> 5, k = i & 31;
            int row = rowBase + r;
            float v = 0.f;
            if (row < Nn) {
                v = in[row * kin + kc + k];
                if (use_rowscale) v *= g_dinvout[row];
            }
            sIn[r][k] = v;
        }
        __syncthreads();
#pragma unroll
        for (int k = 0; k < 32; k++) {
            float4 b = *(const float4*)&sW[k][tx * 4];
#pragma unroll
            for (int i = 0; i < 4; i++) {
                float a = sIn[ty * 4 + i][k];
                acc[i][0] += a * b.x;
                acc[i][1] += a * b.y;
                acc[i][2] += a * b.z;
                acc[i][3] += a * b.w;
            }
        }
        __syncthreads();
    }
#pragma unroll
    for (int i = 0; i < 4; i++) {
        int row = rowBase + ty * 4 + i;
        if (row < Nn) {
            float4 o;
            float b0 = 0.f, b1 = 0.f, b2 = 0.f, b3 = 0.f;
            if (bias) {
                b0 = bias[tx * 4 + 0]; b1 = bias[tx * 4 + 1];
                b2 = bias[tx * 4 + 2]; b3 = bias[tx * 4 + 3];
            }
            o.x = acc[i][0] + b0; o.y = acc[i][1] + b1;
            o.z = acc[i][2] + b2; o.w = acc[i][3] + b3;
            *(float4*)(out + row * HIDf + tx * 4) = o;
        }
    }
}

// ---------------- dual GEMM for GAT: fs = in@Ws+bs, fd = in@Wd+bd (kin = 96)
// same tiling as k_gemm; input staged once, used for both weight matrices.
__global__ void __launch_bounds__(384)
k_gemm2(const float* __restrict__ in,
        const float* __restrict__ Ws, const float* __restrict__ bsv,
        const float* __restrict__ Wd, const float* __restrict__ bdv,
        float* __restrict__ outs, float* __restrict__ outd) {
    __shared__ float sWs[32][HIDf];
    __shared__ float sWd[32][HIDf];
    __shared__ float sIn[64][33];
    int tx = threadIdx.x;            // 0..23
    int ty = threadIdx.y;            // 0..15
    int tid = ty * 24 + tx;
    int rowBase = blockIdx.x * 64;
    float accs[4][4] = {};
    float accd[4][4] = {};

    for (int kc = 0; kc < HIDf; kc += 32) {
        for (int i = tid; i < 32 * HIDf; i += 384) {
            int kk = i / HIDf, cc = i % HIDf;
            sWs[kk][cc] = Ws[(kc + kk) * HIDf + cc];
            sWd[kk][cc] = Wd[(kc + kk) * HIDf + cc];
        }
        for (int i = tid; i < 64 * 32; i += 384) {
            int r = i >> 5, k = i & 31;
            int row = rowBase + r;
            sIn[r][k] = (row < Nn) ? in[row * HIDf + kc + k] : 0.f;
        }
        __syncthreads();
#pragma unroll
        for (int k = 0; k < 32; k++) {
            float4 bs4 = *(const float4*)&sWs[k][tx * 4];
            float4 bd4 = *(const float4*)&sWd[k][tx * 4];
#pragma unroll
            for (int i = 0; i < 4; i++) {
                float a = sIn[ty * 4 + i][k];
                accs[i][0] += a * bs4.x; accs[i][1] += a * bs4.y;
                accs[i][2] += a * bs4.z; accs[i][3] += a * bs4.w;
                accd[i][0] += a * bd4.x; accd[i][1] += a * bd4.y;
                accd[i][2] += a * bd4.z; accd[i][3] += a * bd4.w;
            }
        }
        __syncthreads();
    }
    float s0 = bsv[tx * 4], s1 = bsv[tx * 4 + 1], s2 = bsv[tx * 4 + 2], s3 = bsv[tx * 4 + 3];
    float d0 = bdv[tx * 4], d1 = bdv[tx * 4 + 1], d2 = bdv[tx * 4 + 2], d3 = bdv[tx * 4 + 3];
#pragma unroll
    for (int i = 0; i < 4; i++) {
        int row = rowBase + ty * 4 + i;
        if (row < Nn) {
            float4 o;
            o.x = accs[i][0] + s0; o.y = accs[i][1] + s1;
            o.z = accs[i][2] + s2; o.w = accs[i][3] + s3;
            *(float4*)(outs + row * HIDf + tx * 4) = o;
            o.x = accd[i][0] + d0; o.y = accd[i][1] + d1;
            o.z = accd[i][2] + d2; o.w = accd[i][3] + d3;
            *(float4*)(outd + row * HIDf + tx * 4) = o;
        }
    }
}

// ---------------- GraphConv aggregation: out = relu(sum_in(pre[src]) * dinvin + b)
__global__ void k_agg(const float* __restrict__ pre, const float* __restrict__ bias,
                      float* __restrict__ out) {
    int warp = (blockIdx.x * blockDim.x + threadIdx.x) >> 5;
    int lane = threadIdx.x & 31;
    if (warp >= Nn) return;
    int beg = g_rowptr[warp], end = g_rowptr[warp + 1];
    float a0 = 0.f, a1 = 0.f, a2 = 0.f;
    for (int p = beg; p < end; p++) {
        const float* r = pre + g_esrc[p] * HIDf;
        a0 += r[lane];
        a1 += r[lane + 32];
        a2 += r[lane + 64];
    }
    float sc = g_dinvin[warp];
    out[warp * HIDf + lane]      = fmaxf(a0 * sc + bias[lane], 0.f);
    out[warp * HIDf + lane + 32] = fmaxf(a1 * sc + bias[lane + 32], 0.f);
    out[warp * HIDf + lane + 64] = fmaxf(a2 * sc + bias[lane + 64], 0.f);
}

// ---------------- GATv2 edge logits (dst-sorted order) ----------------
__global__ void k_logits(const float* __restrict__ attn) {
    int idx = blockIdx.x * blockDim.x + threadIdx.x;
    if (idx >= Ee * Hh) return;
    int p = idx >> 3, h = idx & 7;
    int s = g_esrc[p], d = g_edst[p];
    const float4* fsp = (const float4*)(g_fs + s * HIDf + h * Dd);
    const float4* fdp = (const float4*)(g_fd + d * HIDf + h * Dd);
    float lg = 0.f;
#pragma unroll
    for (int j = 0; j < 3; j++) {
        float4 a = fsp[j];
        float4 b = fdp[j];
        float v;
        v = a.x + b.x; v = (v > 0.f) ? v : 0.2f * v; lg += v * __ldg(attn + h * Dd + j * 4 + 0);
        v = a.y + b.y; v = (v > 0.f) ? v : 0.2f * v; lg += v * __ldg(attn + h * Dd + j * 4 + 1);
        v = a.z + b.z; v = (v > 0.f) ? v : 0.2f * v; lg += v * __ldg(attn + h * Dd + j * 4 + 2);
        v = a.w + b.w; v = (v > 0.f) ? v : 0.2f * v; lg += v * __ldg(attn + h * Dd + j * 4 + 3);
    }
    g_logits[idx] = lg;   // idx == p*8 + h
}

// ---------------- GATv2 per-node softmax + weighted sum + relu ----------------
__global__ void k_gatnode(float* __restrict__ out) {
    int warp = (blockIdx.x * blockDim.x + threadIdx.x) >> 5;
    int lane = threadIdx.x & 31;
    if (warp >= Nn) return;
    int beg = g_rowptr[warp], end = g_rowptr[warp + 1];
    int h = lane & 7, sub = lane >> 3;

    float mh = -3.402823466e38f;
    for (int p = beg + sub; p < end; p += 4) mh = fmaxf(mh, g_logits[p * 8 + h]);
    mh = fmaxf(mh, __shfl_xor_sync(0xffffffffu, mh, 8));
    mh = fmaxf(mh, __shfl_xor_sync(0xffffffffu, mh, 16));

    float den = 0.f;
    for (int p = beg + sub; p < end; p += 4) den += __expf(g_logits[p * 8 + h] - mh);
    den += __shfl_xor_sync(0xffffffffu, den, 8);
    den += __shfl_xor_sync(0xffffffffu, den, 16);

    int f0 = lane, f1 = lane + 32, f2 = lane + 64;
    int h0 = f0 / Dd, h1 = f1 / Dd, h2 = f2 / Dd;
    float m0 = __shfl_sync(0xffffffffu, mh, h0);
    float m1 = __shfl_sync(0xffffffffu, mh, h1);
    float m2 = __shfl_sync(0xffffffffu, mh, h2);
    float d0 = __shfl_sync(0xffffffffu, den, h0);
    float d1 = __shfl_sync(0xffffffffu, den, h1);
    float d2 = __shfl_sync(0xffffffffu, den, h2);
    float r0 = (d0 > 0.f) ? 1.f / d0 : 0.f;
    float r1 = (d1 > 0.f) ? 1.f / d1 : 0.f;
    float r2 = (d2 > 0.f) ? 1.f / d2 : 0.f;

    float acc0 = 0.f, acc1 = 0.f, acc2 = 0.f;
    for (int p = beg; p < end; p++) {
        const float* lg = g_logits + p * 8;
        float a0 = __expf(lg[h0] - m0) * r0;
        float a1 = __expf(lg[h1] - m1) * r1;
        float a2 = __expf(lg[h2] - m2) * r2;
        const float* fr = g_fs + g_esrc[p] * HIDf;
        acc0 += a0 * fr[f0];
        acc1 += a1 * fr[f1];
        acc2 += a2 * fr[f2];
    }
    out[warp * HIDf + f0] = fmaxf(acc0, 0.f);
    out[warp * HIDf + f1] = fmaxf(acc1, 0.f);
    out[warp * HIDf + f2] = fmaxf(acc2, 0.f);
}

// ---------------- per-graph max readout (values >= 0 after relu) ----------------
__global__ void k_readout(const float* __restrict__ hfin, const int* __restrict__ gid) {
    __shared__ int s[Gg * HIDf];
    int tid = threadIdx.x;  // 384
    for (int i = tid; i < Gg * HIDf; i += 384) s[i] = 0;
    __syncthreads();
    int f = tid % 96, rr = tid / 96;
    for (int node = blockIdx.x * 4 + rr; node < Nn; node += 64 * 4) {
        int g = gid[node];
        float v = hfin[node * HIDf + f];
        atomicMax(&s[g * HIDf + f], __float_as_int(v));
    }
    __syncthreads();
    for (int i = tid; i < Gg * HIDf; i += 384) atomicMax(&g_hg[i], s[i]);
}

// ---------------- classifier MLP on [64,96] ----------------
__global__ void k_mlp(const float* __restrict__ Wc1, const float* __restrict__ bc1,
                      const float* __restrict__ Wc2, const float* __restrict__ bc2,
                      const float* __restrict__ Wc3, const float* __restrict__ bc3,
                      float* __restrict__ out) {
    __shared__ float A[Gg * HIDf];
    __shared__ float B[Gg * HIDf];
    int tid = threadIdx.x;  // 512
    for (int i = tid; i < Gg * HIDf; i += 512) A[i] = __int_as_float(g_hg[i]);
    __syncthreads();
    for (int i = tid; i < Gg * HIDf; i += 512) {
        int r = i / 96, c = i % 96;
        float acc = bc1[c];
        for (int k = 0; k < 96; k++) acc += A[r * 96 + k] * Wc1[k * 96 + c];
        B[i] = fmaxf(acc, 0.f);
    }
    __syncthreads();
    for (int i = tid; i < Gg * 48; i += 512) {
        int r = i / 48, c = i % 48;
        float acc = bc2[c];
        for (int k = 0; k < 96; k++) acc += B[r * 96 + k] * Wc2[k * 48 + c];
        A[i] = fmaxf(acc, 0.f);
    }
    __syncthreads();
    for (int i = tid; i < Gg * OUTf; i += 512) {
        int r = i / 10, c = i % 10;
        float acc = bc3[c];
        for (int k = 0; k < 48; k++) acc += A[r * 48 + k] * Wc3[k * 10 + c];
        out[i] = acc;
    }
}

// ---------------- host launcher ----------------
extern "C" void kernel_launch(void* const* d_in, const int* in_sizes, int n_in,
                              void* d_out, int out_size) {
    (void)in_sizes; (void)n_in; (void)out_size;
    const float* x    = (const float*)d_in[0];
    const int*   src  = (const int*)d_in[1];
    const int*   dst  = (const int*)d_in[2];
    const int*   gid  = (const int*)d_in[3];
    const float* W1   = (const float*)d_in[4];
    const float* b1   = (const float*)d_in[5];
    const float* W2   = (const float*)d_in[6];
    const float* b2   = (const float*)d_in[7];
    const float* Ws   = (const float*)d_in[8];
    const float* bs   = (const float*)d_in[9];
    const float* Wd   = (const float*)d_in[10];
    const float* bd   = (const float*)d_in[11];
    const float* attn = (const float*)d_in[12];
    const float* Wc1  = (const float*)d_in[13];
    const float* bc1  = (const float*)d_in[14];
    const float* Wc2  = (const float*)d_in[15];
    const float* bc2  = (const float*)d_in[16];
    const float* Wc3  = (const float*)d_in[17];
    const float* bc3  = (const float*)d_in[18];
    float* out = (float*)d_out;

    float *p_tmp, *p_h0, *p_h1, *p_fs, *p_fd;
    cudaGetSymbolAddress((void**)&p_tmp, g_tmp);
    cudaGetSymbolAddress((void**)&p_h0, g_h0);
    cudaGetSymbolAddress((void**)&p_h1, g_h1);
    cudaGetSymbolAddress((void**)&p_fs, g_fs);
    cudaGetSymbolAddress((void**)&p_fd, g_fd);

    const int TPB = 256;
    dim3 gb(24, 16);
    int gemm_blocks = (Nn + 63) / 64;             // 782
    int warp_blocks = (Nn * 32 + TPB - 1) / TPB;  // 6250
    int edge_blocks = (Ee + TPB - 1) / TPB;       // 3125
    int logit_blocks = (Ee * Hh + TPB - 1) / TPB; // 25000

    // ncu captures launch index 3 -> keep first GEMM there
    k_init<<<(Nn + TPB - 1) / TPB, TPB>>>();                         // 0
    k_degree<<<edge_blocks, TPB>>>(src, dst);                        // 1
    k_dinv<<<(Nn + TPB - 1) / TPB, TPB>>>();                         // 2
    k_gemm<<<gemm_blocks, gb>>>(x, W1, nullptr, 1, p_tmp, INF);      // 3  <- profiled
    k_scan1<<<NB_SCAN, 512>>>();                                     // 4
    k_scan2<<<1, 128>>>();                                           // 5
    k_scan3<<<NB_SCAN, 512>>>();                                     // 6
    k_fill<<<edge_blocks, TPB>>>(src, dst);                          // 7
    k_agg<<<warp_blocks, TPB>>>(p_tmp, b1, p_h0);                    // 8

    k_gemm<<<gemm_blocks, gb>>>(p_h0, W2, nullptr, 1, p_tmp, HIDf);
    k_agg<<<warp_blocks, TPB>>>(p_tmp, b2, p_h1);

    float* hin = p_h1;
    float* hout = p_h0;
    for (int i = 0; i < 3; i++) {
        k_gemm2<<<gemm_blocks, gb>>>(hin,
                                     Ws + i * HIDf * HIDf, bs + i * HIDf,
                                     Wd + i * HIDf * HIDf, bd + i * HIDf,
                                     p_fs, p_fd);
        k_logits<<<logit_blocks, TPB>>>(attn + i * Hh * Dd);
        k_gatnode<<<warp_blocks, TPB>>>(hout);
        float* t = hin; hin = hout; hout = t;
    }

    k_readout<<<64, 384>>>(hin, gid);
    k_mlp<<<1, 512>>>(Wc1, bc1, Wc2, bc2, Wc3, bc3, out);
}

// round 8
// speedup vs baseline: 1.3117x; 1.1297x over previous
#include <cuda_runtime.h>
#include <cuda_bf16.h>
#include <cstdint>
#include <stdint.h>
#include <math.h>

#define Nn 50000
#define Ee 800000
#define INF 128
#define HIDf 96
#define Hh 8
#define Dd 12
#define Gg 64
#define OUTf 10
#define NB_SCAN ((Nn + 511) / 512)   // 98
#define ASTRIDE 40    // 32 + 8 pad (bf16)
#define BSTRIDE 104   // 96 + 8 pad (bf16)

// ---------------- scratch (device globals; no allocation allowed) ------------
__device__ __align__(16) float g_tmp[Nn * HIDf];
__device__ __align__(16) float g_h0[Nn * HIDf];
__device__ __align__(16) float g_h1[Nn * HIDf];
__device__ __align__(16) float g_fs[Nn * HIDf];
__device__ __align__(16) float g_fd[Nn * HIDf];
__device__ __align__(16) float g_logits[Ee * Hh];
__device__ int   g_degout[Nn];
__device__ int   g_degin[Nn];
__device__ int   g_fill[Nn];
__device__ int   g_rowptr[Nn + 1];
__device__ int   g_esrc[Ee];
__device__ int   g_edst[Ee];
__device__ int   g_part[128];
__device__ int   g_hg[Gg * HIDf];
__device__ float g_dinvout[Nn];
__device__ float g_dinvin[Nn];

// ---------------- mma helpers ----------------
__device__ __forceinline__ uint32_t sptr(const void* p) {
    return (uint32_t)__cvta_generic_to_shared(p);
}
__device__ __forceinline__ void ldsm_x4(uint32_t addr, uint32_t& r0, uint32_t& r1,
                                        uint32_t& r2, uint32_t& r3) {
    asm volatile("ldmatrix.sync.aligned.m8n8.x4.shared.b16 {%0,%1,%2,%3}, [%4];"
                 : "=r"(r0), "=r"(r1), "=r"(r2), "=r"(r3) : "r"(addr));
}
__device__ __forceinline__ void ldsm_x4t(uint32_t addr, uint32_t& r0, uint32_t& r1,
                                         uint32_t& r2, uint32_t& r3) {
    asm volatile("ldmatrix.sync.aligned.m8n8.x4.trans.shared.b16 {%0,%1,%2,%3}, [%4];"
                 : "=r"(r0), "=r"(r1), "=r"(r2), "=r"(r3) : "r"(addr));
}
__device__ __forceinline__ void mma_bf16(float* c, const uint32_t* a, const uint32_t* b) {
    asm volatile("mma.sync.aligned.m16n8k16.row.col.f32.bf16.bf16.f32 "
                 "{%0,%1,%2,%3}, {%4,%5,%6,%7}, {%8,%9}, {%0,%1,%2,%3};"
                 : "+f"(c[0]), "+f"(c[1]), "+f"(c[2]), "+f"(c[3])
                 : "r"(a[0]), "r"(a[1]), "r"(a[2]), "r"(a[3]), "r"(b[0]), "r"(b[1]));
}

// ---------------- init ----------------
__global__ void k_init() {
    int i = blockIdx.x * blockDim.x + threadIdx.x;
    if (i < Nn) { g_degout[i] = 0; g_degin[i] = 0; g_fill[i] = 0; }
    if (i < Gg * HIDf) g_hg[i] = 0;   // bits of +0.0f; readout inputs are >= 0
}

// ---------------- degrees / histogram ----------------
__global__ void k_degree(const int* __restrict__ src, const int* __restrict__ dst) {
    int e = blockIdx.x * blockDim.x + threadIdx.x;
    if (e < Ee) {
        atomicAdd(&g_degout[src[e]], 1);
        atomicAdd(&g_degin[dst[e]], 1);
    }
}

// ---------------- deg^-0.5 (clamped >= 1) ----------------
__global__ void k_dinv() {
    int i = blockIdx.x * blockDim.x + threadIdx.x;
    if (i < Nn) {
        g_dinvout[i] = rsqrtf((float)max(g_degout[i], 1));
        g_dinvin[i]  = rsqrtf((float)max(g_degin[i], 1));
    }
}

// ---------------- exclusive scan of g_degin -> g_rowptr ----------------
__global__ void k_scan1() {
    __shared__ int s[512];
    int t = threadIdx.x;
    int idx = blockIdx.x * 512 + t;
    int v = (idx < Nn) ? g_degin[idx] : 0;
    s[t] = v;
    __syncthreads();
    for (int off = 1; off < 512; off <<= 1) {
        int x = (t >= off) ? s[t - off] : 0;
        __syncthreads();
        s[t] += x;
        __syncthreads();
    }
    if (idx < Nn) g_rowptr[idx] = s[t] - v;
    if (t == 511) g_part[blockIdx.x] = s[511];
}

__global__ void k_scan2() {
    __shared__ int s[128];
    int t = threadIdx.x;
    int v = (t < NB_SCAN) ? g_part[t] : 0;
    s[t] = v;
    __syncthreads();
    for (int off = 1; off < 128; off <<= 1) {
        int x = (t >= off) ? s[t - off] : 0;
        __syncthreads();
        s[t] += x;
        __syncthreads();
    }
    if (t < NB_SCAN) g_part[t] = s[t] - v;
}

__global__ void k_scan3() {
    int idx = blockIdx.x * blockDim.x + threadIdx.x;
    if (idx < Nn) g_rowptr[idx] += g_part[idx >> 9];
    if (idx == 0) g_rowptr[Nn] = Ee;
}

// ---------------- CSR fill (edges grouped by dst) ----------------
__global__ void k_fill(const int* __restrict__ src, const int* __restrict__ dst) {
    int e = blockIdx.x * blockDim.x + threadIdx.x;
    if (e < Ee) {
        int d = dst[e];
        int pos = g_rowptr[d] + atomicAdd(&g_fill[d], 1);
        g_esrc[pos] = src[e];
        g_edst[pos] = d;
    }
}

// ---------------- tensor-core GEMM (bf16-split, 3-term): out = (in [*dinvout]) @ W [+ bias]
// 64x96 tile, 128 threads (4 warps); warp (wm, wn) does rows wm*32..+31, cols wn*48..+47
// A@W ~= Ahi@Whi + Ahi@Wlo + Alo@Whi  (split during smem staging; rel err ~1e-5)
__global__ void __launch_bounds__(128)
k_gemm(const float* __restrict__ in, const float* __restrict__ W,
       const float* __restrict__ bias, int use_rowscale,
       float* __restrict__ out, int kin) {
    __shared__ __nv_bfloat16 sAh[64][ASTRIDE];
    __shared__ __nv_bfloat16 sAl[64][ASTRIDE];
    __shared__ __nv_bfloat16 sBh[32][BSTRIDE];
    __shared__ __nv_bfloat16 sBl[32][BSTRIDE];
    int tid = threadIdx.x;
    int lane = tid & 31, wid = tid >> 5;
    int wm = wid & 1, wn = wid >> 1;
    int rowBase = blockIdx.x * 64;

    float acc[2][6][4];
#pragma unroll
    for (int i = 0; i < 2; i++)
#pragma unroll
        for (int j = 0; j < 6; j++)
#pragma unroll
            for (int q = 0; q < 4; q++) acc[i][j][q] = 0.f;

    for (int kc = 0; kc < kin; kc += 32) {
        // stage A (fp32 -> hi/lo bf16), 64x32
        for (int i = tid; i < 64 * 32; i += 128) {
            int r = i >> 5, k = i & 31;
            int row = rowBase + r;
            float v = 0.f;
            if (row < Nn) {
                v = in[row * kin + kc + k];
                if (use_rowscale) v *= g_dinvout[row];
            }
            __nv_bfloat16 h = __float2bfloat16(v);
            sAh[r][k] = h;
            sAl[r][k] = __float2bfloat16(v - __bfloat162float(h));
        }
        // stage W (fp32 -> hi/lo bf16), 32x96
        for (int i = tid; i < 32 * 96; i += 128) {
            int r = i / 96, c = i % 96;
            float v = W[(kc + r) * HIDf + c];
            __nv_bfloat16 h = __float2bfloat16(v);
            sBh[r][c] = h;
            sBl[r][c] = __float2bfloat16(v - __bfloat162float(h));
        }
        __syncthreads();
#pragma unroll
        for (int ks = 0; ks < 32; ks += 16) {
            uint32_t ah[2][4], al[2][4];
#pragma unroll
            for (int i = 0; i < 2; i++) {
                int arow = wm * 32 + i * 16 + (lane & 15);
                int acol = ks + (lane >> 4) * 8;
                ldsm_x4(sptr(&sAh[arow][acol]), ah[i][0], ah[i][1], ah[i][2], ah[i][3]);
                ldsm_x4(sptr(&sAl[arow][acol]), al[i][0], al[i][1], al[i][2], al[i][3]);
            }
            uint32_t bh[6][2], bl[6][2];
#pragma unroll
            for (int j2 = 0; j2 < 3; j2++) {
                int brow = ks + (lane & 15);
                int bcol = wn * 48 + j2 * 16 + (lane >> 4) * 8;
                ldsm_x4t(sptr(&sBh[brow][bcol]),
                         bh[2 * j2][0], bh[2 * j2][1], bh[2 * j2 + 1][0], bh[2 * j2 + 1][1]);
                ldsm_x4t(sptr(&sBl[brow][bcol]),
                         bl[2 * j2][0], bl[2 * j2][1], bl[2 * j2 + 1][0], bl[2 * j2 + 1][1]);
            }
#pragma unroll
            for (int i = 0; i < 2; i++)
#pragma unroll
                for (int j = 0; j < 6; j++) {
                    mma_bf16(acc[i][j], ah[i], bh[j]);
                    mma_bf16(acc[i][j], ah[i], bl[j]);
                    mma_bf16(acc[i][j], al[i], bh[j]);
                }
        }
        __syncthreads();
    }
    // epilogue: c0,c1 -> (row, col..col+1); c2,c3 -> (row+8, ...)
#pragma unroll
    for (int i = 0; i < 2; i++) {
#pragma unroll
        for (int j = 0; j < 6; j++) {
            int r0 = rowBase + wm * 32 + i * 16 + (lane >> 2);
            int c = wn * 48 + j * 8 + (lane & 3) * 2;
            float b0 = 0.f, b1 = 0.f;
            if (bias) { b0 = bias[c]; b1 = bias[c + 1]; }
            if (r0 < Nn) {
                float2 o = make_float2(acc[i][j][0] + b0, acc[i][j][1] + b1);
                *(float2*)&out[r0 * HIDf + c] = o;
            }
            int r1 = r0 + 8;
            if (r1 < Nn) {
                float2 o = make_float2(acc[i][j][2] + b0, acc[i][j][3] + b1);
                *(float2*)&out[r1 * HIDf + c] = o;
            }
        }
    }
}

// ---------------- GraphConv aggregation: out = relu(sum_in(pre[src]) * dinvin + b)
__global__ void k_agg(const float* __restrict__ pre, const float* __restrict__ bias,
                      float* __restrict__ out) {
    int warp = (blockIdx.x * blockDim.x + threadIdx.x) >> 5;
    int lane = threadIdx.x & 31;
    if (warp >= Nn) return;
    int beg = g_rowptr[warp], end = g_rowptr[warp + 1];
    float a0 = 0.f, a1 = 0.f, a2 = 0.f;
    for (int p = beg; p < end; p++) {
        const float* r = pre + g_esrc[p] * HIDf;
        a0 += r[lane];
        a1 += r[lane + 32];
        a2 += r[lane + 64];
    }
    float sc = g_dinvin[warp];
    out[warp * HIDf + lane]      = fmaxf(a0 * sc + bias[lane], 0.f);
    out[warp * HIDf + lane + 32] = fmaxf(a1 * sc + bias[lane + 32], 0.f);
    out[warp * HIDf + lane + 64] = fmaxf(a2 * sc + bias[lane + 64], 0.f);
}

// ---------------- GATv2 edge logits (dst-sorted order) ----------------
__global__ void k_logits(const float* __restrict__ attn) {
    int idx = blockIdx.x * blockDim.x + threadIdx.x;
    if (idx >= Ee * Hh) return;
    int p = idx >> 3, h = idx & 7;
    int s = g_esrc[p], d = g_edst[p];
    const float4* fsp = (const float4*)(g_fs + s * HIDf + h * Dd);
    const float4* fdp = (const float4*)(g_fd + d * HIDf + h * Dd);
    float lg = 0.f;
#pragma unroll
    for (int j = 0; j < 3; j++) {
        float4 a = fsp[j];
        float4 b = fdp[j];
        float v;
        v = a.x + b.x; v = (v > 0.f) ? v : 0.2f * v; lg += v * __ldg(attn + h * Dd + j * 4 + 0);
        v = a.y + b.y; v = (v > 0.f) ? v : 0.2f * v; lg += v * __ldg(attn + h * Dd + j * 4 + 1);
        v = a.z + b.z; v = (v > 0.f) ? v : 0.2f * v; lg += v * __ldg(attn + h * Dd + j * 4 + 2);
        v = a.w + b.w; v = (v > 0.f) ? v : 0.2f * v; lg += v * __ldg(attn + h * Dd + j * 4 + 3);
    }
    g_logits[idx] = lg;   // idx == p*8 + h
}

// ---------------- GATv2 per-node softmax + weighted sum + relu ----------------
__global__ void k_gatnode(float* __restrict__ out) {
    int warp = (blockIdx.x * blockDim.x + threadIdx.x) >> 5;
    int lane = threadIdx.x & 31;
    if (warp >= Nn) return;
    int beg = g_rowptr[warp], end = g_rowptr[warp + 1];
    int h = lane & 7, sub = lane >> 3;

    float mh = -3.402823466e38f;
    for (int p = beg + sub; p < end; p += 4) mh = fmaxf(mh, g_logits[p * 8 + h]);
    mh = fmaxf(mh, __shfl_xor_sync(0xffffffffu, mh, 8));
    mh = fmaxf(mh, __shfl_xor_sync(0xffffffffu, mh, 16));

    float den = 0.f;
    for (int p = beg + sub; p < end; p += 4) den += __expf(g_logits[p * 8 + h] - mh);
    den += __shfl_xor_sync(0xffffffffu, den, 8);
    den += __shfl_xor_sync(0xffffffffu, den, 16);

    int f0 = lane, f1 = lane + 32, f2 = lane + 64;
    int h0 = f0 / Dd, h1 = f1 / Dd, h2 = f2 / Dd;
    float m0 = __shfl_sync(0xffffffffu, mh, h0);
    float m1 = __shfl_sync(0xffffffffu, mh, h1);
    float m2 = __shfl_sync(0xffffffffu, mh, h2);
    float d0 = __shfl_sync(0xffffffffu, den, h0);
    float d1 = __shfl_sync(0xffffffffu, den, h1);
    float d2 = __shfl_sync(0xffffffffu, den, h2);
    float r0 = (d0 > 0.f) ? 1.f / d0 : 0.f;
    float r1 = (d1 > 0.f) ? 1.f / d1 : 0.f;
    float r2 = (d2 > 0.f) ? 1.f / d2 : 0.f;

    float acc0 = 0.f, acc1 = 0.f, acc2 = 0.f;
    for (int p = beg; p < end; p++) {
        const float* lg = g_logits + p * 8;
        float a0 = __expf(lg[h0] - m0) * r0;
        float a1 = __expf(lg[h1] - m1) * r1;
        float a2 = __expf(lg[h2] - m2) * r2;
        const float* fr = g_fs + g_esrc[p] * HIDf;
        acc0 += a0 * fr[f0];
        acc1 += a1 * fr[f1];
        acc2 += a2 * fr[f2];
    }
    out[warp * HIDf + f0] = fmaxf(acc0, 0.f);
    out[warp * HIDf + f1] = fmaxf(acc1, 0.f);
    out[warp * HIDf + f2] = fmaxf(acc2, 0.f);
}

// ---------------- per-graph max readout (values >= 0 after relu) ----------------
__global__ void k_readout(const float* __restrict__ hfin, const int* __restrict__ gid) {
    __shared__ int s[Gg * HIDf];
    int tid = threadIdx.x;  // 384
    for (int i = tid; i < Gg * HIDf; i += 384) s[i] = 0;
    __syncthreads();
    int f = tid % 96, rr = tid / 96;
    for (int node = blockIdx.x * 4 + rr; node < Nn; node += 64 * 4) {
        int g = gid[node];
        float v = hfin[node * HIDf + f];
        atomicMax(&s[g * HIDf + f], __float_as_int(v));
    }
    __syncthreads();
    for (int i = tid; i < Gg * HIDf; i += 384) atomicMax(&g_hg[i], s[i]);
}

// ---------------- classifier MLP on [64,96] ----------------
__global__ void k_mlp(const float* __restrict__ Wc1, const float* __restrict__ bc1,
                      const float* __restrict__ Wc2, const float* __restrict__ bc2,
                      const float* __restrict__ Wc3, const float* __restrict__ bc3,
                      float* __restrict__ out) {
    __shared__ float A[Gg * HIDf];
    __shared__ float B[Gg * HIDf];
    int tid = threadIdx.x;  // 512
    for (int i = tid; i < Gg * HIDf; i += 512) A[i] = __int_as_float(g_hg[i]);
    __syncthreads();
    for (int i = tid; i < Gg * HIDf; i += 512) {
        int r = i / 96, c = i % 96;
        float acc = bc1[c];
        for (int k = 0; k < 96; k++) acc += A[r * 96 + k] * Wc1[k * 96 + c];
        B[i] = fmaxf(acc, 0.f);
    }
    __syncthreads();
    for (int i = tid; i < Gg * 48; i += 512) {
        int r = i / 48, c = i % 48;
        float acc = bc2[c];
        for (int k = 0; k < 96; k++) acc += B[r * 96 + k] * Wc2[k * 48 + c];
        A[i] = fmaxf(acc, 0.f);
    }
    __syncthreads();
    for (int i = tid; i < Gg * OUTf; i += 512) {
        int r = i / 10, c = i % 10;
        float acc = bc3[c];
        for (int k = 0; k < 48; k++) acc += A[r * 48 + k] * Wc3[k * 10 + c];
        out[i] = acc;
    }
}

// ---------------- host launcher ----------------
extern "C" void kernel_launch(void* const* d_in, const int* in_sizes, int n_in,
                              void* d_out, int out_size) {
    (void)in_sizes; (void)n_in; (void)out_size;
    const float* x    = (const float*)d_in[0];
    const int*   src  = (const int*)d_in[1];
    const int*   dst  = (const int*)d_in[2];
    const int*   gid  = (const int*)d_in[3];
    const float* W1   = (const float*)d_in[4];
    const float* b1   = (const float*)d_in[5];
    const float* W2   = (const float*)d_in[6];
    const float* b2   = (const float*)d_in[7];
    const float* Ws   = (const float*)d_in[8];
    const float* bs   = (const float*)d_in[9];
    const float* Wd   = (const float*)d_in[10];
    const float* bd   = (const float*)d_in[11];
    const float* attn = (const float*)d_in[12];
    const float* Wc1  = (const float*)d_in[13];
    const float* bc1  = (const float*)d_in[14];
    const float* Wc2  = (const float*)d_in[15];
    const float* bc2  = (const float*)d_in[16];
    const float* Wc3  = (const float*)d_in[17];
    const float* bc3  = (const float*)d_in[18];
    float* out = (float*)d_out;

    float *p_tmp, *p_h0, *p_h1, *p_fs, *p_fd;
    cudaGetSymbolAddress((void**)&p_tmp, g_tmp);
    cudaGetSymbolAddress((void**)&p_h0, g_h0);
    cudaGetSymbolAddress((void**)&p_h1, g_h1);
    cudaGetSymbolAddress((void**)&p_fs, g_fs);
    cudaGetSymbolAddress((void**)&p_fd, g_fd);

    const int TPB = 256;
    int gemm_blocks = (Nn + 63) / 64;             // 782
    int warp_blocks = (Nn * 32 + TPB - 1) / TPB;  // 6250
    int edge_blocks = (Ee + TPB - 1) / TPB;       // 3125
    int logit_blocks = (Ee * Hh + TPB - 1) / TPB; // 25000

    // ncu captures launch index 3 -> keep first GEMM there
    k_init<<<(Nn + TPB - 1) / TPB, TPB>>>();                          // 0
    k_degree<<<edge_blocks, TPB>>>(src, dst);                         // 1
    k_dinv<<<(Nn + TPB - 1) / TPB, TPB>>>();                          // 2
    k_gemm<<<gemm_blocks, 128>>>(x, W1, nullptr, 1, p_tmp, INF);      // 3  <- profiled
    k_scan1<<<NB_SCAN, 512>>>();                                      // 4
    k_scan2<<<1, 128>>>();                                            // 5
    k_scan3<<<NB_SCAN, 512>>>();                                      // 6
    k_fill<<<edge_blocks, TPB>>>(src, dst);                           // 7
    k_agg<<<warp_blocks, TPB>>>(p_tmp, b1, p_h0);                     // 8

    k_gemm<<<gemm_blocks, 128>>>(p_h0, W2, nullptr, 1, p_tmp, HIDf);
    k_agg<<<warp_blocks, TPB>>>(p_tmp, b2, p_h1);

    float* hin = p_h1;
    float* hout = p_h0;
    for (int i = 0; i < 3; i++) {
        k_gemm<<<gemm_blocks, 128>>>(hin, Ws + i * HIDf * HIDf, bs + i * HIDf, 0, p_fs, HIDf);
        k_gemm<<<gemm_blocks, 128>>>(hin, Wd + i * HIDf * HIDf, bd + i * HIDf, 0, p_fd, HIDf);
        k_logits<<<logit_blocks, TPB>>>(attn + i * Hh * Dd);
        k_gatnode<<<warp_blocks, TPB>>>(hout);
        float* t = hin; hin = hout; hout = t;
    }

    k_readout<<<64, 384>>>(hin, gid);
    k_mlp<<<1, 512>>>(Wc1, bc1, Wc2, bc2, Wc3, bc3, out);
}

// round 9
// speedup vs baseline: 1.3691x; 1.0437x over previous
#include <cuda_runtime.h>
#include <cuda_bf16.h>
#include <cstdint>
#include <stdint.h>
#include <math.h>

#define Nn 50000
#define Ee 800000
#define INF 128
#define HIDf 96
#define Hh 8
#define Dd 12
#define Gg 64
#define OUTf 10
#define NB_SCAN ((Nn + 511) / 512)   // 98
#define ASTRIDE 40    // 32 + 8 pad (bf16)
#define BSTRIDE 104   // 96 + 8 pad (bf16)

// ---------------- scratch (device globals; no allocation allowed) ------------
__device__ __align__(16) float g_tmp[Nn * HIDf];
__device__ __align__(16) float g_h0[Nn * HIDf];
__device__ __align__(16) float g_h1[Nn * HIDf];
__device__ __align__(16) float g_fs[Nn * HIDf];
__device__ __align__(16) float g_fd[Nn * HIDf];
__device__ __align__(16) float g_logits[Ee * Hh];
__device__ int   g_degout[Nn];
__device__ int   g_degin[Nn];
__device__ int   g_fill[Nn];
__device__ int   g_rowptr[Nn + 1];
__device__ int   g_esrc[Ee];
__device__ int   g_edst[Ee];
__device__ int   g_part[128];
__device__ int   g_hg[Gg * HIDf];
__device__ float g_dinvout[Nn];
__device__ float g_dinvin[Nn];
// pre-converted bf16 hi/lo weights: [W1 | W2 | Ws0..2 | Wd0..2]
#define W1_OFF 0
#define W2_OFF (INF * HIDf)                    // 12288
#define WS_OFF (W2_OFF + HIDf * HIDf)          // 21504
#define WD_OFF (WS_OFF + 3 * HIDf * HIDf)      // 49152
#define WTOT   (WD_OFF + 3 * HIDf * HIDf)      // 76800
__device__ __align__(16) __nv_bfloat16 g_wh[WTOT];
__device__ __align__(16) __nv_bfloat16 g_wl[WTOT];

// ---------------- mma helpers ----------------
__device__ __forceinline__ uint32_t sptr(const void* p) {
    return (uint32_t)__cvta_generic_to_shared(p);
}
__device__ __forceinline__ void ldsm_x4(uint32_t addr, uint32_t& r0, uint32_t& r1,
                                        uint32_t& r2, uint32_t& r3) {
    asm volatile("ldmatrix.sync.aligned.m8n8.x4.shared.b16 {%0,%1,%2,%3}, [%4];"
                 : "=r"(r0), "=r"(r1), "=r"(r2), "=r"(r3) : "r"(addr));
}
__device__ __forceinline__ void ldsm_x4t(uint32_t addr, uint32_t& r0, uint32_t& r1,
                                         uint32_t& r2, uint32_t& r3) {
    asm volatile("ldmatrix.sync.aligned.m8n8.x4.trans.shared.b16 {%0,%1,%2,%3}, [%4];"
                 : "=r"(r0), "=r"(r1), "=r"(r2), "=r"(r3) : "r"(addr));
}
__device__ __forceinline__ void mma_bf16(float* c, const uint32_t* a, const uint32_t* b) {
    asm volatile("mma.sync.aligned.m16n8k16.row.col.f32.bf16.bf16.f32 "
                 "{%0,%1,%2,%3}, {%4,%5,%6,%7}, {%8,%9}, {%0,%1,%2,%3};"
                 : "+f"(c[0]), "+f"(c[1]), "+f"(c[2]), "+f"(c[3])
                 : "r"(a[0]), "r"(a[1]), "r"(a[2]), "r"(a[3]), "r"(b[0]), "r"(b[1]));
}

// ---------------- init ----------------
__global__ void k_init() {
    int i = blockIdx.x * blockDim.x + threadIdx.x;
    if (i < Nn) { g_degout[i] = 0; g_degin[i] = 0; g_fill[i] = 0; }
    if (i < Gg * HIDf) g_hg[i] = 0;   // bits of +0.0f; readout inputs are >= 0
}

// ---------------- degrees / histogram ----------------
__global__ void k_degree(const int* __restrict__ src, const int* __restrict__ dst) {
    int e = blockIdx.x * blockDim.x + threadIdx.x;
    if (e < Ee) {
        atomicAdd(&g_degout[src[e]], 1);
        atomicAdd(&g_degin[dst[e]], 1);
    }
}

// ---------------- deg^-0.5 + weight bf16 hi/lo conversion (fused) ----------------
__global__ void k_prep(const float* __restrict__ W1, const float* __restrict__ W2,
                       const float* __restrict__ Ws, const float* __restrict__ Wd) {
    int i = blockIdx.x * blockDim.x + threadIdx.x;
    if (i < Nn) {
        g_dinvout[i] = rsqrtf((float)max(g_degout[i], 1));
        g_dinvin[i]  = rsqrtf((float)max(g_degin[i], 1));
    }
    if (i < WTOT) {
        float v;
        if (i < W2_OFF)      v = W1[i];
        else if (i < WS_OFF) v = W2[i - W2_OFF];
        else if (i < WD_OFF) v = Ws[i - WS_OFF];
        else                 v = Wd[i - WD_OFF];
        __nv_bfloat16 h = __float2bfloat16(v);
        g_wh[i] = h;
        g_wl[i] = __float2bfloat16(v - __bfloat162float(h));
    }
}

// ---------------- exclusive scan of g_degin -> g_rowptr ----------------
__global__ void k_scan1() {
    __shared__ int s[512];
    int t = threadIdx.x;
    int idx = blockIdx.x * 512 + t;
    int v = (idx < Nn) ? g_degin[idx] : 0;
    s[t] = v;
    __syncthreads();
    for (int off = 1; off < 512; off <<= 1) {
        int x = (t >= off) ? s[t - off] : 0;
        __syncthreads();
        s[t] += x;
        __syncthreads();
    }
    if (idx < Nn) g_rowptr[idx] = s[t] - v;
    if (t == 511) g_part[blockIdx.x] = s[511];
}

__global__ void k_scan2() {
    __shared__ int s[128];
    int t = threadIdx.x;
    int v = (t < NB_SCAN) ? g_part[t] : 0;
    s[t] = v;
    __syncthreads();
    for (int off = 1; off < 128; off <<= 1) {
        int x = (t >= off) ? s[t - off] : 0;
        __syncthreads();
        s[t] += x;
        __syncthreads();
    }
    if (t < NB_SCAN) g_part[t] = s[t] - v;
}

__global__ void k_scan3() {
    int idx = blockIdx.x * blockDim.x + threadIdx.x;
    if (idx < Nn) g_rowptr[idx] += g_part[idx >> 9];
    if (idx == 0) g_rowptr[Nn] = Ee;
}

// ---------------- CSR fill (edges grouped by dst) ----------------
__global__ void k_fill(const int* __restrict__ src, const int* __restrict__ dst) {
    int e = blockIdx.x * blockDim.x + threadIdx.x;
    if (e < Ee) {
        int d = dst[e];
        int pos = g_rowptr[d] + atomicAdd(&g_fill[d], 1);
        g_esrc[pos] = src[e];
        g_edst[pos] = d;
    }
}

// ---------------- tensor-core GEMM (bf16-split, 3-term, pre-converted W) ----------
// out = (in [*dinvout]) @ W [+ bias].  64x96 tile, 256 threads (8 warps),
// warp (wm 0..3, wn 0..1) -> rows wm*16..+15, cols wn*48..+47 (16x48 per warp).
__global__ void __launch_bounds__(256, 3)
k_gemm(const float* __restrict__ in,
       const __nv_bfloat16* __restrict__ Wh, const __nv_bfloat16* __restrict__ Wl,
       const float* __restrict__ bias, int use_rowscale,
       float* __restrict__ out, int kin) {
    __shared__ __nv_bfloat16 sAh[64][ASTRIDE];
    __shared__ __nv_bfloat16 sAl[64][ASTRIDE];
    __shared__ __nv_bfloat16 sBh[32][BSTRIDE];
    __shared__ __nv_bfloat16 sBl[32][BSTRIDE];
    int tid = threadIdx.x;
    int lane = tid & 31, wid = tid >> 5;
    int wm = wid & 3, wn = wid >> 2;
    int rowBase = blockIdx.x * 64;

    float acc[6][4];
#pragma unroll
    for (int j = 0; j < 6; j++)
#pragma unroll
        for (int q = 0; q < 4; q++) acc[j][q] = 0.f;

    for (int kc = 0; kc < kin; kc += 32) {
        // stage A (fp32 -> hi/lo bf16 pairs), 64 rows x 16 pairs
        for (int i = tid; i < 64 * 16; i += 256) {
            int r = i >> 4, k2 = (i & 15) * 2;
            int row = rowBase + r;
            float2 v = make_float2(0.f, 0.f);
            if (row < Nn) {
                v = *(const float2*)&in[row * kin + kc + k2];
                if (use_rowscale) {
                    float sc = g_dinvout[row];
                    v.x *= sc; v.y *= sc;
                }
            }
            __nv_bfloat162 h = __floats2bfloat162_rn(v.x, v.y);
            *(__nv_bfloat162*)&sAh[r][k2] = h;
            __nv_bfloat162 l = __floats2bfloat162_rn(v.x - __bfloat162float(h.x),
                                                     v.y - __bfloat162float(h.y));
            *(__nv_bfloat162*)&sAl[r][k2] = l;
        }
        // stage W chunk (already bf16): 32 rows x 48 uint32 pairs
        for (int i = tid; i < 32 * 48; i += 256) {
            int r = i / 48, c2 = (i % 48) * 2;
            *(uint32_t*)&sBh[r][c2] = *(const uint32_t*)&Wh[(kc + r) * HIDf + c2];
            *(uint32_t*)&sBl[r][c2] = *(const uint32_t*)&Wl[(kc + r) * HIDf + c2];
        }
        __syncthreads();
#pragma unroll
        for (int ks = 0; ks < 32; ks += 16) {
            uint32_t ah[4], al[4];
            {
                int arow = wm * 16 + (lane & 15);
                int acol = ks + (lane >> 4) * 8;
                ldsm_x4(sptr(&sAh[arow][acol]), ah[0], ah[1], ah[2], ah[3]);
                ldsm_x4(sptr(&sAl[arow][acol]), al[0], al[1], al[2], al[3]);
            }
            uint32_t bh[6][2], bl[6][2];
#pragma unroll
            for (int j2 = 0; j2 < 3; j2++) {
                int brow = ks + (lane & 15);
                int bcol = wn * 48 + j2 * 16 + (lane >> 4) * 8;
                ldsm_x4t(sptr(&sBh[brow][bcol]),
                         bh[2 * j2][0], bh[2 * j2][1], bh[2 * j2 + 1][0], bh[2 * j2 + 1][1]);
                ldsm_x4t(sptr(&sBl[brow][bcol]),
                         bl[2 * j2][0], bl[2 * j2][1], bl[2 * j2 + 1][0], bl[2 * j2 + 1][1]);
            }
#pragma unroll
            for (int j = 0; j < 6; j++) {
                mma_bf16(acc[j], ah, bh[j]);
                mma_bf16(acc[j], ah, bl[j]);
                mma_bf16(acc[j], al, bh[j]);
            }
        }
        __syncthreads();
    }
    // epilogue
#pragma unroll
    for (int j = 0; j < 6; j++) {
        int r0 = rowBase + wm * 16 + (lane >> 2);
        int c = wn * 48 + j * 8 + (lane & 3) * 2;
        float b0 = 0.f, b1 = 0.f;
        if (bias) { b0 = bias[c]; b1 = bias[c + 1]; }
        if (r0 < Nn) {
            float2 o = make_float2(acc[j][0] + b0, acc[j][1] + b1);
            *(float2*)&out[r0 * HIDf + c] = o;
        }
        int r1 = r0 + 8;
        if (r1 < Nn) {
            float2 o = make_float2(acc[j][2] + b0, acc[j][3] + b1);
            *(float2*)&out[r1 * HIDf + c] = o;
        }
    }
}

// ---------------- GraphConv aggregation: out = relu(sum_in(pre[src]) * dinvin + b)
__global__ void k_agg(const float* __restrict__ pre, const float* __restrict__ bias,
                      float* __restrict__ out) {
    int warp = (blockIdx.x * blockDim.x + threadIdx.x) >> 5;
    int lane = threadIdx.x & 31;
    if (warp >= Nn) return;
    int beg = g_rowptr[warp], end = g_rowptr[warp + 1];
    float a0 = 0.f, a1 = 0.f, a2 = 0.f;
    for (int p = beg; p < end; p++) {
        const float* r = pre + g_esrc[p] * HIDf;
        a0 += r[lane];
        a1 += r[lane + 32];
        a2 += r[lane + 64];
    }
    float sc = g_dinvin[warp];
    out[warp * HIDf + lane]      = fmaxf(a0 * sc + bias[lane], 0.f);
    out[warp * HIDf + lane + 32] = fmaxf(a1 * sc + bias[lane + 32], 0.f);
    out[warp * HIDf + lane + 64] = fmaxf(a2 * sc + bias[lane + 64], 0.f);
}

// ---------------- GATv2 edge logits (dst-sorted order) ----------------
__global__ void k_logits(const float* __restrict__ attn) {
    int idx = blockIdx.x * blockDim.x + threadIdx.x;
    if (idx >= Ee * Hh) return;
    int p = idx >> 3, h = idx & 7;
    int s = g_esrc[p], d = g_edst[p];
    const float4* fsp = (const float4*)(g_fs + s * HIDf + h * Dd);
    const float4* fdp = (const float4*)(g_fd + d * HIDf + h * Dd);
    float lg = 0.f;
#pragma unroll
    for (int j = 0; j < 3; j++) {
        float4 a = fsp[j];
        float4 b = fdp[j];
        float v;
        v = a.x + b.x; v = (v > 0.f) ? v : 0.2f * v; lg += v * __ldg(attn + h * Dd + j * 4 + 0);
        v = a.y + b.y; v = (v > 0.f) ? v : 0.2f * v; lg += v * __ldg(attn + h * Dd + j * 4 + 1);
        v = a.z + b.z; v = (v > 0.f) ? v : 0.2f * v; lg += v * __ldg(attn + h * Dd + j * 4 + 2);
        v = a.w + b.w; v = (v > 0.f) ? v : 0.2f * v; lg += v * __ldg(attn + h * Dd + j * 4 + 3);
    }
    g_logits[idx] = lg;   // idx == p*8 + h
}

// ---------------- GATv2 per-node softmax + weighted sum + relu ----------------
__global__ void k_gatnode(float* __restrict__ out) {
    int warp = (blockIdx.x * blockDim.x + threadIdx.x) >> 5;
    int lane = threadIdx.x & 31;
    if (warp >= Nn) return;
    int beg = g_rowptr[warp], end = g_rowptr[warp + 1];
    int h = lane & 7, sub = lane >> 3;

    float mh = -3.402823466e38f;
    for (int p = beg + sub; p < end; p += 4) mh = fmaxf(mh, g_logits[p * 8 + h]);
    mh = fmaxf(mh, __shfl_xor_sync(0xffffffffu, mh, 8));
    mh = fmaxf(mh, __shfl_xor_sync(0xffffffffu, mh, 16));

    float den = 0.f;
    for (int p = beg + sub; p < end; p += 4) den += __expf(g_logits[p * 8 + h] - mh);
    den += __shfl_xor_sync(0xffffffffu, den, 8);
    den += __shfl_xor_sync(0xffffffffu, den, 16);

    int f0 = lane, f1 = lane + 32, f2 = lane + 64;
    int h0 = f0 / Dd, h1 = f1 / Dd, h2 = f2 / Dd;
    float m0 = __shfl_sync(0xffffffffu, mh, h0);
    float m1 = __shfl_sync(0xffffffffu, mh, h1);
    float m2 = __shfl_sync(0xffffffffu, mh, h2);
    float d0 = __shfl_sync(0xffffffffu, den, h0);
    float d1 = __shfl_sync(0xffffffffu, den, h1);
    float d2 = __shfl_sync(0xffffffffu, den, h2);
    float r0 = (d0 > 0.f) ? 1.f / d0 : 0.f;
    float r1 = (d1 > 0.f) ? 1.f / d1 : 0.f;
    float r2 = (d2 > 0.f) ? 1.f / d2 : 0.f;

    float acc0 = 0.f, acc1 = 0.f, acc2 = 0.f;
    for (int p = beg; p < end; p++) {
        const float* lg = g_logits + p * 8;
        float a0 = __expf(lg[h0] - m0) * r0;
        float a1 = __expf(lg[h1] - m1) * r1;
        float a2 = __expf(lg[h2] - m2) * r2;
        const float* fr = g_fs + g_esrc[p] * HIDf;
        acc0 += a0 * fr[f0];
        acc1 += a1 * fr[f1];
        acc2 += a2 * fr[f2];
    }
    out[warp * HIDf + f0] = fmaxf(acc0, 0.f);
    out[warp * HIDf + f1] = fmaxf(acc1, 0.f);
    out[warp * HIDf + f2] = fmaxf(acc2, 0.f);
}

// ---------------- per-graph max readout (values >= 0 after relu) ----------------
__global__ void k_readout(const float* __restrict__ hfin, const int* __restrict__ gid) {
    __shared__ int s[Gg * HIDf];
    int tid = threadIdx.x;  // 384
    for (int i = tid; i < Gg * HIDf; i += 384) s[i] = 0;
    __syncthreads();
    int f = tid % 96, rr = tid / 96;
    for (int node = blockIdx.x * 4 + rr; node < Nn; node += 64 * 4) {
        int g = gid[node];
        float v = hfin[node * HIDf + f];
        atomicMax(&s[g * HIDf + f], __float_as_int(v));
    }
    __syncthreads();
    for (int i = tid; i < Gg * HIDf; i += 384) atomicMax(&g_hg[i], s[i]);
}

// ---------------- classifier MLP on [64,96] ----------------
__global__ void k_mlp(const float* __restrict__ Wc1, const float* __restrict__ bc1,
                      const float* __restrict__ Wc2, const float* __restrict__ bc2,
                      const float* __restrict__ Wc3, const float* __restrict__ bc3,
                      float* __restrict__ out) {
    __shared__ float A[Gg * HIDf];
    __shared__ float B[Gg * HIDf];
    int tid = threadIdx.x;  // 512
    for (int i = tid; i < Gg * HIDf; i += 512) A[i] = __int_as_float(g_hg[i]);
    __syncthreads();
    for (int i = tid; i < Gg * HIDf; i += 512) {
        int r = i / 96, c = i % 96;
        float acc = bc1[c];
        for (int k = 0; k < 96; k++) acc += A[r * 96 + k] * Wc1[k * 96 + c];
        B[i] = fmaxf(acc, 0.f);
    }
    __syncthreads();
    for (int i = tid; i < Gg * 48; i += 512) {
        int r = i / 48, c = i % 48;
        float acc = bc2[c];
        for (int k = 0; k < 96; k++) acc += B[r * 96 + k] * Wc2[k * 48 + c];
        A[i] = fmaxf(acc, 0.f);
    }
    __syncthreads();
    for (int i = tid; i < Gg * OUTf; i += 512) {
        int r = i / 10, c = i % 10;
        float acc = bc3[c];
        for (int k = 0; k < 48; k++) acc += A[r * 48 + k] * Wc3[k * 10 + c];
        out[i] = acc;
    }
}

// ---------------- host launcher ----------------
extern "C" void kernel_launch(void* const* d_in, const int* in_sizes, int n_in,
                              void* d_out, int out_size) {
    (void)in_sizes; (void)n_in; (void)out_size;
    const float* x    = (const float*)d_in[0];
    const int*   src  = (const int*)d_in[1];
    const int*   dst  = (const int*)d_in[2];
    const int*   gid  = (const int*)d_in[3];
    const float* W1   = (const float*)d_in[4];
    const float* b1   = (const float*)d_in[5];
    const float* W2   = (const float*)d_in[6];
    const float* b2   = (const float*)d_in[7];
    const float* Ws   = (const float*)d_in[8];
    const float* bs   = (const float*)d_in[9];
    const float* Wd   = (const float*)d_in[10];
    const float* bd   = (const float*)d_in[11];
    const float* attn = (const float*)d_in[12];
    const float* Wc1  = (const float*)d_in[13];
    const float* bc1  = (const float*)d_in[14];
    const float* Wc2  = (const float*)d_in[15];
    const float* bc2  = (const float*)d_in[16];
    const float* Wc3  = (const float*)d_in[17];
    const float* bc3  = (const float*)d_in[18];
    float* out = (float*)d_out;

    float *p_tmp, *p_h0, *p_h1, *p_fs, *p_fd;
    cudaGetSymbolAddress((void**)&p_tmp, g_tmp);
    cudaGetSymbolAddress((void**)&p_h0, g_h0);
    cudaGetSymbolAddress((void**)&p_h1, g_h1);
    cudaGetSymbolAddress((void**)&p_fs, g_fs);
    cudaGetSymbolAddress((void**)&p_fd, g_fd);
    __nv_bfloat16 *p_wh, *p_wl;
    cudaGetSymbolAddress((void**)&p_wh, g_wh);
    cudaGetSymbolAddress((void**)&p_wl, g_wl);

    const int TPB = 256;
    int gemm_blocks = (Nn + 63) / 64;             // 782
    int warp_blocks = (Nn * 32 + TPB - 1) / TPB;  // 6250
    int edge_blocks = (Ee + TPB - 1) / TPB;       // 3125
    int logit_blocks = (Ee * Hh + TPB - 1) / TPB; // 25000
    int prep_blocks = (WTOT + TPB - 1) / TPB;     // 300 (covers Nn/256=196 too)

    // ncu captures launch index 3 -> keep first GEMM there
    k_init<<<(Nn + TPB - 1) / TPB, TPB>>>();                          // 0
    k_degree<<<edge_blocks, TPB>>>(src, dst);                         // 1
    k_prep<<<prep_blocks, TPB>>>(W1, W2, Ws, Wd);                     // 2
    k_gemm<<<gemm_blocks, 256>>>(x, p_wh + W1_OFF, p_wl + W1_OFF,
                                 nullptr, 1, p_tmp, INF);             // 3  <- profiled
    k_scan1<<<NB_SCAN, 512>>>();                                      // 4
    k_scan2<<<1, 128>>>();                                            // 5
    k_scan3<<<NB_SCAN, 512>>>();                                      // 6
    k_fill<<<edge_blocks, TPB>>>(src, dst);                           // 7
    k_agg<<<warp_blocks, TPB>>>(p_tmp, b1, p_h0);                     // 8

    k_gemm<<<gemm_blocks, 256>>>(p_h0, p_wh + W2_OFF, p_wl + W2_OFF,
                                 nullptr, 1, p_tmp, HIDf);
    k_agg<<<warp_blocks, TPB>>>(p_tmp, b2, p_h1);

    float* hin = p_h1;
    float* hout = p_h0;
    for (int i = 0; i < 3; i++) {
        k_gemm<<<gemm_blocks, 256>>>(hin, p_wh + WS_OFF + i * HIDf * HIDf,
                                     p_wl + WS_OFF + i * HIDf * HIDf,
                                     bs + i * HIDf, 0, p_fs, HIDf);
        k_gemm<<<gemm_blocks, 256>>>(hin, p_wh + WD_OFF + i * HIDf * HIDf,
                                     p_wl + WD_OFF + i * HIDf * HIDf,
                                     bd + i * HIDf, 0, p_fd, HIDf);
        k_logits<<<logit_blocks, TPB>>>(attn + i * Hh * Dd);
        k_gatnode<<<warp_blocks, TPB>>>(hout);
        float* t = hin; hin = hout; hout = t;
    }

    k_readout<<<64, 384>>>(hin, gid);
    k_mlp<<<1, 512>>>(Wc1, bc1, Wc2, bc2, Wc3, bc3, out);
}

// round 10
// speedup vs baseline: 1.4395x; 1.0514x over previous
#include <cuda_runtime.h>
#include <cuda_bf16.h>
#include <cstdint>
#include <stdint.h>
#include <math.h>

#define Nn 50000
#define Ee 800000
#define INF 128
#define HIDf 96
#define Hh 8
#define Dd 12
#define Gg 64
#define OUTf 10
#define NB_SCAN ((Nn + 511) / 512)   // 98
#define ASTRIDE 40    // 32 + 8 pad (bf16)
#define BSTRIDE 104   // 96 + 8 pad (bf16)

// ---------------- scratch (device globals; no allocation allowed) ------------
__device__ __align__(16) float g_tmp[Nn * HIDf];
__device__ __align__(16) float g_h0[Nn * HIDf];
__device__ __align__(16) float g_h1[Nn * HIDf];
__device__ __align__(16) float g_fs[Nn * HIDf];
__device__ __align__(16) float g_fd[Nn * HIDf];
__device__ __align__(16) float g_logits[Ee * Hh];
__device__ int   g_degout[Nn];
__device__ int   g_degin[Nn];
__device__ int   g_fill[Nn];
__device__ int   g_rowptr[Nn + 1];
__device__ int   g_esrc[Ee];
__device__ int   g_edst[Ee];
__device__ int   g_part[128];
__device__ int   g_hg[Gg * HIDf];
__device__ float g_dinvout[Nn];
__device__ float g_dinvin[Nn];
// pre-converted bf16 hi/lo weights: [W1 | W2 | Ws0..2 | Wd0..2]
#define W1_OFF 0
#define W2_OFF (INF * HIDf)                    // 12288
#define WS_OFF (W2_OFF + HIDf * HIDf)          // 21504
#define WD_OFF (WS_OFF + 3 * HIDf * HIDf)      // 49152
#define WTOT   (WD_OFF + 3 * HIDf * HIDf)      // 76800
__device__ __align__(16) __nv_bfloat16 g_wh[WTOT];
__device__ __align__(16) __nv_bfloat16 g_wl[WTOT];

// ---------------- mma helpers ----------------
__device__ __forceinline__ uint32_t sptr(const void* p) {
    return (uint32_t)__cvta_generic_to_shared(p);
}
__device__ __forceinline__ void ldsm_x4(uint32_t addr, uint32_t& r0, uint32_t& r1,
                                        uint32_t& r2, uint32_t& r3) {
    asm volatile("ldmatrix.sync.aligned.m8n8.x4.shared.b16 {%0,%1,%2,%3}, [%4];"
                 : "=r"(r0), "=r"(r1), "=r"(r2), "=r"(r3) : "r"(addr));
}
__device__ __forceinline__ void ldsm_x4t(uint32_t addr, uint32_t& r0, uint32_t& r1,
                                         uint32_t& r2, uint32_t& r3) {
    asm volatile("ldmatrix.sync.aligned.m8n8.x4.trans.shared.b16 {%0,%1,%2,%3}, [%4];"
                 : "=r"(r0), "=r"(r1), "=r"(r2), "=r"(r3) : "r"(addr));
}
__device__ __forceinline__ void mma_bf16(float* c, const uint32_t* a, const uint32_t* b) {
    asm volatile("mma.sync.aligned.m16n8k16.row.col.f32.bf16.bf16.f32 "
                 "{%0,%1,%2,%3}, {%4,%5,%6,%7}, {%8,%9}, {%0,%1,%2,%3};"
                 : "+f"(c[0]), "+f"(c[1]), "+f"(c[2]), "+f"(c[3])
                 : "r"(a[0]), "r"(a[1]), "r"(a[2]), "r"(a[3]), "r"(b[0]), "r"(b[1]));
}

// ---------------- init ----------------
__global__ void k_init() {
    int i = blockIdx.x * blockDim.x + threadIdx.x;
    if (i < Nn) { g_degout[i] = 0; g_degin[i] = 0; g_fill[i] = 0; }
    if (i < Gg * HIDf) g_hg[i] = 0;   // bits of +0.0f; readout inputs are >= 0
}

// ---------------- degrees / histogram ----------------
__global__ void k_degree(const int* __restrict__ src, const int* __restrict__ dst) {
    int e = blockIdx.x * blockDim.x + threadIdx.x;
    if (e < Ee) {
        atomicAdd(&g_degout[src[e]], 1);
        atomicAdd(&g_degin[dst[e]], 1);
    }
}

// ---------------- deg^-0.5 + weight bf16 hi/lo conversion (fused) ----------------
__global__ void k_prep(const float* __restrict__ W1, const float* __restrict__ W2,
                       const float* __restrict__ Ws, const float* __restrict__ Wd) {
    int i = blockIdx.x * blockDim.x + threadIdx.x;
    if (i < Nn) {
        g_dinvout[i] = rsqrtf((float)max(g_degout[i], 1));
        g_dinvin[i]  = rsqrtf((float)max(g_degin[i], 1));
    }
    if (i < WTOT) {
        float v;
        if (i < W2_OFF)      v = W1[i];
        else if (i < WS_OFF) v = W2[i - W2_OFF];
        else if (i < WD_OFF) v = Ws[i - WS_OFF];
        else                 v = Wd[i - WD_OFF];
        __nv_bfloat16 h = __float2bfloat16(v);
        g_wh[i] = h;
        g_wl[i] = __float2bfloat16(v - __bfloat162float(h));
    }
}

// ---------------- exclusive scan of g_degin -> g_rowptr ----------------
__global__ void k_scan1() {
    __shared__ int s[512];
    int t = threadIdx.x;
    int idx = blockIdx.x * 512 + t;
    int v = (idx < Nn) ? g_degin[idx] : 0;
    s[t] = v;
    __syncthreads();
    for (int off = 1; off < 512; off <<= 1) {
        int x = (t >= off) ? s[t - off] : 0;
        __syncthreads();
        s[t] += x;
        __syncthreads();
    }
    if (idx < Nn) g_rowptr[idx] = s[t] - v;
    if (t == 511) g_part[blockIdx.x] = s[511];
}

__global__ void k_scan2() {
    __shared__ int s[128];
    int t = threadIdx.x;
    int v = (t < NB_SCAN) ? g_part[t] : 0;
    s[t] = v;
    __syncthreads();
    for (int off = 1; off < 128; off <<= 1) {
        int x = (t >= off) ? s[t - off] : 0;
        __syncthreads();
        s[t] += x;
        __syncthreads();
    }
    if (t < NB_SCAN) g_part[t] = s[t] - v;
}

__global__ void k_scan3() {
    int idx = blockIdx.x * blockDim.x + threadIdx.x;
    if (idx < Nn) g_rowptr[idx] += g_part[idx >> 9];
    if (idx == 0) g_rowptr[Nn] = Ee;
}

// ---------------- CSR fill (edges grouped by dst) ----------------
__global__ void k_fill(const int* __restrict__ src, const int* __restrict__ dst) {
    int e = blockIdx.x * blockDim.x + threadIdx.x;
    if (e < Ee) {
        int d = dst[e];
        int pos = g_rowptr[d] + atomicAdd(&g_fill[d], 1);
        g_esrc[pos] = src[e];
        g_edst[pos] = d;
    }
}

// ---------------- tensor-core GEMM (bf16-split, 3-term, pre-converted W) ----------
// out = (in [*dinvout]) @ W [+ bias].  64x96 tile, 256 threads (8 warps),
// warp (wm 0..3, wn 0..1) -> rows wm*16..+15, cols wn*48..+47 (16x48 per warp).
__global__ void __launch_bounds__(256, 3)
k_gemm(const float* __restrict__ in,
       const __nv_bfloat16* __restrict__ Wh, const __nv_bfloat16* __restrict__ Wl,
       const float* __restrict__ bias, int use_rowscale,
       float* __restrict__ out, int kin) {
    __shared__ __nv_bfloat16 sAh[64][ASTRIDE];
    __shared__ __nv_bfloat16 sAl[64][ASTRIDE];
    __shared__ __nv_bfloat16 sBh[32][BSTRIDE];
    __shared__ __nv_bfloat16 sBl[32][BSTRIDE];
    int tid = threadIdx.x;
    int lane = tid & 31, wid = tid >> 5;
    int wm = wid & 3, wn = wid >> 2;
    int rowBase = blockIdx.x * 64;

    float acc[6][4];
#pragma unroll
    for (int j = 0; j < 6; j++)
#pragma unroll
        for (int q = 0; q < 4; q++) acc[j][q] = 0.f;

    for (int kc = 0; kc < kin; kc += 32) {
        // stage A (fp32 -> hi/lo bf16 pairs), 64 rows x 16 pairs
        for (int i = tid; i < 64 * 16; i += 256) {
            int r = i >> 4, k2 = (i & 15) * 2;
            int row = rowBase + r;
            float2 v = make_float2(0.f, 0.f);
            if (row < Nn) {
                v = *(const float2*)&in[row * kin + kc + k2];
                if (use_rowscale) {
                    float sc = g_dinvout[row];
                    v.x *= sc; v.y *= sc;
                }
            }
            __nv_bfloat162 h = __floats2bfloat162_rn(v.x, v.y);
            *(__nv_bfloat162*)&sAh[r][k2] = h;
            __nv_bfloat162 l = __floats2bfloat162_rn(v.x - __bfloat162float(h.x),
                                                     v.y - __bfloat162float(h.y));
            *(__nv_bfloat162*)&sAl[r][k2] = l;
        }
        // stage W chunk (already bf16): 32 rows x 48 uint32 pairs
        for (int i = tid; i < 32 * 48; i += 256) {
            int r = i / 48, c2 = (i % 48) * 2;
            *(uint32_t*)&sBh[r][c2] = *(const uint32_t*)&Wh[(kc + r) * HIDf + c2];
            *(uint32_t*)&sBl[r][c2] = *(const uint32_t*)&Wl[(kc + r) * HIDf + c2];
        }
        __syncthreads();
#pragma unroll
        for (int ks = 0; ks < 32; ks += 16) {
            uint32_t ah[4], al[4];
            {
                int arow = wm * 16 + (lane & 15);
                int acol = ks + (lane >> 4) * 8;
                ldsm_x4(sptr(&sAh[arow][acol]), ah[0], ah[1], ah[2], ah[3]);
                ldsm_x4(sptr(&sAl[arow][acol]), al[0], al[1], al[2], al[3]);
            }
            uint32_t bh[6][2], bl[6][2];
#pragma unroll
            for (int j2 = 0; j2 < 3; j2++) {
                int brow = ks + (lane & 15);
                int bcol = wn * 48 + j2 * 16 + (lane >> 4) * 8;
                ldsm_x4t(sptr(&sBh[brow][bcol]),
                         bh[2 * j2][0], bh[2 * j2][1], bh[2 * j2 + 1][0], bh[2 * j2 + 1][1]);
                ldsm_x4t(sptr(&sBl[brow][bcol]),
                         bl[2 * j2][0], bl[2 * j2][1], bl[2 * j2 + 1][0], bl[2 * j2 + 1][1]);
            }
#pragma unroll
            for (int j = 0; j < 6; j++) {
                mma_bf16(acc[j], ah, bh[j]);
                mma_bf16(acc[j], ah, bl[j]);
                mma_bf16(acc[j], al, bh[j]);
            }
        }
        __syncthreads();
    }
    // epilogue
#pragma unroll
    for (int j = 0; j < 6; j++) {
        int r0 = rowBase + wm * 16 + (lane >> 2);
        int c = wn * 48 + j * 8 + (lane & 3) * 2;
        float b0 = 0.f, b1 = 0.f;
        if (bias) { b0 = bias[c]; b1 = bias[c + 1]; }
        if (r0 < Nn) {
            float2 o = make_float2(acc[j][0] + b0, acc[j][1] + b1);
            *(float2*)&out[r0 * HIDf + c] = o;
        }
        int r1 = r0 + 8;
        if (r1 < Nn) {
            float2 o = make_float2(acc[j][2] + b0, acc[j][3] + b1);
            *(float2*)&out[r1 * HIDf + c] = o;
        }
    }
}

// ---------------- GraphConv aggregation: out = relu(sum_in(pre[src]) * dinvin + b)
__global__ void k_agg(const float* __restrict__ pre, const float* __restrict__ bias,
                      float* __restrict__ out) {
    int warp = (blockIdx.x * blockDim.x + threadIdx.x) >> 5;
    int lane = threadIdx.x & 31;
    if (warp >= Nn) return;
    int beg = g_rowptr[warp], end = g_rowptr[warp + 1];
    float a0 = 0.f, a1 = 0.f, a2 = 0.f;
    for (int p = beg; p < end; p++) {
        const float* r = pre + g_esrc[p] * HIDf;
        a0 += r[lane];
        a1 += r[lane + 32];
        a2 += r[lane + 64];
    }
    float sc = g_dinvin[warp];
    out[warp * HIDf + lane]      = fmaxf(a0 * sc + bias[lane], 0.f);
    out[warp * HIDf + lane + 32] = fmaxf(a1 * sc + bias[lane + 32], 0.f);
    out[warp * HIDf + lane + 64] = fmaxf(a2 * sc + bias[lane + 64], 0.f);
}

// ---------------- GATv2 edge logits (dst-sorted order) ----------------
__global__ void k_logits(const float* __restrict__ attn) {
    int idx = blockIdx.x * blockDim.x + threadIdx.x;
    if (idx >= Ee * Hh) return;
    int p = idx >> 3, h = idx & 7;
    int s = g_esrc[p], d = g_edst[p];
    const float4* fsp = (const float4*)(g_fs + s * HIDf + h * Dd);
    const float4* fdp = (const float4*)(g_fd + d * HIDf + h * Dd);
    float lg = 0.f;
#pragma unroll
    for (int j = 0; j < 3; j++) {
        float4 a = fsp[j];
        float4 b = fdp[j];
        float v;
        v = a.x + b.x; v = (v > 0.f) ? v : 0.2f * v; lg += v * __ldg(attn + h * Dd + j * 4 + 0);
        v = a.y + b.y; v = (v > 0.f) ? v : 0.2f * v; lg += v * __ldg(attn + h * Dd + j * 4 + 1);
        v = a.z + b.z; v = (v > 0.f) ? v : 0.2f * v; lg += v * __ldg(attn + h * Dd + j * 4 + 2);
        v = a.w + b.w; v = (v > 0.f) ? v : 0.2f * v; lg += v * __ldg(attn + h * Dd + j * 4 + 3);
    }
    g_logits[idx] = lg;   // idx == p*8 + h
}

// ---------------- GATv2 per-node softmax + weighted sum + relu ----------------
// phase 2 stores exp(logit - m) back into g_logits (slab owned exclusively by
// this warp), so the accumulate loop does zero exps: 8 MUFU/edge, not 96.
__global__ void k_gatnode(float* __restrict__ out) {
    int warp = (blockIdx.x * blockDim.x + threadIdx.x) >> 5;
    int lane = threadIdx.x & 31;
    if (warp >= Nn) return;
    int beg = g_rowptr[warp], end = g_rowptr[warp + 1];
    int h = lane & 7, sub = lane >> 3;

    float mh = -3.402823466e38f;
    for (int p = beg + sub; p < end; p += 4) mh = fmaxf(mh, g_logits[p * 8 + h]);
    mh = fmaxf(mh, __shfl_xor_sync(0xffffffffu, mh, 8));
    mh = fmaxf(mh, __shfl_xor_sync(0xffffffffu, mh, 16));

    float den = 0.f;
    for (int p = beg + sub; p < end; p += 4) {
        float w = __expf(g_logits[p * 8 + h] - mh);
        g_logits[p * 8 + h] = w;      // in-place: logits -> unnormalized weights
        den += w;
    }
    den += __shfl_xor_sync(0xffffffffu, den, 8);
    den += __shfl_xor_sync(0xffffffffu, den, 16);
    __syncwarp();                      // order weight stores before reads below

    int f0 = lane, f1 = lane + 32, f2 = lane + 64;
    int h0 = f0 / Dd, h1 = f1 / Dd, h2 = f2 / Dd;
    float d0 = __shfl_sync(0xffffffffu, den, h0);
    float d1 = __shfl_sync(0xffffffffu, den, h1);
    float d2 = __shfl_sync(0xffffffffu, den, h2);
    float r0 = (d0 > 0.f) ? 1.f / d0 : 0.f;
    float r1 = (d1 > 0.f) ? 1.f / d1 : 0.f;
    float r2 = (d2 > 0.f) ? 1.f / d2 : 0.f;

    float acc0 = 0.f, acc1 = 0.f, acc2 = 0.f;
    for (int p = beg; p < end; p++) {
        const float* lg = g_logits + p * 8;
        float w0 = lg[h0];
        float w1 = lg[h1];
        float w2 = lg[h2];
        const float* fr = g_fs + g_esrc[p] * HIDf;
        acc0 += w0 * fr[f0];
        acc1 += w1 * fr[f1];
        acc2 += w2 * fr[f2];
    }
    out[warp * HIDf + f0] = fmaxf(acc0 * r0, 0.f);
    out[warp * HIDf + f1] = fmaxf(acc1 * r1, 0.f);
    out[warp * HIDf + f2] = fmaxf(acc2 * r2, 0.f);
}

// ---------------- per-graph max readout (values >= 0 after relu) ----------------
__global__ void k_readout(const float* __restrict__ hfin, const int* __restrict__ gid) {
    __shared__ int s[Gg * HIDf];
    int tid = threadIdx.x;  // 384
    for (int i = tid; i < Gg * HIDf; i += 384) s[i] = 0;
    __syncthreads();
    int f = tid % 96, rr = tid / 96;
    for (int node = blockIdx.x * 4 + rr; node < Nn; node += 64 * 4) {
        int g = gid[node];
        float v = hfin[node * HIDf + f];
        atomicMax(&s[g * HIDf + f], __float_as_int(v));
    }
    __syncthreads();
    for (int i = tid; i < Gg * HIDf; i += 384) atomicMax(&g_hg[i], s[i]);
}

// ---------------- classifier MLP on [64,96] ----------------
__global__ void k_mlp(const float* __restrict__ Wc1, const float* __restrict__ bc1,
                      const float* __restrict__ Wc2, const float* __restrict__ bc2,
                      const float* __restrict__ Wc3, const float* __restrict__ bc3,
                      float* __restrict__ out) {
    __shared__ float A[Gg * HIDf];
    __shared__ float B[Gg * HIDf];
    int tid = threadIdx.x;  // 512
    for (int i = tid; i < Gg * HIDf; i += 512) A[i] = __int_as_float(g_hg[i]);
    __syncthreads();
    for (int i = tid; i < Gg * HIDf; i += 512) {
        int r = i / 96, c = i % 96;
        float acc = bc1[c];
        for (int k = 0; k < 96; k++) acc += A[r * 96 + k] * Wc1[k * 96 + c];
        B[i] = fmaxf(acc, 0.f);
    }
    __syncthreads();
    for (int i = tid; i < Gg * 48; i += 512) {
        int r = i / 48, c = i % 48;
        float acc = bc2[c];
        for (int k = 0; k < 96; k++) acc += B[r * 96 + k] * Wc2[k * 48 + c];
        A[i] = fmaxf(acc, 0.f);
    }
    __syncthreads();
    for (int i = tid; i < Gg * OUTf; i += 512) {
        int r = i / 10, c = i % 10;
        float acc = bc3[c];
        for (int k = 0; k < 48; k++) acc += A[r * 48 + k] * Wc3[k * 10 + c];
        out[i] = acc;
    }
}

// ---------------- host launcher ----------------
extern "C" void kernel_launch(void* const* d_in, const int* in_sizes, int n_in,
                              void* d_out, int out_size) {
    (void)in_sizes; (void)n_in; (void)out_size;
    const float* x    = (const float*)d_in[0];
    const int*   src  = (const int*)d_in[1];
    const int*   dst  = (const int*)d_in[2];
    const int*   gid  = (const int*)d_in[3];
    const float* W1   = (const float*)d_in[4];
    const float* b1   = (const float*)d_in[5];
    const float* W2   = (const float*)d_in[6];
    const float* b2   = (const float*)d_in[7];
    const float* Ws   = (const float*)d_in[8];
    const float* bs   = (const float*)d_in[9];
    const float* Wd   = (const float*)d_in[10];
    const float* bd   = (const float*)d_in[11];
    const float* attn = (const float*)d_in[12];
    const float* Wc1  = (const float*)d_in[13];
    const float* bc1  = (const float*)d_in[14];
    const float* Wc2  = (const float*)d_in[15];
    const float* bc2  = (const float*)d_in[16];
    const float* Wc3  = (const float*)d_in[17];
    const float* bc3  = (const float*)d_in[18];
    float* out = (float*)d_out;

    float *p_tmp, *p_h0, *p_h1, *p_fs, *p_fd;
    cudaGetSymbolAddress((void**)&p_tmp, g_tmp);
    cudaGetSymbolAddress((void**)&p_h0, g_h0);
    cudaGetSymbolAddress((void**)&p_h1, g_h1);
    cudaGetSymbolAddress((void**)&p_fs, g_fs);
    cudaGetSymbolAddress((void**)&p_fd, g_fd);
    __nv_bfloat16 *p_wh, *p_wl;
    cudaGetSymbolAddress((void**)&p_wh, g_wh);
    cudaGetSymbolAddress((void**)&p_wl, g_wl);

    const int TPB = 256;
    int gemm_blocks = (Nn + 63) / 64;             // 782
    int warp_blocks = (Nn * 32 + TPB - 1) / TPB;  // 6250
    int edge_blocks = (Ee + TPB - 1) / TPB;       // 3125
    int logit_blocks = (Ee * Hh + TPB - 1) / TPB; // 25000
    int prep_blocks = (WTOT + TPB - 1) / TPB;     // 300

    k_init<<<(Nn + TPB - 1) / TPB, TPB>>>();                          // 0
    k_degree<<<edge_blocks, TPB>>>(src, dst);                         // 1
    k_prep<<<prep_blocks, TPB>>>(W1, W2, Ws, Wd);                     // 2
    k_gemm<<<gemm_blocks, 256>>>(x, p_wh + W1_OFF, p_wl + W1_OFF,
                                 nullptr, 1, p_tmp, INF);             // 3  <- profiled
    k_scan1<<<NB_SCAN, 512>>>();                                      // 4
    k_scan2<<<1, 128>>>();                                            // 5
    k_scan3<<<NB_SCAN, 512>>>();                                      // 6
    k_fill<<<edge_blocks, TPB>>>(src, dst);                           // 7
    k_agg<<<warp_blocks, TPB>>>(p_tmp, b1, p_h0);                     // 8

    k_gemm<<<gemm_blocks, 256>>>(p_h0, p_wh + W2_OFF, p_wl + W2_OFF,
                                 nullptr, 1, p_tmp, HIDf);
    k_agg<<<warp_blocks, TPB>>>(p_tmp, b2, p_h1);

    float* hin = p_h1;
    float* hout = p_h0;
    for (int i = 0; i < 3; i++) {
        k_gemm<<<gemm_blocks, 256>>>(hin, p_wh + WS_OFF + i * HIDf * HIDf,
                                     p_wl + WS_OFF + i * HIDf * HIDf,
                                     bs + i * HIDf, 0, p_fs, HIDf);
        k_gemm<<<gemm_blocks, 256>>>(hin, p_wh + WD_OFF + i * HIDf * HIDf,
                                     p_wl + WD_OFF + i * HIDf * HIDf,
                                     bd + i * HIDf, 0, p_fd, HIDf);
        k_logits<<<logit_blocks, TPB>>>(attn + i * Hh * Dd);
        k_gatnode<<<warp_blocks, TPB>>>(hout);
        float* t = hin; hin = hout; hout = t;
    }

    k_readout<<<64, 384>>>(hin, gid);
    k_mlp<<<1, 512>>>(Wc1, bc1, Wc2, bc2, Wc3, bc3, out);
}

// round 11
// speedup vs baseline: 1.5316x; 1.0640x over previous
#include <cuda_runtime.h>
#include <cuda_bf16.h>
#include <cstdint>
#include <stdint.h>
#include <math.h>

#define Nn 50000
#define Ee 800000
#define INF 128
#define HIDf 96
#define Hh 8
#define Dd 12
#define Gg 64
#define OUTf 10
#define NB_SCAN ((Nn + 511) / 512)   // 98
#define ASTRIDE 40    // 32 + 8 pad (bf16)
#define BSTRIDE 104   // 96 + 8 pad (bf16)

// ---------------- scratch (device globals; no allocation allowed) ------------
__device__ __align__(16) float g_tmp[Nn * HIDf];
__device__ __align__(16) float g_h0[Nn * HIDf];
__device__ __align__(16) float g_h1[Nn * HIDf];
__device__ __align__(16) float g_fs[Nn * HIDf];
__device__ __align__(16) float g_fd[Nn * HIDf];
__device__ __align__(16) float g_logits[Ee * Hh];
__device__ int   g_degout[Nn];
__device__ int   g_degin[Nn];
__device__ int   g_fill[Nn];
__device__ int   g_rowptr[Nn + 1];
__device__ int   g_esrc[Ee];
__device__ int   g_edst[Ee];
__device__ int   g_part[128];
__device__ int   g_hg[Gg * HIDf];
__device__ float g_dinvout[Nn];
__device__ float g_dinvin[Nn];
// pre-converted bf16 hi/lo weights: [W1 | W2 | Ws0..2 | Wd0..2]
#define W1_OFF 0
#define W2_OFF (INF * HIDf)                    // 12288
#define WS_OFF (W2_OFF + HIDf * HIDf)          // 21504
#define WD_OFF (WS_OFF + 3 * HIDf * HIDf)      // 49152
#define WTOT   (WD_OFF + 3 * HIDf * HIDf)      // 76800
__device__ __align__(16) __nv_bfloat16 g_wh[WTOT];
__device__ __align__(16) __nv_bfloat16 g_wl[WTOT];

// ---------------- mma helpers ----------------
__device__ __forceinline__ uint32_t sptr(const void* p) {
    return (uint32_t)__cvta_generic_to_shared(p);
}
__device__ __forceinline__ void ldsm_x4(uint32_t addr, uint32_t& r0, uint32_t& r1,
                                        uint32_t& r2, uint32_t& r3) {
    asm volatile("ldmatrix.sync.aligned.m8n8.x4.shared.b16 {%0,%1,%2,%3}, [%4];"
                 : "=r"(r0), "=r"(r1), "=r"(r2), "=r"(r3) : "r"(addr));
}
__device__ __forceinline__ void ldsm_x4t(uint32_t addr, uint32_t& r0, uint32_t& r1,
                                         uint32_t& r2, uint32_t& r3) {
    asm volatile("ldmatrix.sync.aligned.m8n8.x4.trans.shared.b16 {%0,%1,%2,%3}, [%4];"
                 : "=r"(r0), "=r"(r1), "=r"(r2), "=r"(r3) : "r"(addr));
}
__device__ __forceinline__ void mma_bf16(float* c, const uint32_t* a, const uint32_t* b) {
    asm volatile("mma.sync.aligned.m16n8k16.row.col.f32.bf16.bf16.f32 "
                 "{%0,%1,%2,%3}, {%4,%5,%6,%7}, {%8,%9}, {%0,%1,%2,%3};"
                 : "+f"(c[0]), "+f"(c[1]), "+f"(c[2]), "+f"(c[3])
                 : "r"(a[0]), "r"(a[1]), "r"(a[2]), "r"(a[3]), "r"(b[0]), "r"(b[1]));
}

// ---------------- init ----------------
__global__ void k_init() {
    int i = blockIdx.x * blockDim.x + threadIdx.x;
    if (i < Nn) { g_degout[i] = 0; g_degin[i] = 0; g_fill[i] = 0; }
    if (i < Gg * HIDf) g_hg[i] = 0;   // bits of +0.0f; readout inputs are >= 0
}

// ---------------- degrees / histogram ----------------
__global__ void k_degree(const int* __restrict__ src, const int* __restrict__ dst) {
    int e = blockIdx.x * blockDim.x + threadIdx.x;
    if (e < Ee) {
        atomicAdd(&g_degout[src[e]], 1);
        atomicAdd(&g_degin[dst[e]], 1);
    }
}

// ---------------- deg^-0.5 + weight bf16 hi/lo conversion (fused) ----------------
__global__ void k_prep(const float* __restrict__ W1, const float* __restrict__ W2,
                       const float* __restrict__ Ws, const float* __restrict__ Wd) {
    int i = blockIdx.x * blockDim.x + threadIdx.x;
    if (i < Nn) {
        g_dinvout[i] = rsqrtf((float)max(g_degout[i], 1));
        g_dinvin[i]  = rsqrtf((float)max(g_degin[i], 1));
    }
    if (i < WTOT) {
        float v;
        if (i < W2_OFF)      v = W1[i];
        else if (i < WS_OFF) v = W2[i - W2_OFF];
        else if (i < WD_OFF) v = Ws[i - WS_OFF];
        else                 v = Wd[i - WD_OFF];
        __nv_bfloat16 h = __float2bfloat16(v);
        g_wh[i] = h;
        g_wl[i] = __float2bfloat16(v - __bfloat162float(h));
    }
}

// ---------------- exclusive scan of g_degin -> g_rowptr ----------------
__global__ void k_scan1() {
    __shared__ int s[512];
    int t = threadIdx.x;
    int idx = blockIdx.x * 512 + t;
    int v = (idx < Nn) ? g_degin[idx] : 0;
    s[t] = v;
    __syncthreads();
    for (int off = 1; off < 512; off <<= 1) {
        int x = (t >= off) ? s[t - off] : 0;
        __syncthreads();
        s[t] += x;
        __syncthreads();
    }
    if (idx < Nn) g_rowptr[idx] = s[t] - v;
    if (t == 511) g_part[blockIdx.x] = s[511];
}

__global__ void k_scan2() {
    __shared__ int s[128];
    int t = threadIdx.x;
    int v = (t < NB_SCAN) ? g_part[t] : 0;
    s[t] = v;
    __syncthreads();
    for (int off = 1; off < 128; off <<= 1) {
        int x = (t >= off) ? s[t - off] : 0;
        __syncthreads();
        s[t] += x;
        __syncthreads();
    }
    if (t < NB_SCAN) g_part[t] = s[t] - v;
}

__global__ void k_scan3() {
    int idx = blockIdx.x * blockDim.x + threadIdx.x;
    if (idx < Nn) g_rowptr[idx] += g_part[idx >> 9];
    if (idx == 0) g_rowptr[Nn] = Ee;
}

// ---------------- CSR fill (edges grouped by dst) ----------------
__global__ void k_fill(const int* __restrict__ src, const int* __restrict__ dst) {
    int e = blockIdx.x * blockDim.x + threadIdx.x;
    if (e < Ee) {
        int d = dst[e];
        int pos = g_rowptr[d] + atomicAdd(&g_fill[d], 1);
        g_esrc[pos] = src[e];
        g_edst[pos] = d;
    }
}

// ---------------- tensor-core GEMM (bf16-split, 3-term, pre-converted W) ----------
// out = (in [*dinvout]) @ W [+ bias].  64x96 tile, 256 threads (8 warps),
// warp (wm 0..3, wn 0..1) -> rows wm*16..+15, cols wn*48..+47 (16x48 per warp).
__global__ void __launch_bounds__(256, 3)
k_gemm(const float* __restrict__ in,
       const __nv_bfloat16* __restrict__ Wh, const __nv_bfloat16* __restrict__ Wl,
       const float* __restrict__ bias, int use_rowscale,
       float* __restrict__ out, int kin) {
    __shared__ __nv_bfloat16 sAh[64][ASTRIDE];
    __shared__ __nv_bfloat16 sAl[64][ASTRIDE];
    __shared__ __nv_bfloat16 sBh[32][BSTRIDE];
    __shared__ __nv_bfloat16 sBl[32][BSTRIDE];
    int tid = threadIdx.x;
    int lane = tid & 31, wid = tid >> 5;
    int wm = wid & 3, wn = wid >> 2;
    int rowBase = blockIdx.x * 64;

    float acc[6][4];
#pragma unroll
    for (int j = 0; j < 6; j++)
#pragma unroll
        for (int q = 0; q < 4; q++) acc[j][q] = 0.f;

    for (int kc = 0; kc < kin; kc += 32) {
        // stage A (fp32 -> hi/lo bf16 pairs), 64 rows x 16 pairs
        for (int i = tid; i < 64 * 16; i += 256) {
            int r = i >> 4, k2 = (i & 15) * 2;
            int row = rowBase + r;
            float2 v = make_float2(0.f, 0.f);
            if (row < Nn) {
                v = *(const float2*)&in[row * kin + kc + k2];
                if (use_rowscale) {
                    float sc = g_dinvout[row];
                    v.x *= sc; v.y *= sc;
                }
            }
            __nv_bfloat162 h = __floats2bfloat162_rn(v.x, v.y);
            *(__nv_bfloat162*)&sAh[r][k2] = h;
            __nv_bfloat162 l = __floats2bfloat162_rn(v.x - __bfloat162float(h.x),
                                                     v.y - __bfloat162float(h.y));
            *(__nv_bfloat162*)&sAl[r][k2] = l;
        }
        // stage W chunk (already bf16): 32 rows x 48 uint32 pairs
        for (int i = tid; i < 32 * 48; i += 256) {
            int r = i / 48, c2 = (i % 48) * 2;
            *(uint32_t*)&sBh[r][c2] = *(const uint32_t*)&Wh[(kc + r) * HIDf + c2];
            *(uint32_t*)&sBl[r][c2] = *(const uint32_t*)&Wl[(kc + r) * HIDf + c2];
        }
        __syncthreads();
#pragma unroll
        for (int ks = 0; ks < 32; ks += 16) {
            uint32_t ah[4], al[4];
            {
                int arow = wm * 16 + (lane & 15);
                int acol = ks + (lane >> 4) * 8;
                ldsm_x4(sptr(&sAh[arow][acol]), ah[0], ah[1], ah[2], ah[3]);
                ldsm_x4(sptr(&sAl[arow][acol]), al[0], al[1], al[2], al[3]);
            }
            uint32_t bh[6][2], bl[6][2];
#pragma unroll
            for (int j2 = 0; j2 < 3; j2++) {
                int brow = ks + (lane & 15);
                int bcol = wn * 48 + j2 * 16 + (lane >> 4) * 8;
                ldsm_x4t(sptr(&sBh[brow][bcol]),
                         bh[2 * j2][0], bh[2 * j2][1], bh[2 * j2 + 1][0], bh[2 * j2 + 1][1]);
                ldsm_x4t(sptr(&sBl[brow][bcol]),
                         bl[2 * j2][0], bl[2 * j2][1], bl[2 * j2 + 1][0], bl[2 * j2 + 1][1]);
            }
#pragma unroll
            for (int j = 0; j < 6; j++) {
                mma_bf16(acc[j], ah, bh[j]);
                mma_bf16(acc[j], ah, bl[j]);
                mma_bf16(acc[j], al, bh[j]);
            }
        }
        __syncthreads();
    }
    // epilogue
#pragma unroll
    for (int j = 0; j < 6; j++) {
        int r0 = rowBase + wm * 16 + (lane >> 2);
        int c = wn * 48 + j * 8 + (lane & 3) * 2;
        float b0 = 0.f, b1 = 0.f;
        if (bias) { b0 = bias[c]; b1 = bias[c + 1]; }
        if (r0 < Nn) {
            float2 o = make_float2(acc[j][0] + b0, acc[j][1] + b1);
            *(float2*)&out[r0 * HIDf + c] = o;
        }
        int r1 = r0 + 8;
        if (r1 < Nn) {
            float2 o = make_float2(acc[j][2] + b0, acc[j][3] + b1);
            *(float2*)&out[r1 * HIDf + c] = o;
        }
    }
}

// ---------------- GraphConv aggregation: out = relu(sum_in(pre[src]) * dinvin + b)
__global__ void k_agg(const float* __restrict__ pre, const float* __restrict__ bias,
                      float* __restrict__ out) {
    int warp = (blockIdx.x * blockDim.x + threadIdx.x) >> 5;
    int lane = threadIdx.x & 31;
    if (warp >= Nn) return;
    int beg = g_rowptr[warp], end = g_rowptr[warp + 1];
    float a0 = 0.f, a1 = 0.f, a2 = 0.f;
    for (int p = beg; p < end; p++) {
        const float* r = pre + g_esrc[p] * HIDf;
        a0 += r[lane];
        a1 += r[lane + 32];
        a2 += r[lane + 64];
    }
    float sc = g_dinvin[warp];
    out[warp * HIDf + lane]      = fmaxf(a0 * sc + bias[lane], 0.f);
    out[warp * HIDf + lane + 32] = fmaxf(a1 * sc + bias[lane + 32], 0.f);
    out[warp * HIDf + lane + 64] = fmaxf(a2 * sc + bias[lane + 64], 0.f);
}

// ---------------- GATv2 edge logits: warp per dst node, fd/attn in registers ----
// lane = (sub 0..3, head 0..7); edges are dst-sorted so this warp owns the slab.
// fd row + attn loaded ONCE per node; per edge only the fs slice is gathered.
__global__ void k_logits(const float* __restrict__ attn) {
    int warp = (blockIdx.x * blockDim.x + threadIdx.x) >> 5;
    int lane = threadIdx.x & 31;
    if (warp >= Nn) return;
    int beg = g_rowptr[warp], end = g_rowptr[warp + 1];
    if (beg == end) return;
    int h = lane & 7, sub = lane >> 3;

    float fdv[Dd], av[Dd];
    const float4* fdp = (const float4*)(g_fd + warp * HIDf + h * Dd);
    const float4* ap  = (const float4*)(attn + h * Dd);
#pragma unroll
    for (int j = 0; j < 3; j++) {
        float4 t = fdp[j];
        fdv[4 * j] = t.x; fdv[4 * j + 1] = t.y; fdv[4 * j + 2] = t.z; fdv[4 * j + 3] = t.w;
        float4 u = __ldg(ap + j);
        av[4 * j] = u.x; av[4 * j + 1] = u.y; av[4 * j + 2] = u.z; av[4 * j + 3] = u.w;
    }

    for (int p = beg + sub; p < end; p += 4) {
        const float4* fsp = (const float4*)(g_fs + g_esrc[p] * HIDf + h * Dd);
        float lg = 0.f;
#pragma unroll
        for (int j = 0; j < 3; j++) {
            float4 a = fsp[j];
            float v;
            v = a.x + fdv[4 * j];     v = (v > 0.f) ? v : 0.2f * v; lg += v * av[4 * j];
            v = a.y + fdv[4 * j + 1]; v = (v > 0.f) ? v : 0.2f * v; lg += v * av[4 * j + 1];
            v = a.z + fdv[4 * j + 2]; v = (v > 0.f) ? v : 0.2f * v; lg += v * av[4 * j + 2];
            v = a.w + fdv[4 * j + 3]; v = (v > 0.f) ? v : 0.2f * v; lg += v * av[4 * j + 3];
        }
        g_logits[p * 8 + h] = lg;
    }
}

// ---------------- GATv2 per-node softmax + weighted sum + relu ----------------
// phase 2 stores exp(logit - m) back into g_logits (slab owned exclusively by
// this warp), so the accumulate loop does zero exps: 8 MUFU/edge, not 96.
__global__ void k_gatnode(float* __restrict__ out) {
    int warp = (blockIdx.x * blockDim.x + threadIdx.x) >> 5;
    int lane = threadIdx.x & 31;
    if (warp >= Nn) return;
    int beg = g_rowptr[warp], end = g_rowptr[warp + 1];
    int h = lane & 7, sub = lane >> 3;

    float mh = -3.402823466e38f;
    for (int p = beg + sub; p < end; p += 4) mh = fmaxf(mh, g_logits[p * 8 + h]);
    mh = fmaxf(mh, __shfl_xor_sync(0xffffffffu, mh, 8));
    mh = fmaxf(mh, __shfl_xor_sync(0xffffffffu, mh, 16));

    float den = 0.f;
    for (int p = beg + sub; p < end; p += 4) {
        float w = __expf(g_logits[p * 8 + h] - mh);
        g_logits[p * 8 + h] = w;      // in-place: logits -> unnormalized weights
        den += w;
    }
    den += __shfl_xor_sync(0xffffffffu, den, 8);
    den += __shfl_xor_sync(0xffffffffu, den, 16);
    __syncwarp();                      // order weight stores before reads below

    int f0 = lane, f1 = lane + 32, f2 = lane + 64;
    int h0 = f0 / Dd, h1 = f1 / Dd, h2 = f2 / Dd;
    float d0 = __shfl_sync(0xffffffffu, den, h0);
    float d1 = __shfl_sync(0xffffffffu, den, h1);
    float d2 = __shfl_sync(0xffffffffu, den, h2);
    float r0 = (d0 > 0.f) ? 1.f / d0 : 0.f;
    float r1 = (d1 > 0.f) ? 1.f / d1 : 0.f;
    float r2 = (d2 > 0.f) ? 1.f / d2 : 0.f;

    float acc0 = 0.f, acc1 = 0.f, acc2 = 0.f;
    for (int p = beg; p < end; p++) {
        const float* lg = g_logits + p * 8;
        float w0 = lg[h0];
        float w1 = lg[h1];
        float w2 = lg[h2];
        const float* fr = g_fs + g_esrc[p] * HIDf;
        acc0 += w0 * fr[f0];
        acc1 += w1 * fr[f1];
        acc2 += w2 * fr[f2];
    }
    out[warp * HIDf + f0] = fmaxf(acc0 * r0, 0.f);
    out[warp * HIDf + f1] = fmaxf(acc1 * r1, 0.f);
    out[warp * HIDf + f2] = fmaxf(acc2 * r2, 0.f);
}

// ---------------- per-graph max readout (values >= 0 after relu) ----------------
__global__ void k_readout(const float* __restrict__ hfin, const int* __restrict__ gid) {
    __shared__ int s[Gg * HIDf];
    int tid = threadIdx.x;  // 384
    for (int i = tid; i < Gg * HIDf; i += 384) s[i] = 0;
    __syncthreads();
    int f = tid % 96, rr = tid / 96;
    for (int node = blockIdx.x * 4 + rr; node < Nn; node += 64 * 4) {
        int g = gid[node];
        float v = hfin[node * HIDf + f];
        atomicMax(&s[g * HIDf + f], __float_as_int(v));
    }
    __syncthreads();
    for (int i = tid; i < Gg * HIDf; i += 384) atomicMax(&g_hg[i], s[i]);
}

// ---------------- classifier MLP on [64,96] ----------------
__global__ void k_mlp(const float* __restrict__ Wc1, const float* __restrict__ bc1,
                      const float* __restrict__ Wc2, const float* __restrict__ bc2,
                      const float* __restrict__ Wc3, const float* __restrict__ bc3,
                      float* __restrict__ out) {
    __shared__ float A[Gg * HIDf];
    __shared__ float B[Gg * HIDf];
    int tid = threadIdx.x;  // 512
    for (int i = tid; i < Gg * HIDf; i += 512) A[i] = __int_as_float(g_hg[i]);
    __syncthreads();
    for (int i = tid; i < Gg * HIDf; i += 512) {
        int r = i / 96, c = i % 96;
        float acc = bc1[c];
        for (int k = 0; k < 96; k++) acc += A[r * 96 + k] * Wc1[k * 96 + c];
        B[i] = fmaxf(acc, 0.f);
    }
    __syncthreads();
    for (int i = tid; i < Gg * 48; i += 512) {
        int r = i / 48, c = i % 48;
        float acc = bc2[c];
        for (int k = 0; k < 96; k++) acc += B[r * 96 + k] * Wc2[k * 48 + c];
        A[i] = fmaxf(acc, 0.f);
    }
    __syncthreads();
    for (int i = tid; i < Gg * OUTf; i += 512) {
        int r = i / 10, c = i % 10;
        float acc = bc3[c];
        for (int k = 0; k < 48; k++) acc += A[r * 48 + k] * Wc3[k * 10 + c];
        out[i] = acc;
    }
}

// ---------------- host launcher ----------------
extern "C" void kernel_launch(void* const* d_in, const int* in_sizes, int n_in,
                              void* d_out, int out_size) {
    (void)in_sizes; (void)n_in; (void)out_size;
    const float* x    = (const float*)d_in[0];
    const int*   src  = (const int*)d_in[1];
    const int*   dst  = (const int*)d_in[2];
    const int*   gid  = (const int*)d_in[3];
    const float* W1   = (const float*)d_in[4];
    const float* b1   = (const float*)d_in[5];
    const float* W2   = (const float*)d_in[6];
    const float* b2   = (const float*)d_in[7];
    const float* Ws   = (const float*)d_in[8];
    const float* bs   = (const float*)d_in[9];
    const float* Wd   = (const float*)d_in[10];
    const float* bd   = (const float*)d_in[11];
    const float* attn = (const float*)d_in[12];
    const float* Wc1  = (const float*)d_in[13];
    const float* bc1  = (const float*)d_in[14];
    const float* Wc2  = (const float*)d_in[15];
    const float* bc2  = (const float*)d_in[16];
    const float* Wc3  = (const float*)d_in[17];
    const float* bc3  = (const float*)d_in[18];
    float* out = (float*)d_out;

    float *p_tmp, *p_h0, *p_h1, *p_fs, *p_fd;
    cudaGetSymbolAddress((void**)&p_tmp, g_tmp);
    cudaGetSymbolAddress((void**)&p_h0, g_h0);
    cudaGetSymbolAddress((void**)&p_h1, g_h1);
    cudaGetSymbolAddress((void**)&p_fs, g_fs);
    cudaGetSymbolAddress((void**)&p_fd, g_fd);
    __nv_bfloat16 *p_wh, *p_wl;
    cudaGetSymbolAddress((void**)&p_wh, g_wh);
    cudaGetSymbolAddress((void**)&p_wl, g_wl);

    const int TPB = 256;
    int gemm_blocks = (Nn + 63) / 64;             // 782
    int warp_blocks = (Nn * 32 + TPB - 1) / TPB;  // 6250
    int edge_blocks = (Ee + TPB - 1) / TPB;       // 3125
    int prep_blocks = (WTOT + TPB - 1) / TPB;     // 300

    k_init<<<(Nn + TPB - 1) / TPB, TPB>>>();                          // 0
    k_degree<<<edge_blocks, TPB>>>(src, dst);                         // 1
    k_prep<<<prep_blocks, TPB>>>(W1, W2, Ws, Wd);                     // 2
    k_gemm<<<gemm_blocks, 256>>>(x, p_wh + W1_OFF, p_wl + W1_OFF,
                                 nullptr, 1, p_tmp, INF);             // 3  <- profiled
    k_scan1<<<NB_SCAN, 512>>>();                                      // 4
    k_scan2<<<1, 128>>>();                                            // 5
    k_scan3<<<NB_SCAN, 512>>>();                                      // 6
    k_fill<<<edge_blocks, TPB>>>(src, dst);                           // 7
    k_agg<<<warp_blocks, TPB>>>(p_tmp, b1, p_h0);                     // 8

    k_gemm<<<gemm_blocks, 256>>>(p_h0, p_wh + W2_OFF, p_wl + W2_OFF,
                                 nullptr, 1, p_tmp, HIDf);
    k_agg<<<warp_blocks, TPB>>>(p_tmp, b2, p_h1);

    float* hin = p_h1;
    float* hout = p_h0;
    for (int i = 0; i < 3; i++) {
        k_gemm<<<gemm_blocks, 256>>>(hin, p_wh + WS_OFF + i * HIDf * HIDf,
                                     p_wl + WS_OFF + i * HIDf * HIDf,
                                     bs + i * HIDf, 0, p_fs, HIDf);
        k_gemm<<<gemm_blocks, 256>>>(hin, p_wh + WD_OFF + i * HIDf * HIDf,
                                     p_wl + WD_OFF + i * HIDf * HIDf,
                                     bd + i * HIDf, 0, p_fd, HIDf);
        k_logits<<<warp_blocks, TPB>>>(attn + i * Hh * Dd);
        k_gatnode<<<warp_blocks, TPB>>>(hout);
        float* t = hin; hin = hout; hout = t;
    }

    k_readout<<<64, 384>>>(hin, gid);
    k_mlp<<<1, 512>>>(Wc1, bc1, Wc2, bc2, Wc3, bc3, out);
}

// round 12
// speedup vs baseline: 1.7926x; 1.1704x over previous
#include <cuda_runtime.h>
#include <cuda_bf16.h>
#include <cstdint>
#include <stdint.h>
#include <math.h>

#define Nn 50000
#define Ee 800000
#define INF 128
#define HIDf 96
#define Hh 8
#define Dd 12
#define Gg 64
#define OUTf 10
#define NB_SCAN ((Nn + 511) / 512)   // 98
#define ASTRIDE 40    // 32 + 8 pad (bf16)
#define BSTRIDE 104   // 96 + 8 pad (bf16)

// ---------------- scratch (device globals; no allocation allowed) ------------
__device__ __align__(16) float g_tmp[Nn * HIDf];
__device__ __align__(16) float g_h0[Nn * HIDf];
__device__ __align__(16) float g_h1[Nn * HIDf];
__device__ __align__(16) float g_fs[Nn * HIDf];
__device__ __align__(16) float g_fd[Nn * HIDf];
__device__ __align__(16) float g_logits[Ee * Hh];
__device__ int   g_degout[Nn];
__device__ int   g_degin[Nn];
__device__ int   g_fill[Nn];
__device__ int   g_rowptr[Nn + 1];
__device__ int   g_esrc[Ee];
__device__ int   g_edst[Ee];
__device__ int   g_part[128];
__device__ int   g_hg[Gg * HIDf];
__device__ float g_dinvout[Nn];
__device__ float g_dinvin[Nn];
// pre-converted bf16 hi/lo weights: [W1 | W2 | Ws0..2 | Wd0..2]
#define W1_OFF 0
#define W2_OFF (INF * HIDf)                    // 12288
#define WS_OFF (W2_OFF + HIDf * HIDf)          // 21504
#define WD_OFF (WS_OFF + 3 * HIDf * HIDf)      // 49152
#define WTOT   (WD_OFF + 3 * HIDf * HIDf)      // 76800
__device__ __align__(16) __nv_bfloat16 g_wh[WTOT];
__device__ __align__(16) __nv_bfloat16 g_wl[WTOT];

// ---------------- mma helpers ----------------
__device__ __forceinline__ uint32_t sptr(const void* p) {
    return (uint32_t)__cvta_generic_to_shared(p);
}
__device__ __forceinline__ void ldsm_x4(uint32_t addr, uint32_t& r0, uint32_t& r1,
                                        uint32_t& r2, uint32_t& r3) {
    asm volatile("ldmatrix.sync.aligned.m8n8.x4.shared.b16 {%0,%1,%2,%3}, [%4];"
                 : "=r"(r0), "=r"(r1), "=r"(r2), "=r"(r3) : "r"(addr));
}
__device__ __forceinline__ void ldsm_x4t(uint32_t addr, uint32_t& r0, uint32_t& r1,
                                         uint32_t& r2, uint32_t& r3) {
    asm volatile("ldmatrix.sync.aligned.m8n8.x4.trans.shared.b16 {%0,%1,%2,%3}, [%4];"
                 : "=r"(r0), "=r"(r1), "=r"(r2), "=r"(r3) : "r"(addr));
}
__device__ __forceinline__ void mma_bf16(float* c, const uint32_t* a, const uint32_t* b) {
    asm volatile("mma.sync.aligned.m16n8k16.row.col.f32.bf16.bf16.f32 "
                 "{%0,%1,%2,%3}, {%4,%5,%6,%7}, {%8,%9}, {%0,%1,%2,%3};"
                 : "+f"(c[0]), "+f"(c[1]), "+f"(c[2]), "+f"(c[3])
                 : "r"(a[0]), "r"(a[1]), "r"(a[2]), "r"(a[3]), "r"(b[0]), "r"(b[1]));
}

// ---------------- init ----------------
__global__ void k_init() {
    int i = blockIdx.x * blockDim.x + threadIdx.x;
    if (i < Nn) { g_degout[i] = 0; g_degin[i] = 0; g_fill[i] = 0; }
    if (i < Gg * HIDf) g_hg[i] = 0;   // bits of +0.0f; readout inputs are >= 0
}

// ---------------- degrees / histogram ----------------
__global__ void k_degree(const int* __restrict__ src, const int* __restrict__ dst) {
    int e = blockIdx.x * blockDim.x + threadIdx.x;
    if (e < Ee) {
        atomicAdd(&g_degout[src[e]], 1);
        atomicAdd(&g_degin[dst[e]], 1);
    }
}

// ---------------- deg^-0.5 + weight bf16 hi/lo conversion (fused) ----------------
__global__ void k_prep(const float* __restrict__ W1, const float* __restrict__ W2,
                       const float* __restrict__ Ws, const float* __restrict__ Wd) {
    int i = blockIdx.x * blockDim.x + threadIdx.x;
    if (i < Nn) {
        g_dinvout[i] = rsqrtf((float)max(g_degout[i], 1));
        g_dinvin[i]  = rsqrtf((float)max(g_degin[i], 1));
    }
    if (i < WTOT) {
        float v;
        if (i < W2_OFF)      v = W1[i];
        else if (i < WS_OFF) v = W2[i - W2_OFF];
        else if (i < WD_OFF) v = Ws[i - WS_OFF];
        else                 v = Wd[i - WD_OFF];
        __nv_bfloat16 h = __float2bfloat16(v);
        g_wh[i] = h;
        g_wl[i] = __float2bfloat16(v - __bfloat162float(h));
    }
}

// ---------------- exclusive scan of g_degin -> g_rowptr ----------------
__global__ void k_scan1() {
    __shared__ int s[512];
    int t = threadIdx.x;
    int idx = blockIdx.x * 512 + t;
    int v = (idx < Nn) ? g_degin[idx] : 0;
    s[t] = v;
    __syncthreads();
    for (int off = 1; off < 512; off <<= 1) {
        int x = (t >= off) ? s[t - off] : 0;
        __syncthreads();
        s[t] += x;
        __syncthreads();
    }
    if (idx < Nn) g_rowptr[idx] = s[t] - v;
    if (t == 511) g_part[blockIdx.x] = s[511];
}

__global__ void k_scan2() {
    __shared__ int s[128];
    int t = threadIdx.x;
    int v = (t < NB_SCAN) ? g_part[t] : 0;
    s[t] = v;
    __syncthreads();
    for (int off = 1; off < 128; off <<= 1) {
        int x = (t >= off) ? s[t - off] : 0;
        __syncthreads();
        s[t] += x;
        __syncthreads();
    }
    if (t < NB_SCAN) g_part[t] = s[t] - v;
}

__global__ void k_scan3() {
    int idx = blockIdx.x * blockDim.x + threadIdx.x;
    if (idx < Nn) g_rowptr[idx] += g_part[idx >> 9];
    if (idx == 0) g_rowptr[Nn] = Ee;
}

// ---------------- CSR fill (edges grouped by dst) ----------------
__global__ void k_fill(const int* __restrict__ src, const int* __restrict__ dst) {
    int e = blockIdx.x * blockDim.x + threadIdx.x;
    if (e < Ee) {
        int d = dst[e];
        int pos = g_rowptr[d] + atomicAdd(&g_fill[d], 1);
        g_esrc[pos] = src[e];
        g_edst[pos] = d;
    }
}

// ---------------- tensor-core GEMM (bf16-split, double-buffered pipeline) -------
// out = (in [*dinvout]) @ W [+ bias].  64x96 tile, 256 threads (8 warps).
// Per chunk: issue next LDGs -> MMA current buffer -> convert+STS next -> sync.
__global__ void __launch_bounds__(256, 2)
k_gemm(const float* __restrict__ in,
       const __nv_bfloat16* __restrict__ Wh, const __nv_bfloat16* __restrict__ Wl,
       const float* __restrict__ bias, int use_rowscale,
       float* __restrict__ out, int kin) {
    __shared__ __nv_bfloat16 sAh[2][64][ASTRIDE];
    __shared__ __nv_bfloat16 sAl[2][64][ASTRIDE];
    __shared__ __nv_bfloat16 sBh[2][32][BSTRIDE];
    __shared__ __nv_bfloat16 sBl[2][32][BSTRIDE];
    int tid = threadIdx.x;
    int lane = tid & 31, wid = tid >> 5;
    int wm = wid & 3, wn = wid >> 2;
    int rowBase = blockIdx.x * 64;
    int nc = kin >> 5;

    float acc[6][4] = {};
    float2 a_pf[4];
    uint32_t bh_pf[6], bl_pf[6];

    auto load_regs = [&](int kc) {
#pragma unroll
        for (int t = 0; t < 4; t++) {
            int idx = tid + t * 256;
            int r = idx >> 4, k2 = (idx & 15) * 2;
            int row = rowBase + r;
            float2 v = make_float2(0.f, 0.f);
            if (row < Nn) {
                v = *(const float2*)&in[row * kin + kc + k2];
                if (use_rowscale) { float sc = g_dinvout[row]; v.x *= sc; v.y *= sc; }
            }
            a_pf[t] = v;
        }
#pragma unroll
        for (int t = 0; t < 6; t++) {
            int idx = tid + t * 256;
            int r = idx / 48, c2 = (idx % 48) * 2;
            bh_pf[t] = *(const uint32_t*)&Wh[(kc + r) * HIDf + c2];
            bl_pf[t] = *(const uint32_t*)&Wl[(kc + r) * HIDf + c2];
        }
    };
    auto store_buf = [&](int buf) {
#pragma unroll
        for (int t = 0; t < 4; t++) {
            int idx = tid + t * 256;
            int r = idx >> 4, k2 = (idx & 15) * 2;
            __nv_bfloat162 h = __floats2bfloat162_rn(a_pf[t].x, a_pf[t].y);
            *(__nv_bfloat162*)&sAh[buf][r][k2] = h;
            *(__nv_bfloat162*)&sAl[buf][r][k2] =
                __floats2bfloat162_rn(a_pf[t].x - __bfloat162float(h.x),
                                      a_pf[t].y - __bfloat162float(h.y));
        }
#pragma unroll
        for (int t = 0; t < 6; t++) {
            int idx = tid + t * 256;
            int r = idx / 48, c2 = (idx % 48) * 2;
            *(uint32_t*)&sBh[buf][r][c2] = bh_pf[t];
            *(uint32_t*)&sBl[buf][r][c2] = bl_pf[t];
        }
    };

    load_regs(0);
    store_buf(0);
    __syncthreads();

    for (int c = 0; c < nc; c++) {
        int cur = c & 1;
        bool more = (c + 1 < nc);
        if (more) load_regs((c + 1) << 5);   // LDGs in flight during MMA below
#pragma unroll
        for (int ks = 0; ks < 32; ks += 16) {
            uint32_t ah[4], al[4];
            {
                int arow = wm * 16 + (lane & 15);
                int acol = ks + (lane >> 4) * 8;
                ldsm_x4(sptr(&sAh[cur][arow][acol]), ah[0], ah[1], ah[2], ah[3]);
                ldsm_x4(sptr(&sAl[cur][arow][acol]), al[0], al[1], al[2], al[3]);
            }
            uint32_t bh[6][2], bl[6][2];
#pragma unroll
            for (int j2 = 0; j2 < 3; j2++) {
                int brow = ks + (lane & 15);
                int bcol = wn * 48 + j2 * 16 + (lane >> 4) * 8;
                ldsm_x4t(sptr(&sBh[cur][brow][bcol]),
                         bh[2 * j2][0], bh[2 * j2][1], bh[2 * j2 + 1][0], bh[2 * j2 + 1][1]);
                ldsm_x4t(sptr(&sBl[cur][brow][bcol]),
                         bl[2 * j2][0], bl[2 * j2][1], bl[2 * j2 + 1][0], bl[2 * j2 + 1][1]);
            }
#pragma unroll
            for (int j = 0; j < 6; j++) {
                mma_bf16(acc[j], ah, bh[j]);
                mma_bf16(acc[j], ah, bl[j]);
                mma_bf16(acc[j], al, bh[j]);
            }
        }
        if (more) store_buf(cur ^ 1);
        __syncthreads();
    }
    // epilogue
#pragma unroll
    for (int j = 0; j < 6; j++) {
        int r0 = rowBase + wm * 16 + (lane >> 2);
        int c = wn * 48 + j * 8 + (lane & 3) * 2;
        float b0 = 0.f, b1 = 0.f;
        if (bias) { b0 = bias[c]; b1 = bias[c + 1]; }
        if (r0 < Nn) {
            float2 o = make_float2(acc[j][0] + b0, acc[j][1] + b1);
            *(float2*)&out[r0 * HIDf + c] = o;
        }
        int r1 = r0 + 8;
        if (r1 < Nn) {
            float2 o = make_float2(acc[j][2] + b0, acc[j][3] + b1);
            *(float2*)&out[r1 * HIDf + c] = o;
        }
    }
}

// ---------------- GraphConv aggregation: out = relu(sum_in(pre[src]) * dinvin + b)
__global__ void k_agg(const float* __restrict__ pre, const float* __restrict__ bias,
                      float* __restrict__ out) {
    int warp = (blockIdx.x * blockDim.x + threadIdx.x) >> 5;
    int lane = threadIdx.x & 31;
    if (warp >= Nn) return;
    int beg = g_rowptr[warp], end = g_rowptr[warp + 1];
    float a0 = 0.f, a1 = 0.f, a2 = 0.f;
    for (int p = beg; p < end; p++) {
        const float* r = pre + g_esrc[p] * HIDf;
        a0 += r[lane];
        a1 += r[lane + 32];
        a2 += r[lane + 64];
    }
    float sc = g_dinvin[warp];
    out[warp * HIDf + lane]      = fmaxf(a0 * sc + bias[lane], 0.f);
    out[warp * HIDf + lane + 32] = fmaxf(a1 * sc + bias[lane + 32], 0.f);
    out[warp * HIDf + lane + 64] = fmaxf(a2 * sc + bias[lane + 64], 0.f);
}

// ---------------- GATv2 edge logits: warp per dst node, fd/attn in registers ----
__global__ void k_logits(const float* __restrict__ attn) {
    int warp = (blockIdx.x * blockDim.x + threadIdx.x) >> 5;
    int lane = threadIdx.x & 31;
    if (warp >= Nn) return;
    int beg = g_rowptr[warp], end = g_rowptr[warp + 1];
    if (beg == end) return;
    int h = lane & 7, sub = lane >> 3;

    float fdv[Dd], av[Dd];
    const float4* fdp = (const float4*)(g_fd + warp * HIDf + h * Dd);
    const float4* ap  = (const float4*)(attn + h * Dd);
#pragma unroll
    for (int j = 0; j < 3; j++) {
        float4 t = fdp[j];
        fdv[4 * j] = t.x; fdv[4 * j + 1] = t.y; fdv[4 * j + 2] = t.z; fdv[4 * j + 3] = t.w;
        float4 u = __ldg(ap + j);
        av[4 * j] = u.x; av[4 * j + 1] = u.y; av[4 * j + 2] = u.z; av[4 * j + 3] = u.w;
    }

    for (int p = beg + sub; p < end; p += 4) {
        const float4* fsp = (const float4*)(g_fs + g_esrc[p] * HIDf + h * Dd);
        float lg = 0.f;
#pragma unroll
        for (int j = 0; j < 3; j++) {
            float4 a = fsp[j];
            float v;
            v = a.x + fdv[4 * j];     v = (v > 0.f) ? v : 0.2f * v; lg += v * av[4 * j];
            v = a.y + fdv[4 * j + 1]; v = (v > 0.f) ? v : 0.2f * v; lg += v * av[4 * j + 1];
            v = a.z + fdv[4 * j + 2]; v = (v > 0.f) ? v : 0.2f * v; lg += v * av[4 * j + 2];
            v = a.w + fdv[4 * j + 3]; v = (v > 0.f) ? v : 0.2f * v; lg += v * av[4 * j + 3];
        }
        g_logits[p * 8 + h] = lg;
    }
}

// ---------------- GATv2 per-node softmax + weighted sum + relu ----------------
__global__ void k_gatnode(float* __restrict__ out) {
    int warp = (blockIdx.x * blockDim.x + threadIdx.x) >> 5;
    int lane = threadIdx.x & 31;
    if (warp >= Nn) return;
    int beg = g_rowptr[warp], end = g_rowptr[warp + 1];
    int h = lane & 7, sub = lane >> 3;

    float mh = -3.402823466e38f;
    for (int p = beg + sub; p < end; p += 4) mh = fmaxf(mh, g_logits[p * 8 + h]);
    mh = fmaxf(mh, __shfl_xor_sync(0xffffffffu, mh, 8));
    mh = fmaxf(mh, __shfl_xor_sync(0xffffffffu, mh, 16));

    float den = 0.f;
    for (int p = beg + sub; p < end; p += 4) {
        float w = __expf(g_logits[p * 8 + h] - mh);
        g_logits[p * 8 + h] = w;      // in-place: logits -> unnormalized weights
        den += w;
    }
    den += __shfl_xor_sync(0xffffffffu, den, 8);
    den += __shfl_xor_sync(0xffffffffu, den, 16);
    __syncwarp();                      // order weight stores before reads below

    int f0 = lane, f1 = lane + 32, f2 = lane + 64;
    int h0 = f0 / Dd, h1 = f1 / Dd, h2 = f2 / Dd;
    float d0 = __shfl_sync(0xffffffffu, den, h0);
    float d1 = __shfl_sync(0xffffffffu, den, h1);
    float d2 = __shfl_sync(0xffffffffu, den, h2);
    float r0 = (d0 > 0.f) ? 1.f / d0 : 0.f;
    float r1 = (d1 > 0.f) ? 1.f / d1 : 0.f;
    float r2 = (d2 > 0.f) ? 1.f / d2 : 0.f;

    float acc0 = 0.f, acc1 = 0.f, acc2 = 0.f;
    for (int p = beg; p < end; p++) {
        const float* lg = g_logits + p * 8;
        float w0 = lg[h0];
        float w1 = lg[h1];
        float w2 = lg[h2];
        const float* fr = g_fs + g_esrc[p] * HIDf;
        acc0 += w0 * fr[f0];
        acc1 += w1 * fr[f1];
        acc2 += w2 * fr[f2];
    }
    out[warp * HIDf + f0] = fmaxf(acc0 * r0, 0.f);
    out[warp * HIDf + f1] = fmaxf(acc1 * r1, 0.f);
    out[warp * HIDf + f2] = fmaxf(acc2 * r2, 0.f);
}

// ---------------- per-graph max readout (values >= 0 after relu) ----------------
__global__ void k_readout(const float* __restrict__ hfin, const int* __restrict__ gid) {
    __shared__ int s[Gg * HIDf];
    int tid = threadIdx.x;  // 384
    for (int i = tid; i < Gg * HIDf; i += 384) s[i] = 0;
    __syncthreads();
    int f = tid % 96, rr = tid / 96;
    for (int node = blockIdx.x * 4 + rr; node < Nn; node += 64 * 4) {
        int g = gid[node];
        float v = hfin[node * HIDf + f];
        atomicMax(&s[g * HIDf + f], __float_as_int(v));
    }
    __syncthreads();
    for (int i = tid; i < Gg * HIDf; i += 384) atomicMax(&g_hg[i], s[i]);
}

// ---------------- classifier MLP on [64,96] ----------------
__global__ void k_mlp(const float* __restrict__ Wc1, const float* __restrict__ bc1,
                      const float* __restrict__ Wc2, const float* __restrict__ bc2,
                      const float* __restrict__ Wc3, const float* __restrict__ bc3,
                      float* __restrict__ out) {
    __shared__ float A[Gg * HIDf];
    __shared__ float B[Gg * HIDf];
    int tid = threadIdx.x;  // 512
    for (int i = tid; i < Gg * HIDf; i += 512) A[i] = __int_as_float(g_hg[i]);
    __syncthreads();
    for (int i = tid; i < Gg * HIDf; i += 512) {
        int r = i / 96, c = i % 96;
        float acc = bc1[c];
        for (int k = 0; k < 96; k++) acc += A[r * 96 + k] * Wc1[k * 96 + c];
        B[i] = fmaxf(acc, 0.f);
    }
    __syncthreads();
    for (int i = tid; i < Gg * 48; i += 512) {
        int r = i / 48, c = i % 48;
        float acc = bc2[c];
        for (int k = 0; k < 96; k++) acc += B[r * 96 + k] * Wc2[k * 48 + c];
        A[i] = fmaxf(acc, 0.f);
    }
    __syncthreads();
    for (int i = tid; i < Gg * OUTf; i += 512) {
        int r = i / 10, c = i % 10;
        float acc = bc3[c];
        for (int k = 0; k < 48; k++) acc += A[r * 48 + k] * Wc3[k * 10 + c];
        out[i] = acc;
    }
}

// ---------------- host launcher ----------------
extern "C" void kernel_launch(void* const* d_in, const int* in_sizes, int n_in,
                              void* d_out, int out_size) {
    (void)in_sizes; (void)n_in; (void)out_size;
    const float* x    = (const float*)d_in[0];
    const int*   src  = (const int*)d_in[1];
    const int*   dst  = (const int*)d_in[2];
    const int*   gid  = (const int*)d_in[3];
    const float* W1   = (const float*)d_in[4];
    const float* b1   = (const float*)d_in[5];
    const float* W2   = (const float*)d_in[6];
    const float* b2   = (const float*)d_in[7];
    const float* Ws   = (const float*)d_in[8];
    const float* bs   = (const float*)d_in[9];
    const float* Wd   = (const float*)d_in[10];
    const float* bd   = (const float*)d_in[11];
    const float* attn = (const float*)d_in[12];
    const float* Wc1  = (const float*)d_in[13];
    const float* bc1  = (const float*)d_in[14];
    const float* Wc2  = (const float*)d_in[15];
    const float* bc2  = (const float*)d_in[16];
    const float* Wc3  = (const float*)d_in[17];
    const float* bc3  = (const float*)d_in[18];
    float* out = (float*)d_out;

    float *p_tmp, *p_h0, *p_h1, *p_fs, *p_fd;
    cudaGetSymbolAddress((void**)&p_tmp, g_tmp);
    cudaGetSymbolAddress((void**)&p_h0, g_h0);
    cudaGetSymbolAddress((void**)&p_h1, g_h1);
    cudaGetSymbolAddress((void**)&p_fs, g_fs);
    cudaGetSymbolAddress((void**)&p_fd, g_fd);
    __nv_bfloat16 *p_wh, *p_wl;
    cudaGetSymbolAddress((void**)&p_wh, g_wh);
    cudaGetSymbolAddress((void**)&p_wl, g_wl);

    const int TPB = 256;
    int gemm_blocks = (Nn + 63) / 64;             // 782
    int warp_blocks = (Nn * 32 + TPB - 1) / TPB;  // 6250
    int edge_blocks = (Ee + TPB - 1) / TPB;       // 3125
    int prep_blocks = (WTOT + TPB - 1) / TPB;     // 300

    k_init<<<(Nn + TPB - 1) / TPB, TPB>>>();                          // 0
    k_degree<<<edge_blocks, TPB>>>(src, dst);                         // 1
    k_prep<<<prep_blocks, TPB>>>(W1, W2, Ws, Wd);                     // 2
    k_gemm<<<gemm_blocks, 256>>>(x, p_wh + W1_OFF, p_wl + W1_OFF,
                                 nullptr, 1, p_tmp, INF);             // 3  <- profiled
    k_scan1<<<NB_SCAN, 512>>>();                                      // 4
    k_scan2<<<1, 128>>>();                                            // 5
    k_scan3<<<NB_SCAN, 512>>>();                                      // 6
    k_fill<<<edge_blocks, TPB>>>(src, dst);                           // 7
    k_agg<<<warp_blocks, TPB>>>(p_tmp, b1, p_h0);                     // 8

    k_gemm<<<gemm_blocks, 256>>>(p_h0, p_wh + W2_OFF, p_wl + W2_OFF,
                                 nullptr, 1, p_tmp, HIDf);
    k_agg<<<warp_blocks, TPB>>>(p_tmp, b2, p_h1);

    float* hin = p_h1;
    float* hout = p_h0;
    for (int i = 0; i < 3; i++) {
        k_gemm<<<gemm_blocks, 256>>>(hin, p_wh + WS_OFF + i * HIDf * HIDf,
                                     p_wl + WS_OFF + i * HIDf * HIDf,
                                     bs + i * HIDf, 0, p_fs, HIDf);
        k_gemm<<<gemm_blocks, 256>>>(hin, p_wh + WD_OFF + i * HIDf * HIDf,
                                     p_wl + WD_OFF + i * HIDf * HIDf,
                                     bd + i * HIDf, 0, p_fd, HIDf);
        k_logits<<<warp_blocks, TPB>>>(attn + i * Hh * Dd);
        k_gatnode<<<warp_blocks, TPB>>>(hout);
        float* t = hin; hin = hout; hout = t;
    }

    k_readout<<<64, 384>>>(hin, gid);
    k_mlp<<<1, 512>>>(Wc1, bc1, Wc2, bc2, Wc3, bc3, out);
}

// round 13
// speedup vs baseline: 1.9877x; 1.1088x over previous
#include <cuda_runtime.h>
#include <cuda_bf16.h>
#include <cstdint>
#include <stdint.h>
#include <math.h>

#define Nn 50000
#define Ee 800000
#define INF 128
#define HIDf 96
#define Hh 8
#define Dd 12
#define Gg 64
#define OUTf 10
#define NB_SCAN ((Nn + 511) / 512)   // 98
#define ASTRIDE 40    // 32 + 8 pad (bf16)
#define BSTRIDE 104   // 96 + 8 pad (bf16)

// ---------------- scratch (device globals; no allocation allowed) ------------
__device__ __align__(16) float g_tmp[Nn * HIDf];
__device__ __align__(16) float g_h0[Nn * HIDf];
__device__ __align__(16) float g_h1[Nn * HIDf];
__device__ __align__(16) float g_fs[Nn * HIDf];
__device__ __align__(16) float g_fd[Nn * HIDf];
__device__ __align__(16) float g_logits[Ee * Hh];
__device__ int   g_degout[Nn];
__device__ int   g_degin[Nn];
__device__ int   g_fill[Nn];
__device__ int   g_rowptr[Nn + 1];
__device__ int   g_esrc[Ee];
__device__ int   g_edst[Ee];
__device__ int   g_part[128];
__device__ int   g_hg[Gg * HIDf];
__device__ float g_dinvout[Nn];
__device__ float g_dinvin[Nn];
// pre-converted bf16 hi/lo weights: [W1 | W2 | Ws0..2 | Wd0..2]
#define W1_OFF 0
#define W2_OFF (INF * HIDf)                    // 12288
#define WS_OFF (W2_OFF + HIDf * HIDf)          // 21504
#define WD_OFF (WS_OFF + 3 * HIDf * HIDf)      // 49152
#define WTOT   (WD_OFF + 3 * HIDf * HIDf)      // 76800
__device__ __align__(16) __nv_bfloat16 g_wh[WTOT];
__device__ __align__(16) __nv_bfloat16 g_wl[WTOT];

// ---------------- mma helpers ----------------
__device__ __forceinline__ uint32_t sptr(const void* p) {
    return (uint32_t)__cvta_generic_to_shared(p);
}
__device__ __forceinline__ void ldsm_x4(uint32_t addr, uint32_t& r0, uint32_t& r1,
                                        uint32_t& r2, uint32_t& r3) {
    asm volatile("ldmatrix.sync.aligned.m8n8.x4.shared.b16 {%0,%1,%2,%3}, [%4];"
                 : "=r"(r0), "=r"(r1), "=r"(r2), "=r"(r3) : "r"(addr));
}
__device__ __forceinline__ void ldsm_x4t(uint32_t addr, uint32_t& r0, uint32_t& r1,
                                         uint32_t& r2, uint32_t& r3) {
    asm volatile("ldmatrix.sync.aligned.m8n8.x4.trans.shared.b16 {%0,%1,%2,%3}, [%4];"
                 : "=r"(r0), "=r"(r1), "=r"(r2), "=r"(r3) : "r"(addr));
}
__device__ __forceinline__ void mma_bf16(float* c, const uint32_t* a, const uint32_t* b) {
    asm volatile("mma.sync.aligned.m16n8k16.row.col.f32.bf16.bf16.f32 "
                 "{%0,%1,%2,%3}, {%4,%5,%6,%7}, {%8,%9}, {%0,%1,%2,%3};"
                 : "+f"(c[0]), "+f"(c[1]), "+f"(c[2]), "+f"(c[3])
                 : "r"(a[0]), "r"(a[1]), "r"(a[2]), "r"(a[3]), "r"(b[0]), "r"(b[1]));
}

// ---------------- init ----------------
__global__ void k_init() {
    int i = blockIdx.x * blockDim.x + threadIdx.x;
    if (i < Nn) { g_degout[i] = 0; g_degin[i] = 0; g_fill[i] = 0; }
    if (i < Gg * HIDf) g_hg[i] = 0;   // bits of +0.0f; readout inputs are >= 0
}

// ---------------- degrees / histogram ----------------
__global__ void k_degree(const int* __restrict__ src, const int* __restrict__ dst) {
    int e = blockIdx.x * blockDim.x + threadIdx.x;
    if (e < Ee) {
        atomicAdd(&g_degout[src[e]], 1);
        atomicAdd(&g_degin[dst[e]], 1);
    }
}

// ---------------- deg^-0.5 + weight bf16 hi/lo conversion (fused) ----------------
__global__ void k_prep(const float* __restrict__ W1, const float* __restrict__ W2,
                       const float* __restrict__ Ws, const float* __restrict__ Wd) {
    int i = blockIdx.x * blockDim.x + threadIdx.x;
    if (i < Nn) {
        g_dinvout[i] = rsqrtf((float)max(g_degout[i], 1));
        g_dinvin[i]  = rsqrtf((float)max(g_degin[i], 1));
    }
    if (i < WTOT) {
        float v;
        if (i < W2_OFF)      v = W1[i];
        else if (i < WS_OFF) v = W2[i - W2_OFF];
        else if (i < WD_OFF) v = Ws[i - WS_OFF];
        else                 v = Wd[i - WD_OFF];
        __nv_bfloat16 h = __float2bfloat16(v);
        g_wh[i] = h;
        g_wl[i] = __float2bfloat16(v - __bfloat162float(h));
    }
}

// ---------------- exclusive scan of g_degin -> g_rowptr ----------------
__global__ void k_scan1() {
    __shared__ int s[512];
    int t = threadIdx.x;
    int idx = blockIdx.x * 512 + t;
    int v = (idx < Nn) ? g_degin[idx] : 0;
    s[t] = v;
    __syncthreads();
    for (int off = 1; off < 512; off <<= 1) {
        int x = (t >= off) ? s[t - off] : 0;
        __syncthreads();
        s[t] += x;
        __syncthreads();
    }
    if (idx < Nn) g_rowptr[idx] = s[t] - v;
    if (t == 511) g_part[blockIdx.x] = s[511];
}

__global__ void k_scan2() {
    __shared__ int s[128];
    int t = threadIdx.x;
    int v = (t < NB_SCAN) ? g_part[t] : 0;
    s[t] = v;
    __syncthreads();
    for (int off = 1; off < 128; off <<= 1) {
        int x = (t >= off) ? s[t - off] : 0;
        __syncthreads();
        s[t] += x;
        __syncthreads();
    }
    if (t < NB_SCAN) g_part[t] = s[t] - v;
}

__global__ void k_scan3() {
    int idx = blockIdx.x * blockDim.x + threadIdx.x;
    if (idx < Nn) g_rowptr[idx] += g_part[idx >> 9];
    if (idx == 0) g_rowptr[Nn] = Ee;
}

// ---------------- CSR fill (edges grouped by dst) ----------------
__global__ void k_fill(const int* __restrict__ src, const int* __restrict__ dst) {
    int e = blockIdx.x * blockDim.x + threadIdx.x;
    if (e < Ee) {
        int d = dst[e];
        int pos = g_rowptr[d] + atomicAdd(&g_fill[d], 1);
        g_esrc[pos] = src[e];
        g_edst[pos] = d;
    }
}

// ---------------- tensor-core GEMM (bf16-split, double-buffered pipeline) -------
// out = (in [*dinvout]) @ W [+ bias].  64x96 tile, 256 threads (8 warps).
// Per chunk: issue next LDGs -> MMA current buffer -> convert+STS next -> sync.
__global__ void __launch_bounds__(256, 2)
k_gemm(const float* __restrict__ in,
       const __nv_bfloat16* __restrict__ Wh, const __nv_bfloat16* __restrict__ Wl,
       const float* __restrict__ bias, int use_rowscale,
       float* __restrict__ out, int kin) {
    __shared__ __nv_bfloat16 sAh[2][64][ASTRIDE];
    __shared__ __nv_bfloat16 sAl[2][64][ASTRIDE];
    __shared__ __nv_bfloat16 sBh[2][32][BSTRIDE];
    __shared__ __nv_bfloat16 sBl[2][32][BSTRIDE];
    int tid = threadIdx.x;
    int lane = tid & 31, wid = tid >> 5;
    int wm = wid & 3, wn = wid >> 2;
    int rowBase = blockIdx.x * 64;
    int nc = kin >> 5;

    float acc[6][4] = {};
    float2 a_pf[4];
    uint32_t bh_pf[6], bl_pf[6];

    auto load_regs = [&](int kc) {
#pragma unroll
        for (int t = 0; t < 4; t++) {
            int idx = tid + t * 256;
            int r = idx >> 4, k2 = (idx & 15) * 2;
            int row = rowBase + r;
            float2 v = make_float2(0.f, 0.f);
            if (row < Nn) {
                v = *(const float2*)&in[row * kin + kc + k2];
                if (use_rowscale) { float sc = g_dinvout[row]; v.x *= sc; v.y *= sc; }
            }
            a_pf[t] = v;
        }
#pragma unroll
        for (int t = 0; t < 6; t++) {
            int idx = tid + t * 256;
            int r = idx / 48, c2 = (idx % 48) * 2;
            bh_pf[t] = *(const uint32_t*)&Wh[(kc + r) * HIDf + c2];
            bl_pf[t] = *(const uint32_t*)&Wl[(kc + r) * HIDf + c2];
        }
    };
    auto store_buf = [&](int buf) {
#pragma unroll
        for (int t = 0; t < 4; t++) {
            int idx = tid + t * 256;
            int r = idx >> 4, k2 = (idx & 15) * 2;
            __nv_bfloat162 h = __floats2bfloat162_rn(a_pf[t].x, a_pf[t].y);
            *(__nv_bfloat162*)&sAh[buf][r][k2] = h;
            *(__nv_bfloat162*)&sAl[buf][r][k2] =
                __floats2bfloat162_rn(a_pf[t].x - __bfloat162float(h.x),
                                      a_pf[t].y - __bfloat162float(h.y));
        }
#pragma unroll
        for (int t = 0; t < 6; t++) {
            int idx = tid + t * 256;
            int r = idx / 48, c2 = (idx % 48) * 2;
            *(uint32_t*)&sBh[buf][r][c2] = bh_pf[t];
            *(uint32_t*)&sBl[buf][r][c2] = bl_pf[t];
        }
    };

    load_regs(0);
    store_buf(0);
    __syncthreads();

    for (int c = 0; c < nc; c++) {
        int cur = c & 1;
        bool more = (c + 1 < nc);
        if (more) load_regs((c + 1) << 5);   // LDGs in flight during MMA below
#pragma unroll
        for (int ks = 0; ks < 32; ks += 16) {
            uint32_t ah[4], al[4];
            {
                int arow = wm * 16 + (lane & 15);
                int acol = ks + (lane >> 4) * 8;
                ldsm_x4(sptr(&sAh[cur][arow][acol]), ah[0], ah[1], ah[2], ah[3]);
                ldsm_x4(sptr(&sAl[cur][arow][acol]), al[0], al[1], al[2], al[3]);
            }
            uint32_t bh[6][2], bl[6][2];
#pragma unroll
            for (int j2 = 0; j2 < 3; j2++) {
                int brow = ks + (lane & 15);
                int bcol = wn * 48 + j2 * 16 + (lane >> 4) * 8;
                ldsm_x4t(sptr(&sBh[cur][brow][bcol]),
                         bh[2 * j2][0], bh[2 * j2][1], bh[2 * j2 + 1][0], bh[2 * j2 + 1][1]);
                ldsm_x4t(sptr(&sBl[cur][brow][bcol]),
                         bl[2 * j2][0], bl[2 * j2][1], bl[2 * j2 + 1][0], bl[2 * j2 + 1][1]);
            }
#pragma unroll
            for (int j = 0; j < 6; j++) {
                mma_bf16(acc[j], ah, bh[j]);
                mma_bf16(acc[j], ah, bl[j]);
                mma_bf16(acc[j], al, bh[j]);
            }
        }
        if (more) store_buf(cur ^ 1);
        __syncthreads();
    }
    // epilogue
#pragma unroll
    for (int j = 0; j < 6; j++) {
        int r0 = rowBase + wm * 16 + (lane >> 2);
        int c = wn * 48 + j * 8 + (lane & 3) * 2;
        float b0 = 0.f, b1 = 0.f;
        if (bias) { b0 = bias[c]; b1 = bias[c + 1]; }
        if (r0 < Nn) {
            float2 o = make_float2(acc[j][0] + b0, acc[j][1] + b1);
            *(float2*)&out[r0 * HIDf + c] = o;
        }
        int r1 = r0 + 8;
        if (r1 < Nn) {
            float2 o = make_float2(acc[j][2] + b0, acc[j][3] + b1);
            *(float2*)&out[r1 * HIDf + c] = o;
        }
    }
}

// ---------------- GraphConv aggregation: out = relu(sum_in(pre[src]) * dinvin + b)
__global__ void k_agg(const float* __restrict__ pre, const float* __restrict__ bias,
                      float* __restrict__ out) {
    int warp = (blockIdx.x * blockDim.x + threadIdx.x) >> 5;
    int lane = threadIdx.x & 31;
    if (warp >= Nn) return;
    int beg = g_rowptr[warp], end = g_rowptr[warp + 1];
    float a0 = 0.f, a1 = 0.f, a2 = 0.f;
    for (int p = beg; p < end; p++) {
        const float* r = pre + g_esrc[p] * HIDf;
        a0 += r[lane];
        a1 += r[lane + 32];
        a2 += r[lane + 64];
    }
    float sc = g_dinvin[warp];
    out[warp * HIDf + lane]      = fmaxf(a0 * sc + bias[lane], 0.f);
    out[warp * HIDf + lane + 32] = fmaxf(a1 * sc + bias[lane + 32], 0.f);
    out[warp * HIDf + lane + 64] = fmaxf(a2 * sc + bias[lane + 64], 0.f);
}

// ---------------- fused GATv2: logits + max (phase 1), exp+den (2), accum (3) ---
// warp per dst node; lane=(sub,head). fd/attn in registers. Phase 1 computes
// each logit once, stores it, and folds the running max in registers — no
// separate logits kernel, no extra read pass.
__global__ void k_gat(const float* __restrict__ attn, float* __restrict__ out) {
    int warp = (blockIdx.x * blockDim.x + threadIdx.x) >> 5;
    int lane = threadIdx.x & 31;
    if (warp >= Nn) return;
    int beg = g_rowptr[warp], end = g_rowptr[warp + 1];
    int h = lane & 7, sub = lane >> 3;
    int f0 = lane, f1 = lane + 32, f2 = lane + 64;
    int h0 = f0 / Dd, h1 = f1 / Dd, h2 = f2 / Dd;

    if (beg == end) {
        out[warp * HIDf + f0] = 0.f;
        out[warp * HIDf + f1] = 0.f;
        out[warp * HIDf + f2] = 0.f;
        return;
    }

    float fdv[Dd], av[Dd];
    const float4* fdp = (const float4*)(g_fd + warp * HIDf + h * Dd);
    const float4* ap  = (const float4*)(attn + h * Dd);
#pragma unroll
    for (int j = 0; j < 3; j++) {
        float4 t = fdp[j];
        fdv[4 * j] = t.x; fdv[4 * j + 1] = t.y; fdv[4 * j + 2] = t.z; fdv[4 * j + 3] = t.w;
        float4 u = __ldg(ap + j);
        av[4 * j] = u.x; av[4 * j + 1] = u.y; av[4 * j + 2] = u.z; av[4 * j + 3] = u.w;
    }

    // phase 1: logits + running max
    float mh = -3.402823466e38f;
    for (int p = beg + sub; p < end; p += 4) {
        const float4* fsp = (const float4*)(g_fs + g_esrc[p] * HIDf + h * Dd);
        float lg = 0.f;
#pragma unroll
        for (int j = 0; j < 3; j++) {
            float4 a = fsp[j];
            float v;
            v = a.x + fdv[4 * j];     v = (v > 0.f) ? v : 0.2f * v; lg += v * av[4 * j];
            v = a.y + fdv[4 * j + 1]; v = (v > 0.f) ? v : 0.2f * v; lg += v * av[4 * j + 1];
            v = a.z + fdv[4 * j + 2]; v = (v > 0.f) ? v : 0.2f * v; lg += v * av[4 * j + 2];
            v = a.w + fdv[4 * j + 3]; v = (v > 0.f) ? v : 0.2f * v; lg += v * av[4 * j + 3];
        }
        g_logits[p * 8 + h] = lg;
        mh = fmaxf(mh, lg);
    }
    mh = fmaxf(mh, __shfl_xor_sync(0xffffffffu, mh, 8));
    mh = fmaxf(mh, __shfl_xor_sync(0xffffffffu, mh, 16));

    // phase 2: exp in place + denominator (each lane reads only its own stores)
    float den = 0.f;
    for (int p = beg + sub; p < end; p += 4) {
        float w = __expf(g_logits[p * 8 + h] - mh);
        g_logits[p * 8 + h] = w;
        den += w;
    }
    den += __shfl_xor_sync(0xffffffffu, den, 8);
    den += __shfl_xor_sync(0xffffffffu, den, 16);
    __syncwarp();                      // order weight stores before cross-lane reads

    float d0 = __shfl_sync(0xffffffffu, den, h0);
    float d1 = __shfl_sync(0xffffffffu, den, h1);
    float d2 = __shfl_sync(0xffffffffu, den, h2);
    float r0 = (d0 > 0.f) ? 1.f / d0 : 0.f;
    float r1 = (d1 > 0.f) ? 1.f / d1 : 0.f;
    float r2 = (d2 > 0.f) ? 1.f / d2 : 0.f;

    // phase 3: weighted accumulate
    float acc0 = 0.f, acc1 = 0.f, acc2 = 0.f;
    for (int p = beg; p < end; p++) {
        const float* lg = g_logits + p * 8;
        float w0 = lg[h0];
        float w1 = lg[h1];
        float w2 = lg[h2];
        const float* fr = g_fs + g_esrc[p] * HIDf;
        acc0 += w0 * fr[f0];
        acc1 += w1 * fr[f1];
        acc2 += w2 * fr[f2];
    }
    out[warp * HIDf + f0] = fmaxf(acc0 * r0, 0.f);
    out[warp * HIDf + f1] = fmaxf(acc1 * r1, 0.f);
    out[warp * HIDf + f2] = fmaxf(acc2 * r2, 0.f);
}

// ---------------- per-graph max readout (values >= 0 after relu) ----------------
__global__ void k_readout(const float* __restrict__ hfin, const int* __restrict__ gid) {
    __shared__ int s[Gg * HIDf];
    int tid = threadIdx.x;  // 384
    for (int i = tid; i < Gg * HIDf; i += 384) s[i] = 0;
    __syncthreads();
    int f = tid % 96, rr = tid / 96;
    for (int node = blockIdx.x * 4 + rr; node < Nn; node += 64 * 4) {
        int g = gid[node];
        float v = hfin[node * HIDf + f];
        atomicMax(&s[g * HIDf + f], __float_as_int(v));
    }
    __syncthreads();
    for (int i = tid; i < Gg * HIDf; i += 384) atomicMax(&g_hg[i], s[i]);
}

// ---------------- classifier MLP on [64,96] ----------------
__global__ void k_mlp(const float* __restrict__ Wc1, const float* __restrict__ bc1,
                      const float* __restrict__ Wc2, const float* __restrict__ bc2,
                      const float* __restrict__ Wc3, const float* __restrict__ bc3,
                      float* __restrict__ out) {
    __shared__ float A[Gg * HIDf];
    __shared__ float B[Gg * HIDf];
    int tid = threadIdx.x;  // 512
    for (int i = tid; i < Gg * HIDf; i += 512) A[i] = __int_as_float(g_hg[i]);
    __syncthreads();
    for (int i = tid; i < Gg * HIDf; i += 512) {
        int r = i / 96, c = i % 96;
        float acc = bc1[c];
        for (int k = 0; k < 96; k++) acc += A[r * 96 + k] * Wc1[k * 96 + c];
        B[i] = fmaxf(acc, 0.f);
    }
    __syncthreads();
    for (int i = tid; i < Gg * 48; i += 512) {
        int r = i / 48, c = i % 48;
        float acc = bc2[c];
        for (int k = 0; k < 96; k++) acc += B[r * 96 + k] * Wc2[k * 48 + c];
        A[i] = fmaxf(acc, 0.f);
    }
    __syncthreads();
    for (int i = tid; i < Gg * OUTf; i += 512) {
        int r = i / 10, c = i % 10;
        float acc = bc3[c];
        for (int k = 0; k < 48; k++) acc += A[r * 48 + k] * Wc3[k * 10 + c];
        out[i] = acc;
    }
}

// ---------------- host launcher ----------------
extern "C" void kernel_launch(void* const* d_in, const int* in_sizes, int n_in,
                              void* d_out, int out_size) {
    (void)in_sizes; (void)n_in; (void)out_size;
    const float* x    = (const float*)d_in[0];
    const int*   src  = (const int*)d_in[1];
    const int*   dst  = (const int*)d_in[2];
    const int*   gid  = (const int*)d_in[3];
    const float* W1   = (const float*)d_in[4];
    const float* b1   = (const float*)d_in[5];
    const float* W2   = (const float*)d_in[6];
    const float* b2   = (const float*)d_in[7];
    const float* Ws   = (const float*)d_in[8];
    const float* bs   = (const float*)d_in[9];
    const float* Wd   = (const float*)d_in[10];
    const float* bd   = (const float*)d_in[11];
    const float* attn = (const float*)d_in[12];
    const float* Wc1  = (const float*)d_in[13];
    const float* bc1  = (const float*)d_in[14];
    const float* Wc2  = (const float*)d_in[15];
    const float* bc2  = (const float*)d_in[16];
    const float* Wc3  = (const float*)d_in[17];
    const float* bc3  = (const float*)d_in[18];
    float* out = (float*)d_out;

    float *p_tmp, *p_h0, *p_h1, *p_fs, *p_fd;
    cudaGetSymbolAddress((void**)&p_tmp, g_tmp);
    cudaGetSymbolAddress((void**)&p_h0, g_h0);
    cudaGetSymbolAddress((void**)&p_h1, g_h1);
    cudaGetSymbolAddress((void**)&p_fs, g_fs);
    cudaGetSymbolAddress((void**)&p_fd, g_fd);
    __nv_bfloat16 *p_wh, *p_wl;
    cudaGetSymbolAddress((void**)&p_wh, g_wh);
    cudaGetSymbolAddress((void**)&p_wl, g_wl);

    const int TPB = 256;
    int gemm_blocks = (Nn + 63) / 64;             // 782
    int warp_blocks = (Nn * 32 + TPB - 1) / TPB;  // 6250
    int edge_blocks = (Ee + TPB - 1) / TPB;       // 3125
    int prep_blocks = (WTOT + TPB - 1) / TPB;     // 300

    k_init<<<(Nn + TPB - 1) / TPB, TPB>>>();                          // 0
    k_degree<<<edge_blocks, TPB>>>(src, dst);                         // 1
    k_prep<<<prep_blocks, TPB>>>(W1, W2, Ws, Wd);                     // 2
    k_gemm<<<gemm_blocks, 256>>>(x, p_wh + W1_OFF, p_wl + W1_OFF,
                                 nullptr, 1, p_tmp, INF);             // 3  <- profiled
    k_scan1<<<NB_SCAN, 512>>>();                                      // 4
    k_scan2<<<1, 128>>>();                                            // 5
    k_scan3<<<NB_SCAN, 512>>>();                                      // 6
    k_fill<<<edge_blocks, TPB>>>(src, dst);                           // 7
    k_agg<<<warp_blocks, TPB>>>(p_tmp, b1, p_h0);                     // 8

    k_gemm<<<gemm_blocks, 256>>>(p_h0, p_wh + W2_OFF, p_wl + W2_OFF,
                                 nullptr, 1, p_tmp, HIDf);
    k_agg<<<warp_blocks, TPB>>>(p_tmp, b2, p_h1);

    float* hin = p_h1;
    float* hout = p_h0;
    for (int i = 0; i < 3; i++) {
        k_gemm<<<gemm_blocks, 256>>>(hin, p_wh + WS_OFF + i * HIDf * HIDf,
                                     p_wl + WS_OFF + i * HIDf * HIDf,
                                     bs + i * HIDf, 0, p_fs, HIDf);
        k_gemm<<<gemm_blocks, 256>>>(hin, p_wh + WD_OFF + i * HIDf * HIDf,
                                     p_wl + WD_OFF + i * HIDf * HIDf,
                                     bd + i * HIDf, 0, p_fd, HIDf);
        k_gat<<<warp_blocks, TPB>>>(attn + i * Hh * Dd, hout);
        float* t = hin; hin = hout; hout = t;
    }

    k_readout<<<64, 384>>>(hin, gid);
    k_mlp<<<1, 512>>>(Wc1, bc1, Wc2, bc2, Wc3, bc3, out);
}

// round 14
// speedup vs baseline: 2.0143x; 1.0134x over previous
#include <cuda_runtime.h>
#include <cuda_bf16.h>
#include <cstdint>
#include <stdint.h>
#include <math.h>

#define Nn 50000
#define Ee 800000
#define INF 128
#define HIDf 96
#define Hh 8
#define Dd 12
#define Gg 64
#define OUTf 10
#define NB_SCAN ((Nn + 511) / 512)   // 98
#define ASTRIDE 40    // 32 + 8 pad (bf16)
#define BSTRIDE 104   // 96 + 8 pad (bf16)
#define BSTRIDE2 200  // 192 + 8 pad (bf16)

// ---------------- scratch (device globals; no allocation allowed) ------------
__device__ __align__(16) float g_tmp[Nn * HIDf];
__device__ __align__(16) float g_h0[Nn * HIDf];
__device__ __align__(16) float g_h1[Nn * HIDf];
__device__ __align__(16) float g_fs[Nn * HIDf];
__device__ __align__(16) float g_fd[Nn * HIDf];
__device__ __align__(16) float g_logits[Ee * Hh];
__device__ int   g_degout[Nn];
__device__ int   g_degin[Nn];
__device__ int   g_fill[Nn];
__device__ int   g_rowptr[Nn + 1];
__device__ int   g_esrc[Ee];
__device__ int   g_edst[Ee];
__device__ int   g_part[128];
__device__ int   g_hg[Gg * HIDf];
__device__ float g_dinvout[Nn];
__device__ float g_dinvin[Nn];
// pre-converted bf16 hi/lo weights: [W1 | W2 | (Ws|Wd)0..2 combined 96x192]
#define W1_OFF 0
#define W2_OFF (INF * HIDf)                    // 12288
#define WG_OFF (W2_OFF + HIDf * HIDf)          // 21504
#define WG_STRIDE (HIDf * 192)                 // 18432 per GAT layer
#define WTOT   (WG_OFF + 3 * WG_STRIDE)        // 76800
__device__ __align__(16) __nv_bfloat16 g_wh[WTOT];
__device__ __align__(16) __nv_bfloat16 g_wl[WTOT];

// ---------------- mma helpers ----------------
__device__ __forceinline__ uint32_t sptr(const void* p) {
    return (uint32_t)__cvta_generic_to_shared(p);
}
__device__ __forceinline__ void ldsm_x4(uint32_t addr, uint32_t& r0, uint32_t& r1,
                                        uint32_t& r2, uint32_t& r3) {
    asm volatile("ldmatrix.sync.aligned.m8n8.x4.shared.b16 {%0,%1,%2,%3}, [%4];"
                 : "=r"(r0), "=r"(r1), "=r"(r2), "=r"(r3) : "r"(addr));
}
__device__ __forceinline__ void ldsm_x4t(uint32_t addr, uint32_t& r0, uint32_t& r1,
                                         uint32_t& r2, uint32_t& r3) {
    asm volatile("ldmatrix.sync.aligned.m8n8.x4.trans.shared.b16 {%0,%1,%2,%3}, [%4];"
                 : "=r"(r0), "=r"(r1), "=r"(r2), "=r"(r3) : "r"(addr));
}
__device__ __forceinline__ void mma_bf16(float* c, const uint32_t* a, const uint32_t* b) {
    asm volatile("mma.sync.aligned.m16n8k16.row.col.f32.bf16.bf16.f32 "
                 "{%0,%1,%2,%3}, {%4,%5,%6,%7}, {%8,%9}, {%0,%1,%2,%3};"
                 : "+f"(c[0]), "+f"(c[1]), "+f"(c[2]), "+f"(c[3])
                 : "r"(a[0]), "r"(a[1]), "r"(a[2]), "r"(a[3]), "r"(b[0]), "r"(b[1]));
}

// ---------------- init ----------------
__global__ void k_init() {
    int i = blockIdx.x * blockDim.x + threadIdx.x;
    if (i < Nn) { g_degout[i] = 0; g_degin[i] = 0; g_fill[i] = 0; }
    if (i < Gg * HIDf) g_hg[i] = 0;   // bits of +0.0f; readout inputs are >= 0
}

// ---------------- degrees / histogram ----------------
__global__ void k_degree(const int* __restrict__ src, const int* __restrict__ dst) {
    int e = blockIdx.x * blockDim.x + threadIdx.x;
    if (e < Ee) {
        atomicAdd(&g_degout[src[e]], 1);
        atomicAdd(&g_degin[dst[e]], 1);
    }
}

// ---------------- deg^-0.5 + weight bf16 hi/lo conversion (fused) ----------------
// GAT layers stored as combined [96, 192] = [Ws | Wd] per layer.
__global__ void k_prep(const float* __restrict__ W1, const float* __restrict__ W2,
                       const float* __restrict__ Ws, const float* __restrict__ Wd) {
    int i = blockIdx.x * blockDim.x + threadIdx.x;
    if (i < Nn) {
        g_dinvout[i] = rsqrtf((float)max(g_degout[i], 1));
        g_dinvin[i]  = rsqrtf((float)max(g_degin[i], 1));
    }
    if (i < WTOT) {
        float v;
        if (i < W2_OFF)      v = W1[i];
        else if (i < WG_OFF) v = W2[i - W2_OFF];
        else {
            int j = i - WG_OFF;
            int layer = j / WG_STRIDE, rem = j % WG_STRIDE;
            int k = rem / 192, c = rem % 192;
            v = (c < HIDf) ? Ws[layer * HIDf * HIDf + k * HIDf + c]
                           : Wd[layer * HIDf * HIDf + k * HIDf + (c - HIDf)];
        }
        __nv_bfloat16 h = __float2bfloat16(v);
        g_wh[i] = h;
        g_wl[i] = __float2bfloat16(v - __bfloat162float(h));
    }
}

// ---------------- exclusive scan of g_degin -> g_rowptr ----------------
__global__ void k_scan1() {
    __shared__ int s[512];
    int t = threadIdx.x;
    int idx = blockIdx.x * 512 + t;
    int v = (idx < Nn) ? g_degin[idx] : 0;
    s[t] = v;
    __syncthreads();
    for (int off = 1; off < 512; off <<= 1) {
        int x = (t >= off) ? s[t - off] : 0;
        __syncthreads();
        s[t] += x;
        __syncthreads();
    }
    if (idx < Nn) g_rowptr[idx] = s[t] - v;
    if (t == 511) g_part[blockIdx.x] = s[511];
}

__global__ void k_scan2() {
    __shared__ int s[128];
    int t = threadIdx.x;
    int v = (t < NB_SCAN) ? g_part[t] : 0;
    s[t] = v;
    __syncthreads();
    for (int off = 1; off < 128; off <<= 1) {
        int x = (t >= off) ? s[t - off] : 0;
        __syncthreads();
        s[t] += x;
        __syncthreads();
    }
    if (t < NB_SCAN) g_part[t] = s[t] - v;
}

__global__ void k_scan3() {
    int idx = blockIdx.x * blockDim.x + threadIdx.x;
    if (idx < Nn) g_rowptr[idx] += g_part[idx >> 9];
    if (idx == 0) g_rowptr[Nn] = Ee;
}

// ---------------- CSR fill (edges grouped by dst) ----------------
__global__ void k_fill(const int* __restrict__ src, const int* __restrict__ dst) {
    int e = blockIdx.x * blockDim.x + threadIdx.x;
    if (e < Ee) {
        int d = dst[e];
        int pos = g_rowptr[d] + atomicAdd(&g_fill[d], 1);
        g_esrc[pos] = src[e];
        g_edst[pos] = d;
    }
}

// ---------------- tensor-core GEMM (bf16-split, double-buffered pipeline) -------
__global__ void __launch_bounds__(256, 2)
k_gemm(const float* __restrict__ in,
       const __nv_bfloat16* __restrict__ Wh, const __nv_bfloat16* __restrict__ Wl,
       const float* __restrict__ bias, int use_rowscale,
       float* __restrict__ out, int kin) {
    __shared__ __nv_bfloat16 sAh[2][64][ASTRIDE];
    __shared__ __nv_bfloat16 sAl[2][64][ASTRIDE];
    __shared__ __nv_bfloat16 sBh[2][32][BSTRIDE];
    __shared__ __nv_bfloat16 sBl[2][32][BSTRIDE];
    int tid = threadIdx.x;
    int lane = tid & 31, wid = tid >> 5;
    int wm = wid & 3, wn = wid >> 2;
    int rowBase = blockIdx.x * 64;
    int nc = kin >> 5;

    float acc[6][4] = {};
    float2 a_pf[4];
    uint32_t bh_pf[6], bl_pf[6];

    auto load_regs = [&](int kc) {
#pragma unroll
        for (int t = 0; t < 4; t++) {
            int idx = tid + t * 256;
            int r = idx >> 4, k2 = (idx & 15) * 2;
            int row = rowBase + r;
            float2 v = make_float2(0.f, 0.f);
            if (row < Nn) {
                v = *(const float2*)&in[row * kin + kc + k2];
                if (use_rowscale) { float sc = g_dinvout[row]; v.x *= sc; v.y *= sc; }
            }
            a_pf[t] = v;
        }
#pragma unroll
        for (int t = 0; t < 6; t++) {
            int idx = tid + t * 256;
            int r = idx / 48, c2 = (idx % 48) * 2;
            bh_pf[t] = *(const uint32_t*)&Wh[(kc + r) * HIDf + c2];
            bl_pf[t] = *(const uint32_t*)&Wl[(kc + r) * HIDf + c2];
        }
    };
    auto store_buf = [&](int buf) {
#pragma unroll
        for (int t = 0; t < 4; t++) {
            int idx = tid + t * 256;
            int r = idx >> 4, k2 = (idx & 15) * 2;
            __nv_bfloat162 h = __floats2bfloat162_rn(a_pf[t].x, a_pf[t].y);
            *(__nv_bfloat162*)&sAh[buf][r][k2] = h;
            *(__nv_bfloat162*)&sAl[buf][r][k2] =
                __floats2bfloat162_rn(a_pf[t].x - __bfloat162float(h.x),
                                      a_pf[t].y - __bfloat162float(h.y));
        }
#pragma unroll
        for (int t = 0; t < 6; t++) {
            int idx = tid + t * 256;
            int r = idx / 48, c2 = (idx % 48) * 2;
            *(uint32_t*)&sBh[buf][r][c2] = bh_pf[t];
            *(uint32_t*)&sBl[buf][r][c2] = bl_pf[t];
        }
    };

    load_regs(0);
    store_buf(0);
    __syncthreads();

    for (int c = 0; c < nc; c++) {
        int cur = c & 1;
        bool more = (c + 1 < nc);
        if (more) load_regs((c + 1) << 5);
#pragma unroll
        for (int ks = 0; ks < 32; ks += 16) {
            uint32_t ah[4], al[4];
            {
                int arow = wm * 16 + (lane & 15);
                int acol = ks + (lane >> 4) * 8;
                ldsm_x4(sptr(&sAh[cur][arow][acol]), ah[0], ah[1], ah[2], ah[3]);
                ldsm_x4(sptr(&sAl[cur][arow][acol]), al[0], al[1], al[2], al[3]);
            }
            uint32_t bh[6][2], bl[6][2];
#pragma unroll
            for (int j2 = 0; j2 < 3; j2++) {
                int brow = ks + (lane & 15);
                int bcol = wn * 48 + j2 * 16 + (lane >> 4) * 8;
                ldsm_x4t(sptr(&sBh[cur][brow][bcol]),
                         bh[2 * j2][0], bh[2 * j2][1], bh[2 * j2 + 1][0], bh[2 * j2 + 1][1]);
                ldsm_x4t(sptr(&sBl[cur][brow][bcol]),
                         bl[2 * j2][0], bl[2 * j2][1], bl[2 * j2 + 1][0], bl[2 * j2 + 1][1]);
            }
#pragma unroll
            for (int j = 0; j < 6; j++) {
                mma_bf16(acc[j], ah, bh[j]);
                mma_bf16(acc[j], ah, bl[j]);
                mma_bf16(acc[j], al, bh[j]);
            }
        }
        if (more) store_buf(cur ^ 1);
        __syncthreads();
    }
#pragma unroll
    for (int j = 0; j < 6; j++) {
        int r0 = rowBase + wm * 16 + (lane >> 2);
        int c = wn * 48 + j * 8 + (lane & 3) * 2;
        float b0 = 0.f, b1 = 0.f;
        if (bias) { b0 = bias[c]; b1 = bias[c + 1]; }
        if (r0 < Nn) {
            float2 o = make_float2(acc[j][0] + b0, acc[j][1] + b1);
            *(float2*)&out[r0 * HIDf + c] = o;
        }
        int r1 = r0 + 8;
        if (r1 < Nn) {
            float2 o = make_float2(acc[j][2] + b0, acc[j][3] + b1);
            *(float2*)&out[r1 * HIDf + c] = o;
        }
    }
}

// ---------------- dual-output GEMM for GAT: [fs|fd] = in @ [Ws|Wd] (kin=96) -----
// 64x192 tile, 512 threads / 16 warps; warp (wm 0..3, wn 0..3) -> 16x48 tile.
// A staged/converted ONCE for both weight halves. Dynamic smem (~70 KB).
__global__ void __launch_bounds__(512)
k_gemm2(const float* __restrict__ in,
        const __nv_bfloat16* __restrict__ Wh, const __nv_bfloat16* __restrict__ Wl,
        const float* __restrict__ bsv, const float* __restrict__ bdv,
        float* __restrict__ outs, float* __restrict__ outd) {
    extern __shared__ __nv_bfloat16 dyn[];
    __nv_bfloat16 (*sAh)[64][ASTRIDE]  = (__nv_bfloat16(*)[64][ASTRIDE])(dyn);
    __nv_bfloat16 (*sAl)[64][ASTRIDE]  = (__nv_bfloat16(*)[64][ASTRIDE])(dyn + 5120);
    __nv_bfloat16 (*sBh)[32][BSTRIDE2] = (__nv_bfloat16(*)[32][BSTRIDE2])(dyn + 10240);
    __nv_bfloat16 (*sBl)[32][BSTRIDE2] = (__nv_bfloat16(*)[32][BSTRIDE2])(dyn + 23040);
    int tid = threadIdx.x;
    int lane = tid & 31, wid = tid >> 5;
    int wm = wid & 3, wn = wid >> 2;   // wm 0..3, wn 0..3
    int rowBase = blockIdx.x * 64;

    float acc[6][4] = {};
    float2 a_pf[2];
    uint32_t bh_pf[6], bl_pf[6];

    auto load_regs = [&](int kc) {
#pragma unroll
        for (int t = 0; t < 2; t++) {
            int idx = tid + t * 512;        // 1024 items: 64 rows x 16 pairs
            int r = idx >> 4, k2 = (idx & 15) * 2;
            int row = rowBase + r;
            float2 v = make_float2(0.f, 0.f);
            if (row < Nn) v = *(const float2*)&in[row * HIDf + kc + k2];
            a_pf[t] = v;
        }
#pragma unroll
        for (int t = 0; t < 6; t++) {
            int idx = tid + t * 512;        // 3072 items: 32 rows x 96 pairs
            int r = idx / 96, c2 = (idx % 96) * 2;
            bh_pf[t] = *(const uint32_t*)&Wh[(kc + r) * 192 + c2];
            bl_pf[t] = *(const uint32_t*)&Wl[(kc + r) * 192 + c2];
        }
    };
    auto store_buf = [&](int buf) {
#pragma unroll
        for (int t = 0; t < 2; t++) {
            int idx = tid + t * 512;
            int r = idx >> 4, k2 = (idx & 15) * 2;
            __nv_bfloat162 h = __floats2bfloat162_rn(a_pf[t].x, a_pf[t].y);
            *(__nv_bfloat162*)&sAh[buf][r][k2] = h;
            *(__nv_bfloat162*)&sAl[buf][r][k2] =
                __floats2bfloat162_rn(a_pf[t].x - __bfloat162float(h.x),
                                      a_pf[t].y - __bfloat162float(h.y));
        }
#pragma unroll
        for (int t = 0; t < 6; t++) {
            int idx = tid + t * 512;
            int r = idx / 96, c2 = (idx % 96) * 2;
            *(uint32_t*)&sBh[buf][r][c2] = bh_pf[t];
            *(uint32_t*)&sBl[buf][r][c2] = bl_pf[t];
        }
    };

    load_regs(0);
    store_buf(0);
    __syncthreads();

    for (int c = 0; c < 3; c++) {          // kin = 96 -> 3 chunks
        int cur = c & 1;
        bool more = (c + 1 < 3);
        if (more) load_regs((c + 1) << 5);
#pragma unroll
        for (int ks = 0; ks < 32; ks += 16) {
            uint32_t ah[4], al[4];
            {
                int arow = wm * 16 + (lane & 15);
                int acol = ks + (lane >> 4) * 8;
                ldsm_x4(sptr(&sAh[cur][arow][acol]), ah[0], ah[1], ah[2], ah[3]);
                ldsm_x4(sptr(&sAl[cur][arow][acol]), al[0], al[1], al[2], al[3]);
            }
            uint32_t bh[6][2], bl[6][2];
#pragma unroll
            for (int j2 = 0; j2 < 3; j2++) {
                int brow = ks + (lane & 15);
                int bcol = wn * 48 + j2 * 16 + (lane >> 4) * 8;
                ldsm_x4t(sptr(&sBh[cur][brow][bcol]),
                         bh[2 * j2][0], bh[2 * j2][1], bh[2 * j2 + 1][0], bh[2 * j2 + 1][1]);
                ldsm_x4t(sptr(&sBl[cur][brow][bcol]),
                         bl[2 * j2][0], bl[2 * j2][1], bl[2 * j2 + 1][0], bl[2 * j2 + 1][1]);
            }
#pragma unroll
            for (int j = 0; j < 6; j++) {
                mma_bf16(acc[j], ah, bh[j]);
                mma_bf16(acc[j], ah, bl[j]);
                mma_bf16(acc[j], al, bh[j]);
            }
        }
        if (more) store_buf(cur ^ 1);
        __syncthreads();
    }
    // epilogue: cols 0..95 -> outs (+bs), cols 96..191 -> outd (+bd)
#pragma unroll
    for (int j = 0; j < 6; j++) {
        int r0 = rowBase + wm * 16 + (lane >> 2);
        int cg = wn * 48 + j * 8 + (lane & 3) * 2;
        float* dstp;
        float b0, b1;
        if (cg < HIDf) { dstp = outs; b0 = bsv[cg]; b1 = bsv[cg + 1]; }
        else { dstp = outd; cg -= HIDf; b0 = bdv[cg]; b1 = bdv[cg + 1]; }
        if (r0 < Nn) {
            float2 o = make_float2(acc[j][0] + b0, acc[j][1] + b1);
            *(float2*)&dstp[r0 * HIDf + cg] = o;
        }
        int r1 = r0 + 8;
        if (r1 < Nn) {
            float2 o = make_float2(acc[j][2] + b0, acc[j][3] + b1);
            *(float2*)&dstp[r1 * HIDf + cg] = o;
        }
    }
}

// ---------------- GraphConv aggregation: out = relu(sum_in(pre[src]) * dinvin + b)
__global__ void k_agg(const float* __restrict__ pre, const float* __restrict__ bias,
                      float* __restrict__ out) {
    int warp = (blockIdx.x * blockDim.x + threadIdx.x) >> 5;
    int lane = threadIdx.x & 31;
    if (warp >= Nn) return;
    int beg = g_rowptr[warp], end = g_rowptr[warp + 1];
    float a0 = 0.f, a1 = 0.f, a2 = 0.f;
    for (int p = beg; p < end; p++) {
        const float* r = pre + g_esrc[p] * HIDf;
        a0 += r[lane];
        a1 += r[lane + 32];
        a2 += r[lane + 64];
    }
    float sc = g_dinvin[warp];
    out[warp * HIDf + lane]      = fmaxf(a0 * sc + bias[lane], 0.f);
    out[warp * HIDf + lane + 32] = fmaxf(a1 * sc + bias[lane + 32], 0.f);
    out[warp * HIDf + lane + 64] = fmaxf(a2 * sc + bias[lane + 64], 0.f);
}

// ---------------- fused GATv2: logits + max (1), exp+den (2), accumulate (3) ----
__global__ void k_gat(const float* __restrict__ attn, float* __restrict__ out) {
    int warp = (blockIdx.x * blockDim.x + threadIdx.x) >> 5;
    int lane = threadIdx.x & 31;
    if (warp >= Nn) return;
    int beg = g_rowptr[warp], end = g_rowptr[warp + 1];
    int h = lane & 7, sub = lane >> 3;
    int f0 = lane, f1 = lane + 32, f2 = lane + 64;
    int h0 = f0 / Dd, h1 = f1 / Dd, h2 = f2 / Dd;

    if (beg == end) {
        out[warp * HIDf + f0] = 0.f;
        out[warp * HIDf + f1] = 0.f;
        out[warp * HIDf + f2] = 0.f;
        return;
    }

    float fdv[Dd], av[Dd];
    const float4* fdp = (const float4*)(g_fd + warp * HIDf + h * Dd);
    const float4* ap  = (const float4*)(attn + h * Dd);
#pragma unroll
    for (int j = 0; j < 3; j++) {
        float4 t = fdp[j];
        fdv[4 * j] = t.x; fdv[4 * j + 1] = t.y; fdv[4 * j + 2] = t.z; fdv[4 * j + 3] = t.w;
        float4 u = __ldg(ap + j);
        av[4 * j] = u.x; av[4 * j + 1] = u.y; av[4 * j + 2] = u.z; av[4 * j + 3] = u.w;
    }

    float mh = -3.402823466e38f;
    for (int p = beg + sub; p < end; p += 4) {
        const float4* fsp = (const float4*)(g_fs + g_esrc[p] * HIDf + h * Dd);
        float lg = 0.f;
#pragma unroll
        for (int j = 0; j < 3; j++) {
            float4 a = fsp[j];
            float v;
            v = a.x + fdv[4 * j];     v = (v > 0.f) ? v : 0.2f * v; lg += v * av[4 * j];
            v = a.y + fdv[4 * j + 1]; v = (v > 0.f) ? v : 0.2f * v; lg += v * av[4 * j + 1];
            v = a.z + fdv[4 * j + 2]; v = (v > 0.f) ? v : 0.2f * v; lg += v * av[4 * j + 2];
            v = a.w + fdv[4 * j + 3]; v = (v > 0.f) ? v : 0.2f * v; lg += v * av[4 * j + 3];
        }
        g_logits[p * 8 + h] = lg;
        mh = fmaxf(mh, lg);
    }
    mh = fmaxf(mh, __shfl_xor_sync(0xffffffffu, mh, 8));
    mh = fmaxf(mh, __shfl_xor_sync(0xffffffffu, mh, 16));

    float den = 0.f;
    for (int p = beg + sub; p < end; p += 4) {
        float w = __expf(g_logits[p * 8 + h] - mh);
        g_logits[p * 8 + h] = w;
        den += w;
    }
    den += __shfl_xor_sync(0xffffffffu, den, 8);
    den += __shfl_xor_sync(0xffffffffu, den, 16);
    __syncwarp();

    float d0 = __shfl_sync(0xffffffffu, den, h0);
    float d1 = __shfl_sync(0xffffffffu, den, h1);
    float d2 = __shfl_sync(0xffffffffu, den, h2);
    float r0 = (d0 > 0.f) ? 1.f / d0 : 0.f;
    float r1 = (d1 > 0.f) ? 1.f / d1 : 0.f;
    float r2 = (d2 > 0.f) ? 1.f / d2 : 0.f;

    float acc0 = 0.f, acc1 = 0.f, acc2 = 0.f;
    for (int p = beg; p < end; p++) {
        const float* lg = g_logits + p * 8;
        float w0 = lg[h0];
        float w1 = lg[h1];
        float w2 = lg[h2];
        const float* fr = g_fs + g_esrc[p] * HIDf;
        acc0 += w0 * fr[f0];
        acc1 += w1 * fr[f1];
        acc2 += w2 * fr[f2];
    }
    out[warp * HIDf + f0] = fmaxf(acc0 * r0, 0.f);
    out[warp * HIDf + f1] = fmaxf(acc1 * r1, 0.f);
    out[warp * HIDf + f2] = fmaxf(acc2 * r2, 0.f);
}

// ---------------- per-graph max readout (values >= 0 after relu) ----------------
__global__ void k_readout(const float* __restrict__ hfin, const int* __restrict__ gid) {
    __shared__ int s[Gg * HIDf];
    int tid = threadIdx.x;  // 384
    for (int i = tid; i < Gg * HIDf; i += 384) s[i] = 0;
    __syncthreads();
    int f = tid % 96, rr = tid / 96;
    for (int node = blockIdx.x * 4 + rr; node < Nn; node += 64 * 4) {
        int g = gid[node];
        float v = hfin[node * HIDf + f];
        atomicMax(&s[g * HIDf + f], __float_as_int(v));
    }
    __syncthreads();
    for (int i = tid; i < Gg * HIDf; i += 384) atomicMax(&g_hg[i], s[i]);
}

// ---------------- classifier MLP on [64,96] ----------------
__global__ void k_mlp(const float* __restrict__ Wc1, const float* __restrict__ bc1,
                      const float* __restrict__ Wc2, const float* __restrict__ bc2,
                      const float* __restrict__ Wc3, const float* __restrict__ bc3,
                      float* __restrict__ out) {
    __shared__ float A[Gg * HIDf];
    __shared__ float B[Gg * HIDf];
    int tid = threadIdx.x;  // 512
    for (int i = tid; i < Gg * HIDf; i += 512) A[i] = __int_as_float(g_hg[i]);
    __syncthreads();
    for (int i = tid; i < Gg * HIDf; i += 512) {
        int r = i / 96, c = i % 96;
        float acc = bc1[c];
        for (int k = 0; k < 96; k++) acc += A[r * 96 + k] * Wc1[k * 96 + c];
        B[i] = fmaxf(acc, 0.f);
    }
    __syncthreads();
    for (int i = tid; i < Gg * 48; i += 512) {
        int r = i / 48, c = i % 48;
        float acc = bc2[c];
        for (int k = 0; k < 96; k++) acc += B[r * 96 + k] * Wc2[k * 48 + c];
        A[i] = fmaxf(acc, 0.f);
    }
    __syncthreads();
    for (int i = tid; i < Gg * OUTf; i += 512) {
        int r = i / 10, c = i % 10;
        float acc = bc3[c];
        for (int k = 0; k < 48; k++) acc += A[r * 48 + k] * Wc3[k * 10 + c];
        out[i] = acc;
    }
}

// ---------------- host launcher ----------------
extern "C" void kernel_launch(void* const* d_in, const int* in_sizes, int n_in,
                              void* d_out, int out_size) {
    (void)in_sizes; (void)n_in; (void)out_size;
    const float* x    = (const float*)d_in[0];
    const int*   src  = (const int*)d_in[1];
    const int*   dst  = (const int*)d_in[2];
    const int*   gid  = (const int*)d_in[3];
    const float* W1   = (const float*)d_in[4];
    const float* b1   = (const float*)d_in[5];
    const float* W2   = (const float*)d_in[6];
    const float* b2   = (const float*)d_in[7];
    const float* Ws   = (const float*)d_in[8];
    const float* bs   = (const float*)d_in[9];
    const float* Wd   = (const float*)d_in[10];
    const float* bd   = (const float*)d_in[11];
    const float* attn = (const float*)d_in[12];
    const float* Wc1  = (const float*)d_in[13];
    const float* bc1  = (const float*)d_in[14];
    const float* Wc2  = (const float*)d_in[15];
    const float* bc2  = (const float*)d_in[16];
    const float* Wc3  = (const float*)d_in[17];
    const float* bc3  = (const float*)d_in[18];
    float* out = (float*)d_out;

    float *p_tmp, *p_h0, *p_h1, *p_fs, *p_fd;
    cudaGetSymbolAddress((void**)&p_tmp, g_tmp);
    cudaGetSymbolAddress((void**)&p_h0, g_h0);
    cudaGetSymbolAddress((void**)&p_h1, g_h1);
    cudaGetSymbolAddress((void**)&p_fs, g_fs);
    cudaGetSymbolAddress((void**)&p_fd, g_fd);
    __nv_bfloat16 *p_wh, *p_wl;
    cudaGetSymbolAddress((void**)&p_wh, g_wh);
    cudaGetSymbolAddress((void**)&p_wl, g_wl);

    const int SMEM2 = 35840 * 2;   // 70 KB dynamic for k_gemm2
    static int smem_set = 0;
    cudaFuncSetAttribute(k_gemm2, cudaFuncAttributeMaxDynamicSharedMemorySize, SMEM2);
    (void)smem_set;

    const int TPB = 256;
    int gemm_blocks = (Nn + 63) / 64;             // 782
    int warp_blocks = (Nn * 32 + TPB - 1) / TPB;  // 6250
    int edge_blocks = (Ee + TPB - 1) / TPB;       // 3125
    int prep_blocks = (WTOT + TPB - 1) / TPB;     // 300

    k_init<<<(Nn + TPB - 1) / TPB, TPB>>>();                          // 0
    k_degree<<<edge_blocks, TPB>>>(src, dst);                         // 1
    k_prep<<<prep_blocks, TPB>>>(W1, W2, Ws, Wd);                     // 2
    k_gemm<<<gemm_blocks, 256>>>(x, p_wh + W1_OFF, p_wl + W1_OFF,
                                 nullptr, 1, p_tmp, INF);             // 3  <- profiled
    k_scan1<<<NB_SCAN, 512>>>();                                      // 4
    k_scan2<<<1, 128>>>();                                            // 5
    k_scan3<<<NB_SCAN, 512>>>();                                      // 6
    k_fill<<<edge_blocks, TPB>>>(src, dst);                           // 7
    k_agg<<<warp_blocks, TPB>>>(p_tmp, b1, p_h0);                     // 8

    k_gemm<<<gemm_blocks, 256>>>(p_h0, p_wh + W2_OFF, p_wl + W2_OFF,
                                 nullptr, 1, p_tmp, HIDf);
    k_agg<<<warp_blocks, TPB>>>(p_tmp, b2, p_h1);

    float* hin = p_h1;
    float* hout = p_h0;
    for (int i = 0; i < 3; i++) {
        k_gemm2<<<gemm_blocks, 512, SMEM2>>>(hin,
                                             p_wh + WG_OFF + i * WG_STRIDE,
                                             p_wl + WG_OFF + i * WG_STRIDE,
                                             bs + i * HIDf, bd + i * HIDf,
                                             p_fs, p_fd);
        k_gat<<<warp_blocks, TPB>>>(attn + i * Hh * Dd, hout);
        float* t = hin; hin = hout; hout = t;
    }

    k_readout<<<64, 384>>>(hin, gid);
    k_mlp<<<1, 512>>>(Wc1, bc1, Wc2, bc2, Wc3, bc3, out);
}